// round 9
// baseline (speedup 1.0000x reference)
#include <cuda_runtime.h>
#include <cuda_bf16.h>
#include <stdint.h>
#include <math.h>

// ---------------- problem constants ----------------
#define B_    32
#define N_    64
#define T_    50
#define WD_   200
#define H_    128
#define G4_   512
#define D2_   256
#define BN_   2048
#define C_    8

// ---------------- scratch ----------------
__device__ uint4 wih_pk_buf[2 * 13 * 64 * 32];   // packed W_ih tf32 B-frags [dir][kt][ng][lane]
__device__ uint4 whh_pk_buf[2 * 8 * 64 * 32];    // packed sent W_hh tf32 B-frags
__device__ uint4 whh_tag_pk_buf[2 * 8 * 64 * 32];// packed tag  W_hh tf32 B-frags
__device__ float sentpres_buf[BN_ * D2_];
__device__ float q_buf[BN_ * D2_];
__device__ float k_buf[BN_ * D2_];
__device__ float sentFt_buf[BN_ * 15];
__device__ float roleFt_buf[BN_ * 15];
__device__ float g_tag_buf[2 * BN_ * G4_];
__device__ float tag_out_buf[BN_ * D2_];
__device__ float agg_buf[BN_ * D2_];

__device__ __forceinline__ float sigf(float x) { return __fdividef(1.0f, 1.0f + __expf(-x)); }

#define MMA_TF32(d, a, b) \
    asm volatile("mma.sync.aligned.m16n8k8.row.col.f32.tf32.tf32.f32 " \
                 "{%0,%1,%2,%3},{%4,%5,%6,%7},{%8,%9},{%0,%1,%2,%3};\n" \
                 : "+f"(d[0]), "+f"(d[1]), "+f"(d[2]), "+f"(d[3]) \
                 : "r"(a[0]), "r"(a[1]), "r"(a[2]), "r"(a[3]), "r"(b[0]), "r"(b[1]))

__device__ __forceinline__ void ldsm_x4(unsigned& r0, unsigned& r1, unsigned& r2, unsigned& r3,
                                        const float* p)
{
    unsigned addr = (unsigned)__cvta_generic_to_shared(p);
    asm volatile("ldmatrix.sync.aligned.m8n8.x4.shared.b16 {%0,%1,%2,%3}, [%4];"
                 : "=r"(r0), "=r"(r1), "=r"(r2), "=r"(r3) : "r"(addr));
}

__device__ __forceinline__ void lda_frag(unsigned af[4], const float* base, int stride,
                                         int mrow0, int kcol0, int lane)
{
    int tile = lane >> 3, rin = lane & 7;
    int row = mrow0 + ((tile & 1) << 3) + rin;
    int col = kcol0 + ((tile >> 1) << 2);
    ldsm_x4(af[0], af[1], af[2], af[3], base + row * stride + col);
}

// ================== pack W_ih (512x200) into tf32 B-fragments ==================
__global__ void pack_wih_tf32(const float* __restrict__ wf, const float* __restrict__ wb,
                              uint4* __restrict__ out)
{
    int i = blockIdx.x * 256 + threadIdx.x;
    if (i >= 2 * 13 * 64 * 32) return;
    const int per = 13 * 64 * 32;
    int dir = i / per, rem = i % per;
    int kt = rem >> 11, ng = (rem >> 5) & 63, lane = rem & 31;
    const float* w = dir ? wb : wf;
    int n = ng * 8 + (lane >> 2);
    int k = kt * 16 + (lane & 3);
    uint4 v;
    v.x = (k      < WD_) ? __float_as_uint(w[n * WD_ + k])      : 0u;
    v.y = (k + 4  < WD_) ? __float_as_uint(w[n * WD_ + k + 4])  : 0u;
    v.z = (k + 8  < WD_) ? __float_as_uint(w[n * WD_ + k + 8])  : 0u;
    v.w = (k + 12 < WD_) ? __float_as_uint(w[n * WD_ + k + 12]) : 0u;
    out[i] = v;
}

// ================== pack a 512x128 W_hh into tf32 B-fragments ==================
__global__ void pack_whh_tf32(const float* __restrict__ wf, const float* __restrict__ wb,
                              uint4* __restrict__ out)
{
    int i = blockIdx.x * 256 + threadIdx.x;
    if (i >= 2 * 8 * 64 * 32) return;
    int lane = i & 31, ng = (i >> 5) & 63, kt = (i >> 11) & 7, dir = i >> 14;
    const float* w = dir ? wb : wf;
    int n = ng * 8 + (lane >> 2);
    int k = kt * 16 + (lane & 3);
    uint4 v;
    v.x = __float_as_uint(w[n * 128 + k]);
    v.y = __float_as_uint(w[n * 128 + k + 4]);
    v.z = __float_as_uint(w[n * 128 + k + 8]);
    v.w = __float_as_uint(w[n * 128 + k + 12]);
    out[i] = v;
}

// ================== FUSED sentence BiLSTM v3: M=64/block, register-local gates ==================
// grid (32, 2), 256 threads / 8 warps. Block: 64 batch rows, 512 gates.
// Warp w owns cols w*16 + 128*g (+8 sub), g=0..3 -> i,f,g,o for one (row,col) live in one thread.
#define SD_STR 212
#define SH_STR 132
#define OFF_SD0   0
#define OFF_SD1   13568
#define OFF_HH    27136
#define OFF_CC    35584
#define OFF_HS    44032
#define OFF_BIAS  52480
#define FUSED_SMEM ((52480 + 512) * 4)

__global__ __launch_bounds__(256, 1)
void lstm_sent_fused(const float* __restrict__ doc,
                     const uint4* __restrict__ wih, const uint4* __restrict__ whh,
                     const float* __restrict__ biasf, const float* __restrict__ biasb,
                     float* __restrict__ sentpres)
{
    extern __shared__ __align__(16) float smf[];
    float* sh_h  = smf + OFF_HH;    // [64][132]
    float* c_s   = smf + OFF_CC;    // [64][132]
    float* hs_s  = smf + OFF_HS;    // [64][132]
    float* sbias = smf + OFF_BIAS;  // [512]

    int dir = blockIdx.y;
    int r0 = blockIdx.x << 6;
    const uint4* wih0 = wih + dir * 13 * 64 * 32;
    const uint4* whh0 = whh + dir * 8 * 64 * 32;
    const float* bias = dir ? biasb : biasf;

    int tid = threadIdx.x, lane = tid & 31, w = tid >> 5;
    int gid = lane >> 2, qk = (lane & 3) << 1;

    for (int i = tid; i < 64 * SH_STR; i += 256) { sh_h[i] = 0.f; c_s[i] = 0.f; hs_s[i] = 0.f; }
    for (int i = tid; i < 512; i += 256) sbias[i] = bias[i];

    // preload doc tile for step 0
    {
        int t0 = dir ? (T_ - 1) : 0;
        for (int idx = tid; idx < 64 * 52; idx += 256) {
            int rr = idx / 52, c4 = idx - rr * 52;
            int k = c4 << 2;
            float4 v = (k < WD_)
                ? *(const float4*)(doc + ((size_t)(r0 + rr) * T_ + t0) * WD_ + k)
                : make_float4(0.f, 0.f, 0.f, 0.f);
            *(float4*)&smf[OFF_SD0 + rr * SD_STR + k] = v;
        }
    }
    __syncthreads();

    int buf = 0;
    for (int s = 0; s < T_; s++) {
        const float* sd = smf + (buf ? OFF_SD1 : OFF_SD0);

        // acc[mt][nt][e], nt = g*2+sub -> col = 128*g + w*16 + sub*8 + qk
        float acc[4][8][4];
#pragma unroll
        for (int mt = 0; mt < 4; mt++)
#pragma unroll
            for (int nt = 0; nt < 8; nt++) {
                int col = ((nt >> 1) << 7) + (w << 4) + ((nt & 1) << 3) + qk;
                float b0 = sbias[col], b1 = sbias[col + 1];
                acc[mt][nt][0] = b0; acc[mt][nt][1] = b1;
                acc[mt][nt][2] = b0; acc[mt][nt][3] = b1;
            }

        uint4 wv0[8], wv1[8];

#define LOADW(dst, ktv) do { \
            int _kt = (ktv); \
            const uint4* _p = (_kt < 13) ? (wih0 + _kt * 64 * 32) \
                                         : (whh0 + (_kt - 13) * 64 * 32); \
            _Pragma("unroll") \
            for (int nt = 0; nt < 8; nt++) { \
                int _ng = ((nt >> 1) << 4) + (w << 1) + (nt & 1); \
                dst[nt] = _p[_ng * 32 + lane]; \
            } \
        } while (0)

#define COMPUTE(ktv, wv) do { \
            int _kt = (ktv); \
            const float* _ab = (_kt < 13) ? sd : sh_h; \
            int _astr = (_kt < 13) ? SD_STR : SH_STR; \
            int _kc = (_kt < 13) ? (_kt << 4) : ((_kt - 13) << 4); \
            _Pragma("unroll") \
            for (int mt = 0; mt < 4; mt++) { \
                unsigned _af0[4], _af1[4]; \
                lda_frag(_af0, _ab, _astr, mt * 16, _kc, lane); \
                lda_frag(_af1, _ab, _astr, mt * 16, _kc + 8, lane); \
                _Pragma("unroll") \
                for (int nt = 0; nt < 8; nt++) { \
                    unsigned _b0[2] = { wv[nt].x, wv[nt].y }; \
                    unsigned _b1[2] = { wv[nt].z, wv[nt].w }; \
                    MMA_TF32(acc[mt][nt], _af0, _b0); \
                    MMA_TF32(acc[mt][nt], _af1, _b1); \
                } \
            } \
        } while (0)

        LOADW(wv0, 0);
#pragma unroll 1
        for (int k2 = 0; k2 < 20; k2 += 2) {
            LOADW(wv1, k2 + 1);
            COMPUTE(k2, wv0);
            LOADW(wv0, k2 + 2);
            COMPUTE(k2 + 1, wv1);
        }
        COMPUTE(20, wv0);
#undef LOADW
#undef COMPUTE

        // prefetch doc tile for step s+1 (writes other buffer; no sync needed yet)
        if (s + 1 < T_) {
            int tn = dir ? (T_ - 2 - s) : (s + 1);
            float* sdn = smf + (buf ? OFF_SD0 : OFF_SD1);
            for (int idx = tid; idx < 64 * 52; idx += 256) {
                int rr = idx / 52, c4 = idx - rr * 52;
                int k = c4 << 2;
                float4 v = (k < WD_)
                    ? *(const float4*)(doc + ((size_t)(r0 + rr) * T_ + tn) * WD_ + k)
                    : make_float4(0.f, 0.f, 0.f, 0.f);
                *(float4*)&sdn[rr * SD_STR + k] = v;
            }
        }
        __syncthreads();   // all warps done reading sh_h before cell update rewrites it

        // register-local cell update: i,f,g,o in this thread's accumulators
#pragma unroll
        for (int mt = 0; mt < 4; mt++)
#pragma unroll
            for (int sub = 0; sub < 2; sub++)
#pragma unroll
                for (int e = 0; e < 4; e++) {
                    int row = mt * 16 + gid + ((e >> 1) << 3);
                    int col = (w << 4) + (sub << 3) + qk + (e & 1);
                    float iv = acc[mt][0 + sub][e];
                    float fv = acc[mt][2 + sub][e];
                    float gv = acc[mt][4 + sub][e];
                    float ov = acc[mt][6 + sub][e];
                    float cp = c_s[row * SH_STR + col];
                    float cv = sigf(fv) * cp + sigf(iv) * tanhf(gv);
                    c_s[row * SH_STR + col] = cv;
                    float h = sigf(ov) * tanhf(cv);
                    hs_s[row * SH_STR + col] += h;
                    sh_h[row * SH_STR + col] = h;
                }
        __syncthreads();
        buf ^= 1;
    }

    for (int idx = tid; idx < 64 * 128; idx += 256) {
        int row = idx >> 7, j = idx & 127;
        sentpres[(size_t)(r0 + row) * 256 + dir * 128 + j] =
            tanhf(hs_s[row * SH_STR + j] * (1.0f / T_));
    }
}

// ================== FUSED tag BiLSTM: one block per direction, tf32 mma ==================
#define TAG2_SMEM ((32 * SH_STR + 32 * 520) * 4)
__global__ __launch_bounds__(512, 1)
void lstm_tag_fused(const float* __restrict__ Gt, const uint4* __restrict__ whhtag,
                    float* __restrict__ tag_out)
{
    extern __shared__ __align__(16) float smt[];
    float* sh_h = smt;                 // [32][132]
    float* sh_g = smt + 32 * SH_STR;   // [32][520]

    int dir = blockIdx.x;
    const uint4* wp0 = whhtag + dir * 8 * 64 * 32;
    const float* G0 = Gt + (size_t)dir * 2048 * 512;

    int tid = threadIdx.x, lane = tid & 31, w = tid >> 5;
    int gid = lane >> 2, qk = (lane & 3) << 1;
    int ur = tid >> 4, uj = (tid & 15) << 3;

    float c_reg[8];
#pragma unroll
    for (int i = 0; i < 8; i++) c_reg[i] = 0.f;
    for (int i = tid; i < 32 * SH_STR; i += 512) sh_h[i] = 0.f;
    __syncthreads();

    for (int s = 0; s < 64; s++) {
        int n = dir ? (63 - s) : s;
        const float* Gn = G0 + (size_t)(n * 32) * 512;

        float acc[2][4][4];
#pragma unroll
        for (int mt = 0; mt < 2; mt++) {
            const float* gr  = Gn + (size_t)(mt * 16 + gid) * 512;
            const float* gr8 = Gn + (size_t)(mt * 16 + gid + 8) * 512;
#pragma unroll
            for (int nt = 0; nt < 4; nt++) {
                int col = w * 32 + nt * 8 + qk;
                float2 v0 = *(const float2*)(gr + col);
                float2 v1 = *(const float2*)(gr8 + col);
                acc[mt][nt][0] = v0.x; acc[mt][nt][1] = v0.y;
                acc[mt][nt][2] = v1.x; acc[mt][nt][3] = v1.y;
            }
        }

        uint4 wv0[4], wv1[4];
        {
            const uint4* p = wp0 + (w * 4) * 32 + lane;
#pragma unroll
            for (int nt = 0; nt < 4; nt++) wv0[nt] = p[nt * 32];
        }
#pragma unroll 1
        for (int kt = 0; kt < 8; kt += 2) {
            {
                const uint4* p = wp0 + ((kt + 1) * 64 + w * 4) * 32 + lane;
#pragma unroll
                for (int nt = 0; nt < 4; nt++) wv1[nt] = p[nt * 32];
            }
            {
                unsigned af[2][2][4];
#pragma unroll
                for (int mt = 0; mt < 2; mt++) {
                    lda_frag(af[mt][0], sh_h, SH_STR, mt * 16, kt * 16,     lane);
                    lda_frag(af[mt][1], sh_h, SH_STR, mt * 16, kt * 16 + 8, lane);
                }
#pragma unroll
                for (int nt = 0; nt < 4; nt++) {
                    unsigned b0[2] = { wv0[nt].x, wv0[nt].y };
                    unsigned b1[2] = { wv0[nt].z, wv0[nt].w };
#pragma unroll
                    for (int mt = 0; mt < 2; mt++) {
                        MMA_TF32(acc[mt][nt], af[mt][0], b0);
                        MMA_TF32(acc[mt][nt], af[mt][1], b1);
                    }
                }
            }
            if (kt + 2 < 8) {
                const uint4* p = wp0 + ((kt + 2) * 64 + w * 4) * 32 + lane;
#pragma unroll
                for (int nt = 0; nt < 4; nt++) wv0[nt] = p[nt * 32];
            }
            {
                unsigned af[2][2][4];
#pragma unroll
                for (int mt = 0; mt < 2; mt++) {
                    lda_frag(af[mt][0], sh_h, SH_STR, mt * 16, (kt + 1) * 16,     lane);
                    lda_frag(af[mt][1], sh_h, SH_STR, mt * 16, (kt + 1) * 16 + 8, lane);
                }
#pragma unroll
                for (int nt = 0; nt < 4; nt++) {
                    unsigned b0[2] = { wv1[nt].x, wv1[nt].y };
                    unsigned b1[2] = { wv1[nt].z, wv1[nt].w };
#pragma unroll
                    for (int mt = 0; mt < 2; mt++) {
                        MMA_TF32(acc[mt][nt], af[mt][0], b0);
                        MMA_TF32(acc[mt][nt], af[mt][1], b1);
                    }
                }
            }
        }

#pragma unroll
        for (int mt = 0; mt < 2; mt++)
#pragma unroll
            for (int nt = 0; nt < 4; nt++) {
                int lrow = mt * 16 + gid;
                int col = w * 32 + nt * 8 + qk;
                *(float2*)&sh_g[lrow * 520 + col] = make_float2(acc[mt][nt][0], acc[mt][nt][1]);
                *(float2*)&sh_g[(lrow + 8) * 520 + col] = make_float2(acc[mt][nt][2], acc[mt][nt][3]);
            }
        __syncthreads();

#pragma unroll
        for (int jj = 0; jj < 8; jj++) {
            int j = uj + jj;
            float ig = sh_g[ur * 520 + j];
            float fg = sh_g[ur * 520 + 128 + j];
            float gg = sh_g[ur * 520 + 256 + j];
            float og = sh_g[ur * 520 + 384 + j];
            float cv = sigf(fg) * c_reg[jj] + sigf(ig) * tanhf(gg);
            c_reg[jj] = cv;
            float h = sigf(og) * tanhf(cv);
            sh_h[ur * SH_STR + j] = h;
            tag_out[(size_t)(ur * 64 + n) * 256 + dir * 128 + j] = tanhf(h);
        }
        __syncthreads();
    }
}

// ================== generic tiled SGEMM (small GEMMs, fp32) ==================
__global__ void sgemm_k(const float* __restrict__ A, const float* __restrict__ W,
                        const float* __restrict__ bias, float* __restrict__ C,
                        int M, int K, int G, int amode, int relu)
{
    __shared__ float As[8][64];
    __shared__ float Ws[8][64];
    int tid = threadIdx.x;
    int mb = blockIdx.y << 6;
    int gb = blockIdx.x << 6;
    int tx = tid & 15, ty = tid >> 4;
    int mi = tid & 63;
    int kh = (tid >> 6) << 1;

    int m = mb + mi;
    long arow;
    if (amode == 0) arow = (long)m * K;
    else { int b = m & 31; int n = m >> 5; arow = (long)((b << 6) + n) * K; }
    long wrow = (long)(gb + mi) * K;

    float acc[4][4];
#pragma unroll
    for (int i = 0; i < 4; i++)
#pragma unroll
        for (int j = 0; j < 4; j++) acc[i][j] = 0.0f;

    for (int k0 = 0; k0 < K; k0 += 8) {
        float2 av = *(const float2*)(A + arow + k0 + kh);
        float2 wv = *(const float2*)(W + wrow + k0 + kh);
        __syncthreads();
        As[kh][mi] = av.x; As[kh + 1][mi] = av.y;
        Ws[kh][mi] = wv.x; Ws[kh + 1][mi] = wv.y;
        __syncthreads();
#pragma unroll
        for (int kk = 0; kk < 8; kk++) {
            float4 a = *(float4*)(&As[kk][ty << 2]);
            float4 w = *(float4*)(&Ws[kk][tx << 2]);
            float aa[4] = {a.x, a.y, a.z, a.w};
            float ww[4] = {w.x, w.y, w.z, w.w};
#pragma unroll
            for (int i = 0; i < 4; i++)
#pragma unroll
                for (int j = 0; j < 4; j++) acc[i][j] += aa[i] * ww[j];
        }
    }

    float4 b4 = *(const float4*)(bias + gb + (tx << 2));
    float bb[4] = {b4.x, b4.y, b4.z, b4.w};
#pragma unroll
    for (int i = 0; i < 4; i++) {
        float4 r;
        r.x = acc[i][0] + bb[0];
        r.y = acc[i][1] + bb[1];
        r.z = acc[i][2] + bb[2];
        r.w = acc[i][3] + bb[3];
        if (relu) {
            r.x = fmaxf(r.x, 0.f); r.y = fmaxf(r.y, 0.f);
            r.z = fmaxf(r.z, 0.f); r.w = fmaxf(r.w, 0.f);
        }
        *(float4*)(C + (size_t)(mb + (ty << 2) + i) * G + gb + (tx << 2)) = r;
    }
}

// ================== SPP ==================
__global__ void spp_kernel(const float* __restrict__ q, const float* __restrict__ k,
                           float* __restrict__ out)
{
    int bn = blockIdx.x;
    int b = bn >> 6;
    __shared__ float shq[256];
    __shared__ float att[64];
    __shared__ float e8[8];
    int tid = threadIdx.x;
    for (int l = tid; l < 256; l += 64) shq[l] = q[(size_t)bn * 256 + l];
    __syncthreads();
    const float* kr = k + (size_t)(b * 64 + tid) * 256;
    float s = 0.f;
    for (int l = 0; l < 256; l += 4) {
        float4 qa = *(float4*)&shq[l];
        float4 ka = *(const float4*)&kr[l];
        s += qa.x * ka.x + qa.y * ka.y + qa.z * ka.z + qa.w * ka.w;
    }
    att[tid] = s * 0.0625f;
    __syncthreads();
    if (tid < 8) {
        float m = att[tid * 8];
#pragma unroll
        for (int l = 1; l < 8; l++) m = fmaxf(m, att[tid * 8 + l]);
        e8[tid] = m;
    }
    __syncthreads();
    if (tid == 0) {
        float q4[4];
#pragma unroll
        for (int l = 0; l < 4; l++) q4[l] = fmaxf(e8[2 * l], e8[2 * l + 1]);
        float h2a = fmaxf(q4[0], q4[1]);
        float h2b = fmaxf(q4[2], q4[3]);
        float* o = out + bn * 15;
        o[0] = fmaxf(h2a, h2b);
        o[1] = h2a; o[2] = h2b;
        o[3] = q4[0]; o[4] = q4[1]; o[5] = q4[2]; o[6] = q4[3];
#pragma unroll
        for (int l = 0; l < 8; l++) o[7 + l] = e8[l];
    }
}

// ================== GCN ==================
#define GCN_SMEM ((64 * 256 + 64 * 64 + 64) * 4)
__global__ void gcn_kernel(const float* __restrict__ x, float* __restrict__ agg)
{
    extern __shared__ float gs[];
    float* shx = gs;
    float* shc = gs + 16384;
    float* shn = gs + 20480;
    int b = blockIdx.x;
    int tid = threadIdx.x;
    for (int l = tid; l < 16384; l += 256) shx[l] = x[(size_t)b * 16384 + l];
    __syncthreads();
    if (tid < 64) {
        float s = 0.f;
        for (int l = 0; l < 256; l++) { float v = shx[tid * 256 + l]; s += v * v; }
        shn[tid] = sqrtf(s) + 1e-8f;
    }
    __syncthreads();
    for (int p = tid; p < 4096; p += 256) {
        int i = p >> 6, j = p & 63;
        float s = 0.f;
        for (int l = 0; l < 256; l++) s += shx[i * 256 + l] * shx[j * 256 + l];
        shc[p] = s / (shn[i] * shn[j]);
    }
    __syncthreads();
    for (int p = tid; p < 16384; p += 256) {
        int i = p >> 8, d = p & 255;
        float s = 2.0f * shx[i * 256 + d];
        for (int j = 0; j < 64; j++) s += shc[i * 64 + j] * shx[j * 256 + d];
        agg[(size_t)b * 16384 + p] = s * (1.0f / 66.0f);
    }
}

// ================== classifier + log_softmax ==================
__global__ void cls_kernel(const float* __restrict__ tago, const float* __restrict__ sFt,
                           const float* __restrict__ rFt, const float* __restrict__ W,
                           const float* __restrict__ bias, float* __restrict__ out)
{
    int bn = blockIdx.x;
    int c = threadIdx.x;
    __shared__ float sh[8];
    if (c < 8) {
        const float* w = W + c * 286;
        float s = bias[c];
        const float* t = tago + (size_t)bn * 256;
        for (int l = 0; l < 256; l++) s += t[l] * w[l];
        const float* sf = sFt + bn * 15;
        for (int l = 0; l < 15; l++) s += sf[l] * w[256 + l];
        const float* rf = rFt + bn * 15;
        for (int l = 0; l < 15; l++) s += rf[l] * w[271 + l];
        sh[c] = s;
    }
    __syncthreads();
    if (c < 8) {
        float m = sh[0];
#pragma unroll
        for (int l = 1; l < 8; l++) m = fmaxf(m, sh[l]);
        float se = 0.f;
#pragma unroll
        for (int l = 0; l < 8; l++) se += expf(sh[l] - m);
        out[bn * 8 + c] = sh[c] - m - logf(se);
    }
}

// ================== launch ==================
extern "C" void kernel_launch(void* const* d_in, const int* in_sizes, int n_in,
                              void* d_out, int out_size)
{
    const float* documents = (const float*)d_in[0];
    const float* sw_ih_f = (const float*)d_in[1];
    const float* sw_hh_f = (const float*)d_in[2];
    const float* sb_f    = (const float*)d_in[3];
    const float* sw_ih_b = (const float*)d_in[4];
    const float* sw_hh_b = (const float*)d_in[5];
    const float* sb_b    = (const float*)d_in[6];
    const float* sf_Wq = (const float*)d_in[7];
    const float* sf_bq = (const float*)d_in[8];
    const float* sf_Wk = (const float*)d_in[9];
    const float* sf_bk = (const float*)d_in[10];
    const float* rf_Wq = (const float*)d_in[11];
    const float* rf_bq = (const float*)d_in[12];
    const float* rf_Wk = (const float*)d_in[13];
    const float* rf_bk = (const float*)d_in[14];
    const float* tw_ih_f = (const float*)d_in[15];
    const float* tw_hh_f = (const float*)d_in[16];
    const float* tb_f    = (const float*)d_in[17];
    const float* tw_ih_b = (const float*)d_in[18];
    const float* tw_hh_b = (const float*)d_in[19];
    const float* tb_b    = (const float*)d_in[20];
    const float* sage_W = (const float*)d_in[21];
    const float* sage_b = (const float*)d_in[22];
    const float* cls_W  = (const float*)d_in[23];
    const float* cls_b  = (const float*)d_in[24];

    float* out = (float*)d_out;
    float* result_out = out;
    float* gcn_out = out + B_ * N_ * C_;

    float *sentpres, *qb, *kb, *sFt, *rFt, *gtag, *tago, *agg;
    uint4 *wihp, *whhp, *whhtagp;
    cudaGetSymbolAddress((void**)&wihp, wih_pk_buf);
    cudaGetSymbolAddress((void**)&whhp, whh_pk_buf);
    cudaGetSymbolAddress((void**)&whhtagp, whh_tag_pk_buf);
    cudaGetSymbolAddress((void**)&sentpres, sentpres_buf);
    cudaGetSymbolAddress((void**)&qb, q_buf);
    cudaGetSymbolAddress((void**)&kb, k_buf);
    cudaGetSymbolAddress((void**)&sFt, sentFt_buf);
    cudaGetSymbolAddress((void**)&rFt, roleFt_buf);
    cudaGetSymbolAddress((void**)&gtag, g_tag_buf);
    cudaGetSymbolAddress((void**)&tago, tag_out_buf);
    cudaGetSymbolAddress((void**)&agg, agg_buf);

    cudaFuncSetAttribute(lstm_sent_fused, cudaFuncAttributeMaxDynamicSharedMemorySize, FUSED_SMEM);
    cudaFuncSetAttribute(lstm_tag_fused, cudaFuncAttributeMaxDynamicSharedMemorySize, TAG2_SMEM);
    cudaFuncSetAttribute(gcn_kernel, cudaFuncAttributeMaxDynamicSharedMemorySize, GCN_SMEM);

    // prep
    pack_wih_tf32<<<(2 * 13 * 64 * 32 + 255) / 256, 256>>>(sw_ih_f, sw_ih_b, wihp);
    pack_whh_tf32<<<128, 256>>>(sw_hh_f, sw_hh_b, whhp);
    pack_whh_tf32<<<128, 256>>>(tw_hh_f, tw_hh_b, whhtagp);

    // FUSED sentence BiLSTM v3 (index 3 — ncu capture slot)
    lstm_sent_fused<<<dim3(32, 2), 256, FUSED_SMEM>>>(documents, wihp, whhp, sb_f, sb_b, sentpres);

    // sentFt SPP
    sgemm_k<<<dim3(4, 32), 256>>>(sentpres, sf_Wq, sf_bq, qb, BN_, D2_, D2_, 0, 0);
    sgemm_k<<<dim3(4, 32), 256>>>(sentpres, sf_Wk, sf_bk, kb, BN_, D2_, D2_, 0, 0);
    spp_kernel<<<2048, 64>>>(qb, kb, sFt);

    // Tag LSTM input projections
    sgemm_k<<<dim3(8, 32), 256>>>(sentpres, tw_ih_f, tb_f, gtag,             BN_, D2_, G4_, 1, 0);
    sgemm_k<<<dim3(8, 32), 256>>>(sentpres, tw_ih_b, tb_b, gtag + BN_ * G4_, BN_, D2_, G4_, 1, 0);

    // FUSED tag BiLSTM
    lstm_tag_fused<<<2, 512, TAG2_SMEM>>>(gtag, whhtagp, tago);

    // GCN
    gcn_kernel<<<32, 256, GCN_SMEM>>>(tago, agg);
    sgemm_k<<<dim3(4, 32), 256>>>(agg, sage_W, sage_b, gcn_out, BN_, D2_, D2_, 0, 1);

    // roleFt SPP
    sgemm_k<<<dim3(4, 32), 256>>>(tago, rf_Wq, rf_bq, qb, BN_, D2_, D2_, 0, 0);
    sgemm_k<<<dim3(4, 32), 256>>>(tago, rf_Wk, rf_bk, kb, BN_, D2_, D2_, 0, 0);
    spp_kernel<<<2048, 64>>>(qb, kb, rFt);

    cls_kernel<<<2048, 32>>>(tago, sFt, rFt, cls_W, cls_b, result_out);

    (void)in_sizes; (void)n_in; (void)out_size;
}

// round 10
// speedup vs baseline: 1.2349x; 1.2349x over previous
#include <cuda_runtime.h>
#include <cuda_bf16.h>
#include <stdint.h>
#include <math.h>

// ---------------- problem constants ----------------
#define B_    32
#define N_    64
#define T_    50
#define WD_   200
#define H_    128
#define G4_   512
#define D2_   256
#define BN_   2048
#define C_    8

// ---------------- scratch ----------------
__device__ uint4 wih_pk_buf[2 * 13 * 64 * 32];   // packed W_ih tf32 B-frags [dir][kt][ng][lane]
__device__ uint4 whh_pk_buf[2 * 8 * 64 * 32];    // packed sent W_hh tf32 B-frags
__device__ uint4 whh_tag_pk_buf[2 * 8 * 64 * 32];// packed tag  W_hh tf32 B-frags
__device__ float sentpres_buf[BN_ * D2_];
__device__ float q_buf[BN_ * D2_];
__device__ float k_buf[BN_ * D2_];
__device__ float sentFt_buf[BN_ * 15];
__device__ float roleFt_buf[BN_ * 15];
__device__ float g_tag_buf[2 * BN_ * G4_];
__device__ float tag_out_buf[BN_ * D2_];
__device__ float agg_buf[BN_ * D2_];

__device__ __forceinline__ float sigf(float x) { return __fdividef(1.0f, 1.0f + __expf(-x)); }

#define MMA_TF32(d, a, b) \
    asm volatile("mma.sync.aligned.m16n8k8.row.col.f32.tf32.tf32.f32 " \
                 "{%0,%1,%2,%3},{%4,%5,%6,%7},{%8,%9},{%0,%1,%2,%3};\n" \
                 : "+f"(d[0]), "+f"(d[1]), "+f"(d[2]), "+f"(d[3]) \
                 : "r"(a[0]), "r"(a[1]), "r"(a[2]), "r"(a[3]), "r"(b[0]), "r"(b[1]))

__device__ __forceinline__ void ldsm_x4(unsigned& r0, unsigned& r1, unsigned& r2, unsigned& r3,
                                        const float* p)
{
    unsigned addr = (unsigned)__cvta_generic_to_shared(p);
    asm volatile("ldmatrix.sync.aligned.m8n8.x4.shared.b16 {%0,%1,%2,%3}, [%4];"
                 : "=r"(r0), "=r"(r1), "=r"(r2), "=r"(r3) : "r"(addr));
}

__device__ __forceinline__ void lda_frag(unsigned af[4], const float* base, int stride,
                                         int mrow0, int kcol0, int lane)
{
    int tile = lane >> 3, rin = lane & 7;
    int row = mrow0 + ((tile & 1) << 3) + rin;
    int col = kcol0 + ((tile >> 1) << 2);
    ldsm_x4(af[0], af[1], af[2], af[3], base + row * stride + col);
}

// ================== pack W_ih (512x200) into tf32 B-fragments ==================
__global__ void pack_wih_tf32(const float* __restrict__ wf, const float* __restrict__ wb,
                              uint4* __restrict__ out)
{
    int i = blockIdx.x * 256 + threadIdx.x;
    if (i >= 2 * 13 * 64 * 32) return;
    const int per = 13 * 64 * 32;
    int dir = i / per, rem = i % per;
    int kt = rem >> 11, ng = (rem >> 5) & 63, lane = rem & 31;
    const float* w = dir ? wb : wf;
    int n = ng * 8 + (lane >> 2);
    int k = kt * 16 + (lane & 3);
    uint4 v;
    v.x = (k      < WD_) ? __float_as_uint(w[n * WD_ + k])      : 0u;
    v.y = (k + 4  < WD_) ? __float_as_uint(w[n * WD_ + k + 4])  : 0u;
    v.z = (k + 8  < WD_) ? __float_as_uint(w[n * WD_ + k + 8])  : 0u;
    v.w = (k + 12 < WD_) ? __float_as_uint(w[n * WD_ + k + 12]) : 0u;
    out[i] = v;
}

// ================== pack a 512x128 W_hh into tf32 B-fragments ==================
__global__ void pack_whh_tf32(const float* __restrict__ wf, const float* __restrict__ wb,
                              uint4* __restrict__ out)
{
    int i = blockIdx.x * 256 + threadIdx.x;
    if (i >= 2 * 8 * 64 * 32) return;
    int lane = i & 31, ng = (i >> 5) & 63, kt = (i >> 11) & 7, dir = i >> 14;
    const float* w = dir ? wb : wf;
    int n = ng * 8 + (lane >> 2);
    int k = kt * 16 + (lane & 3);
    uint4 v;
    v.x = __float_as_uint(w[n * 128 + k]);
    v.y = __float_as_uint(w[n * 128 + k + 4]);
    v.z = __float_as_uint(w[n * 128 + k + 8]);
    v.w = __float_as_uint(w[n * 128 + k + 12]);
    out[i] = v;
}

// ================== FUSED sentence BiLSTM v4: 16 warps, register-local gates ==================
// grid (64, 2), 512 threads / 16 warps. Block: 32 batch rows, 512 gates.
// Warp w owns cols 128*g + w*8 (g=0..3) -> i,f,g,o for one (row,col) live in one thread.
#define SD_STR 212
#define SH_STR 132
#define OFF_SD0   0
#define OFF_SD1   6784
#define OFF_HH    13568
#define OFF_BIAS  17792
#define FUSED_SMEM ((17792 + 512) * 4)

__global__ __launch_bounds__(512, 1)
void lstm_sent_fused(const float* __restrict__ doc,
                     const uint4* __restrict__ wih, const uint4* __restrict__ whh,
                     const float* __restrict__ biasf, const float* __restrict__ biasb,
                     float* __restrict__ sentpres)
{
    extern __shared__ __align__(16) float smf[];
    float* sh_h  = smf + OFF_HH;    // [32][132]
    float* sbias = smf + OFF_BIAS;  // [512]

    int dir = blockIdx.y;
    int r0 = blockIdx.x << 5;
    const uint4* wih0 = wih + dir * 13 * 64 * 32;
    const uint4* whh0 = whh + dir * 8 * 64 * 32;
    const float* bias = dir ? biasb : biasf;

    int tid = threadIdx.x, lane = tid & 31, w = tid >> 5;   // w: 0..15
    int gid = lane >> 2, qk = (lane & 3) << 1;

    float c_reg[8], hs_reg[8];
#pragma unroll
    for (int i = 0; i < 8; i++) { c_reg[i] = 0.f; hs_reg[i] = 0.f; }
    for (int i = tid; i < 32 * SH_STR; i += 512) sh_h[i] = 0.f;
    for (int i = tid; i < 512; i += 512) sbias[i] = bias[i];
    if (tid < 512) sbias[tid] = bias[tid];

    // preload doc tile for step 0
    {
        int t0 = dir ? (T_ - 1) : 0;
        for (int idx = tid; idx < 32 * 52; idx += 512) {
            int rr = idx / 52, c4 = idx - rr * 52;
            int k = c4 << 2;
            float4 v = (k < WD_)
                ? *(const float4*)(doc + ((size_t)(r0 + rr) * T_ + t0) * WD_ + k)
                : make_float4(0.f, 0.f, 0.f, 0.f);
            *(float4*)&smf[OFF_SD0 + rr * SD_STR + k] = v;
        }
    }
    __syncthreads();

    int buf = 0;
    for (int s = 0; s < T_; s++) {
        const float* sd = smf + (buf ? OFF_SD1 : OFF_SD0);

        // acc[mt][g][e]: col(g) = 128*g + w*8 + qk (+ (e&1)); row = mt*16 + gid + 8*(e>>1)
        float acc[2][4][4];
#pragma unroll
        for (int mt = 0; mt < 2; mt++)
#pragma unroll
            for (int g = 0; g < 4; g++) {
                int col = (g << 7) + (w << 3) + qk;
                float b0 = sbias[col], b1 = sbias[col + 1];
                acc[mt][g][0] = b0; acc[mt][g][1] = b1;
                acc[mt][g][2] = b0; acc[mt][g][3] = b1;
            }

        uint4 wv0[4], wv1[4], wv2[4];

#define LOADW(dst, ktv) do { \
            int _kt = (ktv); \
            if (_kt < 21) { \
                const uint4* _p = (_kt < 13) ? (wih0 + _kt * 64 * 32) \
                                             : (whh0 + (_kt - 13) * 64 * 32); \
                _Pragma("unroll") \
                for (int g = 0; g < 4; g++) \
                    dst[g] = _p[((g << 4) + w) * 32 + lane]; \
            } \
        } while (0)

#define COMPUTE(ktv, wv) do { \
            int _kt = (ktv); \
            const float* _ab = (_kt < 13) ? sd : sh_h; \
            int _astr = (_kt < 13) ? SD_STR : SH_STR; \
            int _kc = (_kt < 13) ? (_kt << 4) : ((_kt - 13) << 4); \
            _Pragma("unroll") \
            for (int mt = 0; mt < 2; mt++) { \
                unsigned _af0[4], _af1[4]; \
                lda_frag(_af0, _ab, _astr, mt * 16, _kc, lane); \
                lda_frag(_af1, _ab, _astr, mt * 16, _kc + 8, lane); \
                _Pragma("unroll") \
                for (int g = 0; g < 4; g++) { \
                    unsigned _b0[2] = { wv[g].x, wv[g].y }; \
                    unsigned _b1[2] = { wv[g].z, wv[g].w }; \
                    MMA_TF32(acc[mt][g], _af0, _b0); \
                    MMA_TF32(acc[mt][g], _af1, _b1); \
                } \
            } \
        } while (0)

        LOADW(wv0, 0);
        LOADW(wv1, 1);
#pragma unroll 1
        for (int k3 = 0; k3 < 21; k3 += 3) {
            LOADW(wv2, k3 + 2);
            COMPUTE(k3, wv0);
            LOADW(wv0, k3 + 3);
            COMPUTE(k3 + 1, wv1);
            LOADW(wv1, k3 + 4);
            COMPUTE(k3 + 2, wv2);
        }
#undef LOADW
#undef COMPUTE

        // prefetch doc tile for step s+1 into the other buffer
        if (s + 1 < T_) {
            int tn = dir ? (T_ - 2 - s) : (s + 1);
            float* sdn = smf + (buf ? OFF_SD0 : OFF_SD1);
            for (int idx = tid; idx < 32 * 52; idx += 512) {
                int rr = idx / 52, c4 = idx - rr * 52;
                int k = c4 << 2;
                float4 v = (k < WD_)
                    ? *(const float4*)(doc + ((size_t)(r0 + rr) * T_ + tn) * WD_ + k)
                    : make_float4(0.f, 0.f, 0.f, 0.f);
                *(float4*)&sdn[rr * SD_STR + k] = v;
            }
        }
        __syncthreads();   // all warps done reading sh_h before cell update rewrites it

        // register-local LSTM cell update
#pragma unroll
        for (int mt = 0; mt < 2; mt++)
#pragma unroll
            for (int e = 0; e < 4; e++) {
                int row = mt * 16 + gid + ((e >> 1) << 3);
                int col = (w << 3) + qk + (e & 1);
                int ix = mt * 4 + e;
                float iv = acc[mt][0][e];
                float fv = acc[mt][1][e];
                float gv = acc[mt][2][e];
                float ov = acc[mt][3][e];
                float cv = sigf(fv) * c_reg[ix] + sigf(iv) * tanhf(gv);
                c_reg[ix] = cv;
                float h = sigf(ov) * tanhf(cv);
                hs_reg[ix] += h;
                sh_h[row * SH_STR + col] = h;
            }
        __syncthreads();
        buf ^= 1;
    }

    // write sentpres from register h-sums
#pragma unroll
    for (int mt = 0; mt < 2; mt++)
#pragma unroll
        for (int e = 0; e < 4; e++) {
            int row = mt * 16 + gid + ((e >> 1) << 3);
            int col = (w << 3) + qk + (e & 1);
            sentpres[(size_t)(r0 + row) * 256 + dir * 128 + col] =
                tanhf(hs_reg[mt * 4 + e] * (1.0f / T_));
        }
}

// ================== FUSED tag BiLSTM: one block per direction, tf32 mma ==================
#define TAG2_SMEM ((32 * SH_STR + 32 * 520) * 4)
__global__ __launch_bounds__(512, 1)
void lstm_tag_fused(const float* __restrict__ Gt, const uint4* __restrict__ whhtag,
                    float* __restrict__ tag_out)
{
    extern __shared__ __align__(16) float smt[];
    float* sh_h = smt;                 // [32][132]
    float* sh_g = smt + 32 * SH_STR;   // [32][520]

    int dir = blockIdx.x;
    const uint4* wp0 = whhtag + dir * 8 * 64 * 32;
    const float* G0 = Gt + (size_t)dir * 2048 * 512;

    int tid = threadIdx.x, lane = tid & 31, w = tid >> 5;
    int gid = lane >> 2, qk = (lane & 3) << 1;
    int ur = tid >> 4, uj = (tid & 15) << 3;

    float c_reg[8];
#pragma unroll
    for (int i = 0; i < 8; i++) c_reg[i] = 0.f;
    for (int i = tid; i < 32 * SH_STR; i += 512) sh_h[i] = 0.f;
    __syncthreads();

    for (int s = 0; s < 64; s++) {
        int n = dir ? (63 - s) : s;
        const float* Gn = G0 + (size_t)(n * 32) * 512;

        float acc[2][4][4];
#pragma unroll
        for (int mt = 0; mt < 2; mt++) {
            const float* gr  = Gn + (size_t)(mt * 16 + gid) * 512;
            const float* gr8 = Gn + (size_t)(mt * 16 + gid + 8) * 512;
#pragma unroll
            for (int nt = 0; nt < 4; nt++) {
                int col = w * 32 + nt * 8 + qk;
                float2 v0 = *(const float2*)(gr + col);
                float2 v1 = *(const float2*)(gr8 + col);
                acc[mt][nt][0] = v0.x; acc[mt][nt][1] = v0.y;
                acc[mt][nt][2] = v1.x; acc[mt][nt][3] = v1.y;
            }
        }

        uint4 wv0[4], wv1[4];
        {
            const uint4* p = wp0 + (w * 4) * 32 + lane;
#pragma unroll
            for (int nt = 0; nt < 4; nt++) wv0[nt] = p[nt * 32];
        }
#pragma unroll 1
        for (int kt = 0; kt < 8; kt += 2) {
            {
                const uint4* p = wp0 + ((kt + 1) * 64 + w * 4) * 32 + lane;
#pragma unroll
                for (int nt = 0; nt < 4; nt++) wv1[nt] = p[nt * 32];
            }
            {
                unsigned af[2][2][4];
#pragma unroll
                for (int mt = 0; mt < 2; mt++) {
                    lda_frag(af[mt][0], sh_h, SH_STR, mt * 16, kt * 16,     lane);
                    lda_frag(af[mt][1], sh_h, SH_STR, mt * 16, kt * 16 + 8, lane);
                }
#pragma unroll
                for (int nt = 0; nt < 4; nt++) {
                    unsigned b0[2] = { wv0[nt].x, wv0[nt].y };
                    unsigned b1[2] = { wv0[nt].z, wv0[nt].w };
#pragma unroll
                    for (int mt = 0; mt < 2; mt++) {
                        MMA_TF32(acc[mt][nt], af[mt][0], b0);
                        MMA_TF32(acc[mt][nt], af[mt][1], b1);
                    }
                }
            }
            if (kt + 2 < 8) {
                const uint4* p = wp0 + ((kt + 2) * 64 + w * 4) * 32 + lane;
#pragma unroll
                for (int nt = 0; nt < 4; nt++) wv0[nt] = p[nt * 32];
            }
            {
                unsigned af[2][2][4];
#pragma unroll
                for (int mt = 0; mt < 2; mt++) {
                    lda_frag(af[mt][0], sh_h, SH_STR, mt * 16, (kt + 1) * 16,     lane);
                    lda_frag(af[mt][1], sh_h, SH_STR, mt * 16, (kt + 1) * 16 + 8, lane);
                }
#pragma unroll
                for (int nt = 0; nt < 4; nt++) {
                    unsigned b0[2] = { wv1[nt].x, wv1[nt].y };
                    unsigned b1[2] = { wv1[nt].z, wv1[nt].w };
#pragma unroll
                    for (int mt = 0; mt < 2; mt++) {
                        MMA_TF32(acc[mt][nt], af[mt][0], b0);
                        MMA_TF32(acc[mt][nt], af[mt][1], b1);
                    }
                }
            }
        }

#pragma unroll
        for (int mt = 0; mt < 2; mt++)
#pragma unroll
            for (int nt = 0; nt < 4; nt++) {
                int lrow = mt * 16 + gid;
                int col = w * 32 + nt * 8 + qk;
                *(float2*)&sh_g[lrow * 520 + col] = make_float2(acc[mt][nt][0], acc[mt][nt][1]);
                *(float2*)&sh_g[(lrow + 8) * 520 + col] = make_float2(acc[mt][nt][2], acc[mt][nt][3]);
            }
        __syncthreads();

#pragma unroll
        for (int jj = 0; jj < 8; jj++) {
            int j = uj + jj;
            float ig = sh_g[ur * 520 + j];
            float fg = sh_g[ur * 520 + 128 + j];
            float gg = sh_g[ur * 520 + 256 + j];
            float og = sh_g[ur * 520 + 384 + j];
            float cv = sigf(fg) * c_reg[jj] + sigf(ig) * tanhf(gg);
            c_reg[jj] = cv;
            float h = sigf(og) * tanhf(cv);
            sh_h[ur * SH_STR + j] = h;
            tag_out[(size_t)(ur * 64 + n) * 256 + dir * 128 + j] = tanhf(h);
        }
        __syncthreads();
    }
}

// ================== generic tiled SGEMM (small GEMMs, fp32) ==================
__global__ void sgemm_k(const float* __restrict__ A, const float* __restrict__ W,
                        const float* __restrict__ bias, float* __restrict__ C,
                        int M, int K, int G, int amode, int relu)
{
    __shared__ float As[8][64];
    __shared__ float Ws[8][64];
    int tid = threadIdx.x;
    int mb = blockIdx.y << 6;
    int gb = blockIdx.x << 6;
    int tx = tid & 15, ty = tid >> 4;
    int mi = tid & 63;
    int kh = (tid >> 6) << 1;

    int m = mb + mi;
    long arow;
    if (amode == 0) arow = (long)m * K;
    else { int b = m & 31; int n = m >> 5; arow = (long)((b << 6) + n) * K; }
    long wrow = (long)(gb + mi) * K;

    float acc[4][4];
#pragma unroll
    for (int i = 0; i < 4; i++)
#pragma unroll
        for (int j = 0; j < 4; j++) acc[i][j] = 0.0f;

    for (int k0 = 0; k0 < K; k0 += 8) {
        float2 av = *(const float2*)(A + arow + k0 + kh);
        float2 wv = *(const float2*)(W + wrow + k0 + kh);
        __syncthreads();
        As[kh][mi] = av.x; As[kh + 1][mi] = av.y;
        Ws[kh][mi] = wv.x; Ws[kh + 1][mi] = wv.y;
        __syncthreads();
#pragma unroll
        for (int kk = 0; kk < 8; kk++) {
            float4 a = *(float4*)(&As[kk][ty << 2]);
            float4 w = *(float4*)(&Ws[kk][tx << 2]);
            float aa[4] = {a.x, a.y, a.z, a.w};
            float ww[4] = {w.x, w.y, w.z, w.w};
#pragma unroll
            for (int i = 0; i < 4; i++)
#pragma unroll
                for (int j = 0; j < 4; j++) acc[i][j] += aa[i] * ww[j];
        }
    }

    float4 b4 = *(const float4*)(bias + gb + (tx << 2));
    float bb[4] = {b4.x, b4.y, b4.z, b4.w};
#pragma unroll
    for (int i = 0; i < 4; i++) {
        float4 r;
        r.x = acc[i][0] + bb[0];
        r.y = acc[i][1] + bb[1];
        r.z = acc[i][2] + bb[2];
        r.w = acc[i][3] + bb[3];
        if (relu) {
            r.x = fmaxf(r.x, 0.f); r.y = fmaxf(r.y, 0.f);
            r.z = fmaxf(r.z, 0.f); r.w = fmaxf(r.w, 0.f);
        }
        *(float4*)(C + (size_t)(mb + (ty << 2) + i) * G + gb + (tx << 2)) = r;
    }
}

// ================== SPP ==================
__global__ void spp_kernel(const float* __restrict__ q, const float* __restrict__ k,
                           float* __restrict__ out)
{
    int bn = blockIdx.x;
    int b = bn >> 6;
    __shared__ float shq[256];
    __shared__ float att[64];
    __shared__ float e8[8];
    int tid = threadIdx.x;
    for (int l = tid; l < 256; l += 64) shq[l] = q[(size_t)bn * 256 + l];
    __syncthreads();
    const float* kr = k + (size_t)(b * 64 + tid) * 256;
    float s = 0.f;
    for (int l = 0; l < 256; l += 4) {
        float4 qa = *(float4*)&shq[l];
        float4 ka = *(const float4*)&kr[l];
        s += qa.x * ka.x + qa.y * ka.y + qa.z * ka.z + qa.w * ka.w;
    }
    att[tid] = s * 0.0625f;
    __syncthreads();
    if (tid < 8) {
        float m = att[tid * 8];
#pragma unroll
        for (int l = 1; l < 8; l++) m = fmaxf(m, att[tid * 8 + l]);
        e8[tid] = m;
    }
    __syncthreads();
    if (tid == 0) {
        float q4[4];
#pragma unroll
        for (int l = 0; l < 4; l++) q4[l] = fmaxf(e8[2 * l], e8[2 * l + 1]);
        float h2a = fmaxf(q4[0], q4[1]);
        float h2b = fmaxf(q4[2], q4[3]);
        float* o = out + bn * 15;
        o[0] = fmaxf(h2a, h2b);
        o[1] = h2a; o[2] = h2b;
        o[3] = q4[0]; o[4] = q4[1]; o[5] = q4[2]; o[6] = q4[3];
#pragma unroll
        for (int l = 0; l < 8; l++) o[7 + l] = e8[l];
    }
}

// ================== GCN ==================
#define GCN_SMEM ((64 * 256 + 64 * 64 + 64) * 4)
__global__ void gcn_kernel(const float* __restrict__ x, float* __restrict__ agg)
{
    extern __shared__ float gs[];
    float* shx = gs;
    float* shc = gs + 16384;
    float* shn = gs + 20480;
    int b = blockIdx.x;
    int tid = threadIdx.x;
    for (int l = tid; l < 16384; l += 256) shx[l] = x[(size_t)b * 16384 + l];
    __syncthreads();
    if (tid < 64) {
        float s = 0.f;
        for (int l = 0; l < 256; l++) { float v = shx[tid * 256 + l]; s += v * v; }
        shn[tid] = sqrtf(s) + 1e-8f;
    }
    __syncthreads();
    for (int p = tid; p < 4096; p += 256) {
        int i = p >> 6, j = p & 63;
        float s = 0.f;
        for (int l = 0; l < 256; l++) s += shx[i * 256 + l] * shx[j * 256 + l];
        shc[p] = s / (shn[i] * shn[j]);
    }
    __syncthreads();
    for (int p = tid; p < 16384; p += 256) {
        int i = p >> 8, d = p & 255;
        float s = 2.0f * shx[i * 256 + d];
        for (int j = 0; j < 64; j++) s += shc[i * 64 + j] * shx[j * 256 + d];
        agg[(size_t)b * 16384 + p] = s * (1.0f / 66.0f);
    }
}

// ================== classifier + log_softmax ==================
__global__ void cls_kernel(const float* __restrict__ tago, const float* __restrict__ sFt,
                           const float* __restrict__ rFt, const float* __restrict__ W,
                           const float* __restrict__ bias, float* __restrict__ out)
{
    int bn = blockIdx.x;
    int c = threadIdx.x;
    __shared__ float sh[8];
    if (c < 8) {
        const float* w = W + c * 286;
        float s = bias[c];
        const float* t = tago + (size_t)bn * 256;
        for (int l = 0; l < 256; l++) s += t[l] * w[l];
        const float* sf = sFt + bn * 15;
        for (int l = 0; l < 15; l++) s += sf[l] * w[256 + l];
        const float* rf = rFt + bn * 15;
        for (int l = 0; l < 15; l++) s += rf[l] * w[271 + l];
        sh[c] = s;
    }
    __syncthreads();
    if (c < 8) {
        float m = sh[0];
#pragma unroll
        for (int l = 1; l < 8; l++) m = fmaxf(m, sh[l]);
        float se = 0.f;
#pragma unroll
        for (int l = 0; l < 8; l++) se += expf(sh[l] - m);
        out[bn * 8 + c] = sh[c] - m - logf(se);
    }
}

// ================== launch ==================
extern "C" void kernel_launch(void* const* d_in, const int* in_sizes, int n_in,
                              void* d_out, int out_size)
{
    const float* documents = (const float*)d_in[0];
    const float* sw_ih_f = (const float*)d_in[1];
    const float* sw_hh_f = (const float*)d_in[2];
    const float* sb_f    = (const float*)d_in[3];
    const float* sw_ih_b = (const float*)d_in[4];
    const float* sw_hh_b = (const float*)d_in[5];
    const float* sb_b    = (const float*)d_in[6];
    const float* sf_Wq = (const float*)d_in[7];
    const float* sf_bq = (const float*)d_in[8];
    const float* sf_Wk = (const float*)d_in[9];
    const float* sf_bk = (const float*)d_in[10];
    const float* rf_Wq = (const float*)d_in[11];
    const float* rf_bq = (const float*)d_in[12];
    const float* rf_Wk = (const float*)d_in[13];
    const float* rf_bk = (const float*)d_in[14];
    const float* tw_ih_f = (const float*)d_in[15];
    const float* tw_hh_f = (const float*)d_in[16];
    const float* tb_f    = (const float*)d_in[17];
    const float* tw_ih_b = (const float*)d_in[18];
    const float* tw_hh_b = (const float*)d_in[19];
    const float* tb_b    = (const float*)d_in[20];
    const float* sage_W = (const float*)d_in[21];
    const float* sage_b = (const float*)d_in[22];
    const float* cls_W  = (const float*)d_in[23];
    const float* cls_b  = (const float*)d_in[24];

    float* out = (float*)d_out;
    float* result_out = out;
    float* gcn_out = out + B_ * N_ * C_;

    float *sentpres, *qb, *kb, *sFt, *rFt, *gtag, *tago, *agg;
    uint4 *wihp, *whhp, *whhtagp;
    cudaGetSymbolAddress((void**)&wihp, wih_pk_buf);
    cudaGetSymbolAddress((void**)&whhp, whh_pk_buf);
    cudaGetSymbolAddress((void**)&whhtagp, whh_tag_pk_buf);
    cudaGetSymbolAddress((void**)&sentpres, sentpres_buf);
    cudaGetSymbolAddress((void**)&qb, q_buf);
    cudaGetSymbolAddress((void**)&kb, k_buf);
    cudaGetSymbolAddress((void**)&sFt, sentFt_buf);
    cudaGetSymbolAddress((void**)&rFt, roleFt_buf);
    cudaGetSymbolAddress((void**)&gtag, g_tag_buf);
    cudaGetSymbolAddress((void**)&tago, tag_out_buf);
    cudaGetSymbolAddress((void**)&agg, agg_buf);

    cudaFuncSetAttribute(lstm_sent_fused, cudaFuncAttributeMaxDynamicSharedMemorySize, FUSED_SMEM);
    cudaFuncSetAttribute(lstm_tag_fused, cudaFuncAttributeMaxDynamicSharedMemorySize, TAG2_SMEM);
    cudaFuncSetAttribute(gcn_kernel, cudaFuncAttributeMaxDynamicSharedMemorySize, GCN_SMEM);

    // prep
    pack_wih_tf32<<<(2 * 13 * 64 * 32 + 255) / 256, 256>>>(sw_ih_f, sw_ih_b, wihp);
    pack_whh_tf32<<<128, 256>>>(sw_hh_f, sw_hh_b, whhp);
    pack_whh_tf32<<<128, 256>>>(tw_hh_f, tw_hh_b, whhtagp);

    // FUSED sentence BiLSTM v4 (index 3 — ncu capture slot)
    lstm_sent_fused<<<dim3(64, 2), 512, FUSED_SMEM>>>(documents, wihp, whhp, sb_f, sb_b, sentpres);

    // sentFt SPP
    sgemm_k<<<dim3(4, 32), 256>>>(sentpres, sf_Wq, sf_bq, qb, BN_, D2_, D2_, 0, 0);
    sgemm_k<<<dim3(4, 32), 256>>>(sentpres, sf_Wk, sf_bk, kb, BN_, D2_, D2_, 0, 0);
    spp_kernel<<<2048, 64>>>(qb, kb, sFt);

    // Tag LSTM input projections
    sgemm_k<<<dim3(8, 32), 256>>>(sentpres, tw_ih_f, tb_f, gtag,             BN_, D2_, G4_, 1, 0);
    sgemm_k<<<dim3(8, 32), 256>>>(sentpres, tw_ih_b, tb_b, gtag + BN_ * G4_, BN_, D2_, G4_, 1, 0);

    // FUSED tag BiLSTM
    lstm_tag_fused<<<2, 512, TAG2_SMEM>>>(gtag, whhtagp, tago);

    // GCN
    gcn_kernel<<<32, 256, GCN_SMEM>>>(tago, agg);
    sgemm_k<<<dim3(4, 32), 256>>>(agg, sage_W, sage_b, gcn_out, BN_, D2_, D2_, 0, 1);

    // roleFt SPP
    sgemm_k<<<dim3(4, 32), 256>>>(tago, rf_Wq, rf_bq, qb, BN_, D2_, D2_, 0, 0);
    sgemm_k<<<dim3(4, 32), 256>>>(tago, rf_Wk, rf_bk, kb, BN_, D2_, D2_, 0, 0);
    spp_kernel<<<2048, 64>>>(qb, kb, rFt);

    cls_kernel<<<2048, 32>>>(tago, sFt, rFt, cls_W, cls_b, result_out);

    (void)in_sizes; (void)n_in; (void)out_size;
}

// round 11
// speedup vs baseline: 1.2856x; 1.0411x over previous
#include <cuda_runtime.h>
#include <cuda_bf16.h>
#include <stdint.h>
#include <math.h>

// ---------------- problem constants ----------------
#define B_    32
#define N_    64
#define T_    50
#define WD_   200
#define H_    128
#define G4_   512
#define D2_   256
#define BN_   2048
#define C_    8

// ---------------- scratch ----------------
__device__ uint4 wih_pk_buf[2 * 13 * 64 * 32];
__device__ uint4 whh_pk_buf[2 * 8 * 64 * 32];
__device__ uint4 whh_tag_pk_buf[2 * 8 * 64 * 32];
__device__ float sentpres_buf[BN_ * D2_];
__device__ float q_buf[BN_ * D2_];
__device__ float k_buf[BN_ * D2_];
__device__ float sentFt_buf[BN_ * 15];
__device__ float roleFt_buf[BN_ * 15];
__device__ float g_tag_buf[2 * BN_ * G4_];
__device__ float tag_out_buf[BN_ * D2_];
__device__ float agg_buf[BN_ * D2_];

__device__ __forceinline__ float sigf(float x) { return __fdividef(1.0f, 1.0f + __expf(-x)); }

#define MMA_TF32(d, a, b) \
    asm volatile("mma.sync.aligned.m16n8k8.row.col.f32.tf32.tf32.f32 " \
                 "{%0,%1,%2,%3},{%4,%5,%6,%7},{%8,%9},{%0,%1,%2,%3};\n" \
                 : "+f"(d[0]), "+f"(d[1]), "+f"(d[2]), "+f"(d[3]) \
                 : "r"(a[0]), "r"(a[1]), "r"(a[2]), "r"(a[3]), "r"(b[0]), "r"(b[1]))

__device__ __forceinline__ void ldsm_x4_a(unsigned af[4], unsigned addr)
{
    asm volatile("ldmatrix.sync.aligned.m8n8.x4.shared.b16 {%0,%1,%2,%3}, [%4];"
                 : "=r"(af[0]), "=r"(af[1]), "=r"(af[2]), "=r"(af[3]) : "r"(addr));
}

__device__ __forceinline__ void ldsm_x4(unsigned& r0, unsigned& r1, unsigned& r2, unsigned& r3,
                                        const float* p)
{
    unsigned addr = (unsigned)__cvta_generic_to_shared(p);
    asm volatile("ldmatrix.sync.aligned.m8n8.x4.shared.b16 {%0,%1,%2,%3}, [%4];"
                 : "=r"(r0), "=r"(r1), "=r"(r2), "=r"(r3) : "r"(addr));
}

__device__ __forceinline__ void lda_frag(unsigned af[4], const float* base, int stride,
                                         int mrow0, int kcol0, int lane)
{
    int tile = lane >> 3, rin = lane & 7;
    int row = mrow0 + ((tile & 1) << 3) + rin;
    int col = kcol0 + ((tile >> 1) << 2);
    ldsm_x4(af[0], af[1], af[2], af[3], base + row * stride + col);
}

// ================== pack W_ih (512x200) into tf32 B-fragments ==================
__global__ void pack_wih_tf32(const float* __restrict__ wf, const float* __restrict__ wb,
                              uint4* __restrict__ out)
{
    int i = blockIdx.x * 256 + threadIdx.x;
    if (i >= 2 * 13 * 64 * 32) return;
    const int per = 13 * 64 * 32;
    int dir = i / per, rem = i % per;
    int kt = rem >> 11, ng = (rem >> 5) & 63, lane = rem & 31;
    const float* w = dir ? wb : wf;
    int n = ng * 8 + (lane >> 2);
    int k = kt * 16 + (lane & 3);
    uint4 v;
    v.x = (k      < WD_) ? __float_as_uint(w[n * WD_ + k])      : 0u;
    v.y = (k + 4  < WD_) ? __float_as_uint(w[n * WD_ + k + 4])  : 0u;
    v.z = (k + 8  < WD_) ? __float_as_uint(w[n * WD_ + k + 8])  : 0u;
    v.w = (k + 12 < WD_) ? __float_as_uint(w[n * WD_ + k + 12]) : 0u;
    out[i] = v;
}

// ================== pack a 512x128 W_hh into tf32 B-fragments ==================
__global__ void pack_whh_tf32(const float* __restrict__ wf, const float* __restrict__ wb,
                              uint4* __restrict__ out)
{
    int i = blockIdx.x * 256 + threadIdx.x;
    if (i >= 2 * 8 * 64 * 32) return;
    int lane = i & 31, ng = (i >> 5) & 63, kt = (i >> 11) & 7, dir = i >> 14;
    const float* w = dir ? wb : wf;
    int n = ng * 8 + (lane >> 2);
    int k = kt * 16 + (lane & 3);
    uint4 v;
    v.x = __float_as_uint(w[n * 128 + k]);
    v.y = __float_as_uint(w[n * 128 + k + 4]);
    v.z = __float_as_uint(w[n * 128 + k + 8]);
    v.w = __float_as_uint(w[n * 128 + k + 12]);
    out[i] = v;
}

// ================== FUSED sentence BiLSTM v5: ping-pong h, precomputed addrs ==================
// grid (64, 2), 512 threads / 16 warps. Block: 32 batch rows, 512 gates.
#define SD_STR 212
#define SH_STR 132
#define OFF_SD0   0
#define OFF_SD1   6784
#define OFF_H0    13568
#define OFF_H1    17792
#define OFF_BIAS  22016
#define FUSED_SMEM ((22016 + 512) * 4)
#define SD_BUFB   27136     // bytes between sd buffers
#define SH_BUFB   16896     // bytes between h buffers

__global__ __launch_bounds__(512, 1)
void lstm_sent_fused(const float* __restrict__ doc,
                     const uint4* __restrict__ wih, const uint4* __restrict__ whh,
                     const float* __restrict__ biasf, const float* __restrict__ biasb,
                     float* __restrict__ sentpres)
{
    extern __shared__ __align__(16) float smf[];
    float* sbias = smf + OFF_BIAS;

    int dir = blockIdx.y;
    int r0 = blockIdx.x << 5;
    const uint4* wih0 = wih + dir * 13 * 64 * 32;
    const uint4* whh0 = whh + dir * 8 * 64 * 32;
    const float* bias = dir ? biasb : biasf;

    int tid = threadIdx.x, lane = tid & 31, w = tid >> 5;
    int gid = lane >> 2, qk = (lane & 3) << 1;

    // precomputed ldmatrix smem byte addresses (buffer 0, mt = 0/1)
    unsigned smbase = (unsigned)__cvta_generic_to_shared(smf);
    int tile = lane >> 3, rin = lane & 7;
    int r_off = ((tile & 1) << 3) + rin;
    int c_off = (tile >> 1) << 2;
    unsigned sd_addr[2], sh_addr[2];
#pragma unroll
    for (int mt = 0; mt < 2; mt++) {
        sd_addr[mt] = smbase + ((unsigned)(OFF_SD0 + (mt * 16 + r_off) * SD_STR + c_off) << 2);
        sh_addr[mt] = smbase + ((unsigned)(OFF_H0 + (mt * 16 + r_off) * SH_STR + c_off) << 2);
    }

    float c_reg[8], hs_reg[8];
#pragma unroll
    for (int i = 0; i < 8; i++) { c_reg[i] = 0.f; hs_reg[i] = 0.f; }
    for (int i = tid; i < 2 * 32 * SH_STR; i += 512) smf[OFF_H0 + i] = 0.f;
    if (tid < 512) sbias[tid] = bias[tid];

    // preload doc tile for step 0
    {
        int t0 = dir ? (T_ - 1) : 0;
        for (int idx = tid; idx < 32 * 52; idx += 512) {
            int rr = idx / 52, c4 = idx - rr * 52;
            int k = c4 << 2;
            float4 v = (k < WD_)
                ? *(const float4*)(doc + ((size_t)(r0 + rr) * T_ + t0) * WD_ + k)
                : make_float4(0.f, 0.f, 0.f, 0.f);
            *(float4*)&smf[OFF_SD0 + rr * SD_STR + k] = v;
        }
    }
    __syncthreads();

    for (int s = 0; s < T_; s++) {
        int p = s & 1;
        unsigned po = p ? SD_BUFB : 0u;     // doc read buffer offset (bytes)
        unsigned ph = p ? SH_BUFB : 0u;     // h read buffer offset (bytes)

        float acc[2][4][4];
#pragma unroll
        for (int mt = 0; mt < 2; mt++)
#pragma unroll
            for (int g = 0; g < 4; g++) {
                int col = (g << 7) + (w << 3) + qk;
                float b0 = sbias[col], b1 = sbias[col + 1];
                acc[mt][g][0] = b0; acc[mt][g][1] = b1;
                acc[mt][g][2] = b0; acc[mt][g][3] = b1;
            }

        uint4 wv0[4], wv1[4], wv2[4];

#define LOADW(dst, ktv) do { \
            int _kt = (ktv); \
            if (_kt < 21) { \
                const uint4* _p = (_kt < 13) ? (wih0 + _kt * 64 * 32) \
                                             : (whh0 + (_kt - 13) * 64 * 32); \
                _Pragma("unroll") \
                for (int g = 0; g < 4; g++) \
                    dst[g] = _p[((g << 4) + w) * 32 + lane]; \
            } \
        } while (0)

#define COMPUTE(ktv, wv) do { \
            int _kt = (ktv); \
            _Pragma("unroll") \
            for (int mt = 0; mt < 2; mt++) { \
                unsigned _a0 = (_kt < 13) ? (sd_addr[mt] + po + ((unsigned)_kt << 6)) \
                                          : (sh_addr[mt] + ph + ((unsigned)(_kt - 13) << 6)); \
                unsigned _af0[4], _af1[4]; \
                ldsm_x4_a(_af0, _a0); \
                ldsm_x4_a(_af1, _a0 + 32); \
                _Pragma("unroll") \
                for (int g = 0; g < 4; g++) { \
                    unsigned _b0[2] = { wv[g].x, wv[g].y }; \
                    unsigned _b1[2] = { wv[g].z, wv[g].w }; \
                    MMA_TF32(acc[mt][g], _af0, _b0); \
                    MMA_TF32(acc[mt][g], _af1, _b1); \
                } \
            } \
        } while (0)

        LOADW(wv0, 0);
        LOADW(wv1, 1);
#pragma unroll 1
        for (int k3 = 0; k3 < 21; k3 += 3) {
            LOADW(wv2, k3 + 2);
            COMPUTE(k3, wv0);
            LOADW(wv0, k3 + 3);
            COMPUTE(k3 + 1, wv1);
            LOADW(wv1, k3 + 4);
            COMPUTE(k3 + 2, wv2);
        }
#undef LOADW
#undef COMPUTE

        // prefetch doc tile for step s+1 into the other doc buffer
        if (s + 1 < T_) {
            int tn = dir ? (T_ - 2 - s) : (s + 1);
            float* sdn = smf + (p ? OFF_SD0 : OFF_SD1);
            for (int idx = tid; idx < 32 * 52; idx += 512) {
                int rr = idx / 52, c4 = idx - rr * 52;
                int k = c4 << 2;
                float4 v = (k < WD_)
                    ? *(const float4*)(doc + ((size_t)(r0 + rr) * T_ + tn) * WD_ + k)
                    : make_float4(0.f, 0.f, 0.f, 0.f);
                *(float4*)&sdn[rr * SD_STR + k] = v;
            }
        }

        // register-local LSTM cell update -> write h into the OTHER h buffer (no sync needed first)
        float* hw = smf + (p ? OFF_H0 : OFF_H1);
#pragma unroll
        for (int mt = 0; mt < 2; mt++)
#pragma unroll
            for (int e = 0; e < 4; e++) {
                int row = mt * 16 + gid + ((e >> 1) << 3);
                int col = (w << 3) + qk + (e & 1);
                int ix = mt * 4 + e;
                float iv = acc[mt][0][e];
                float fv = acc[mt][1][e];
                float gv = acc[mt][2][e];
                float ov = acc[mt][3][e];
                float cv = sigf(fv) * c_reg[ix] + sigf(iv) * tanhf(gv);
                c_reg[ix] = cv;
                float h = sigf(ov) * tanhf(cv);
                hs_reg[ix] += h;
                hw[row * SH_STR + col] = h;
            }
        __syncthreads();   // single sync: h writes + doc prefetch visible for next step
    }

#pragma unroll
    for (int mt = 0; mt < 2; mt++)
#pragma unroll
        for (int e = 0; e < 4; e++) {
            int row = mt * 16 + gid + ((e >> 1) << 3);
            int col = (w << 3) + qk + (e & 1);
            sentpres[(size_t)(r0 + row) * 256 + dir * 128 + col] =
                tanhf(hs_reg[mt * 4 + e] * (1.0f / T_));
        }
}

// ================== FUSED tag BiLSTM v2: 1024 threads / 32 warps per direction ==================
#define TAG2_SMEM ((32 * SH_STR + 32 * 520) * 4)
__global__ __launch_bounds__(1024, 1)
void lstm_tag_fused(const float* __restrict__ Gt, const uint4* __restrict__ whhtag,
                    float* __restrict__ tag_out)
{
    extern __shared__ __align__(16) float smt[];
    float* sh_h = smt;                 // [32][132]
    float* sh_g = smt + 32 * SH_STR;   // [32][520]

    int dir = blockIdx.x;
    const uint4* wp0 = whhtag + dir * 8 * 64 * 32;
    const float* G0 = Gt + (size_t)dir * 2048 * 512;

    int tid = threadIdx.x, lane = tid & 31, w = tid >> 5;   // w: 0..31
    int gid = lane >> 2, qk = (lane & 3) << 1;
    int ur = tid >> 5;                  // cell row 0..31
    int uc0 = (tid & 31) << 2;          // cell col base (4 cols per thread)

    float c_reg[4];
#pragma unroll
    for (int i = 0; i < 4; i++) c_reg[i] = 0.f;
    for (int i = tid; i < 32 * SH_STR; i += 1024) sh_h[i] = 0.f;
    __syncthreads();

    for (int s = 0; s < 64; s++) {
        int n = dir ? (63 - s) : s;
        const float* Gn = G0 + (size_t)(n * 32) * 512;

        // init acc from precomputed input projection (includes bias); warp owns cols w*16..+15
        float acc[2][2][4];
#pragma unroll
        for (int mt = 0; mt < 2; mt++) {
            const float* gr  = Gn + (size_t)(mt * 16 + gid) * 512;
            const float* gr8 = Gn + (size_t)(mt * 16 + gid + 8) * 512;
#pragma unroll
            for (int nt = 0; nt < 2; nt++) {
                int col = (w << 4) + nt * 8 + qk;
                float2 v0 = *(const float2*)(gr + col);
                float2 v1 = *(const float2*)(gr8 + col);
                acc[mt][nt][0] = v0.x; acc[mt][nt][1] = v0.y;
                acc[mt][nt][2] = v1.x; acc[mt][nt][3] = v1.y;
            }
        }

        // h @ W_hh^T over 8 k-tiles, double-buffered W fragments. ng = w*2 + nt.
        uint4 wv0[2], wv1[2];
        {
            const uint4* p = wp0 + (w * 2) * 32 + lane;
            wv0[0] = p[0]; wv0[1] = p[32];
        }
#pragma unroll 1
        for (int kt = 0; kt < 8; kt += 2) {
            {
                const uint4* p = wp0 + ((kt + 1) * 64 + w * 2) * 32 + lane;
                wv1[0] = p[0]; wv1[1] = p[32];
            }
            {
                unsigned af[2][2][4];
#pragma unroll
                for (int mt = 0; mt < 2; mt++) {
                    lda_frag(af[mt][0], sh_h, SH_STR, mt * 16, kt * 16,     lane);
                    lda_frag(af[mt][1], sh_h, SH_STR, mt * 16, kt * 16 + 8, lane);
                }
#pragma unroll
                for (int nt = 0; nt < 2; nt++) {
                    unsigned b0[2] = { wv0[nt].x, wv0[nt].y };
                    unsigned b1[2] = { wv0[nt].z, wv0[nt].w };
#pragma unroll
                    for (int mt = 0; mt < 2; mt++) {
                        MMA_TF32(acc[mt][nt], af[mt][0], b0);
                        MMA_TF32(acc[mt][nt], af[mt][1], b1);
                    }
                }
            }
            if (kt + 2 < 8) {
                const uint4* p = wp0 + ((kt + 2) * 64 + w * 2) * 32 + lane;
                wv0[0] = p[0]; wv0[1] = p[32];
            }
            {
                unsigned af[2][2][4];
#pragma unroll
                for (int mt = 0; mt < 2; mt++) {
                    lda_frag(af[mt][0], sh_h, SH_STR, mt * 16, (kt + 1) * 16,     lane);
                    lda_frag(af[mt][1], sh_h, SH_STR, mt * 16, (kt + 1) * 16 + 8, lane);
                }
#pragma unroll
                for (int nt = 0; nt < 2; nt++) {
                    unsigned b0[2] = { wv1[nt].x, wv1[nt].y };
                    unsigned b1[2] = { wv1[nt].z, wv1[nt].w };
#pragma unroll
                    for (int mt = 0; mt < 2; mt++) {
                        MMA_TF32(acc[mt][nt], af[mt][0], b0);
                        MMA_TF32(acc[mt][nt], af[mt][1], b1);
                    }
                }
            }
        }

        // scatter gates
#pragma unroll
        for (int mt = 0; mt < 2; mt++)
#pragma unroll
            for (int nt = 0; nt < 2; nt++) {
                int lrow = mt * 16 + gid;
                int col = (w << 4) + nt * 8 + qk;
                *(float2*)&sh_g[lrow * 520 + col] = make_float2(acc[mt][nt][0], acc[mt][nt][1]);
                *(float2*)&sh_g[(lrow + 8) * 520 + col] = make_float2(acc[mt][nt][2], acc[mt][nt][3]);
            }
        __syncthreads();

        // cell update: thread owns (ur, uc0..uc0+3)
#pragma unroll
        for (int jj = 0; jj < 4; jj++) {
            int j = uc0 + jj;
            float ig = sh_g[ur * 520 + j];
            float fg = sh_g[ur * 520 + 128 + j];
            float gg = sh_g[ur * 520 + 256 + j];
            float og = sh_g[ur * 520 + 384 + j];
            float cv = sigf(fg) * c_reg[jj] + sigf(ig) * tanhf(gg);
            c_reg[jj] = cv;
            float h = sigf(og) * tanhf(cv);
            sh_h[ur * SH_STR + j] = h;
            tag_out[(size_t)(ur * 64 + n) * 256 + dir * 128 + j] = tanhf(h);
        }
        __syncthreads();
    }
}

// ================== generic tiled SGEMM (small GEMMs, fp32) ==================
__global__ void sgemm_k(const float* __restrict__ A, const float* __restrict__ W,
                        const float* __restrict__ bias, float* __restrict__ C,
                        int M, int K, int G, int amode, int relu)
{
    __shared__ float As[8][64];
    __shared__ float Ws[8][64];
    int tid = threadIdx.x;
    int mb = blockIdx.y << 6;
    int gb = blockIdx.x << 6;
    int tx = tid & 15, ty = tid >> 4;
    int mi = tid & 63;
    int kh = (tid >> 6) << 1;

    int m = mb + mi;
    long arow;
    if (amode == 0) arow = (long)m * K;
    else { int b = m & 31; int n = m >> 5; arow = (long)((b << 6) + n) * K; }
    long wrow = (long)(gb + mi) * K;

    float acc[4][4];
#pragma unroll
    for (int i = 0; i < 4; i++)
#pragma unroll
        for (int j = 0; j < 4; j++) acc[i][j] = 0.0f;

    for (int k0 = 0; k0 < K; k0 += 8) {
        float2 av = *(const float2*)(A + arow + k0 + kh);
        float2 wv = *(const float2*)(W + wrow + k0 + kh);
        __syncthreads();
        As[kh][mi] = av.x; As[kh + 1][mi] = av.y;
        Ws[kh][mi] = wv.x; Ws[kh + 1][mi] = wv.y;
        __syncthreads();
#pragma unroll
        for (int kk = 0; kk < 8; kk++) {
            float4 a = *(float4*)(&As[kk][ty << 2]);
            float4 w = *(float4*)(&Ws[kk][tx << 2]);
            float aa[4] = {a.x, a.y, a.z, a.w};
            float ww[4] = {w.x, w.y, w.z, w.w};
#pragma unroll
            for (int i = 0; i < 4; i++)
#pragma unroll
                for (int j = 0; j < 4; j++) acc[i][j] += aa[i] * ww[j];
        }
    }

    float4 b4 = *(const float4*)(bias + gb + (tx << 2));
    float bb[4] = {b4.x, b4.y, b4.z, b4.w};
#pragma unroll
    for (int i = 0; i < 4; i++) {
        float4 r;
        r.x = acc[i][0] + bb[0];
        r.y = acc[i][1] + bb[1];
        r.z = acc[i][2] + bb[2];
        r.w = acc[i][3] + bb[3];
        if (relu) {
            r.x = fmaxf(r.x, 0.f); r.y = fmaxf(r.y, 0.f);
            r.z = fmaxf(r.z, 0.f); r.w = fmaxf(r.w, 0.f);
        }
        *(float4*)(C + (size_t)(mb + (ty << 2) + i) * G + gb + (tx << 2)) = r;
    }
}

// ================== SPP ==================
__global__ void spp_kernel(const float* __restrict__ q, const float* __restrict__ k,
                           float* __restrict__ out)
{
    int bn = blockIdx.x;
    int b = bn >> 6;
    __shared__ float shq[256];
    __shared__ float att[64];
    __shared__ float e8[8];
    int tid = threadIdx.x;
    for (int l = tid; l < 256; l += 64) shq[l] = q[(size_t)bn * 256 + l];
    __syncthreads();
    const float* kr = k + (size_t)(b * 64 + tid) * 256;
    float s = 0.f;
    for (int l = 0; l < 256; l += 4) {
        float4 qa = *(float4*)&shq[l];
        float4 ka = *(const float4*)&kr[l];
        s += qa.x * ka.x + qa.y * ka.y + qa.z * ka.z + qa.w * ka.w;
    }
    att[tid] = s * 0.0625f;
    __syncthreads();
    if (tid < 8) {
        float m = att[tid * 8];
#pragma unroll
        for (int l = 1; l < 8; l++) m = fmaxf(m, att[tid * 8 + l]);
        e8[tid] = m;
    }
    __syncthreads();
    if (tid == 0) {
        float q4[4];
#pragma unroll
        for (int l = 0; l < 4; l++) q4[l] = fmaxf(e8[2 * l], e8[2 * l + 1]);
        float h2a = fmaxf(q4[0], q4[1]);
        float h2b = fmaxf(q4[2], q4[3]);
        float* o = out + bn * 15;
        o[0] = fmaxf(h2a, h2b);
        o[1] = h2a; o[2] = h2b;
        o[3] = q4[0]; o[4] = q4[1]; o[5] = q4[2]; o[6] = q4[3];
#pragma unroll
        for (int l = 0; l < 8; l++) o[7 + l] = e8[l];
    }
}

// ================== GCN ==================
#define GCN_SMEM ((64 * 256 + 64 * 64 + 64) * 4)
__global__ void gcn_kernel(const float* __restrict__ x, float* __restrict__ agg)
{
    extern __shared__ float gs[];
    float* shx = gs;
    float* shc = gs + 16384;
    float* shn = gs + 20480;
    int b = blockIdx.x;
    int tid = threadIdx.x;
    for (int l = tid; l < 16384; l += 256) shx[l] = x[(size_t)b * 16384 + l];
    __syncthreads();
    if (tid < 64) {
        float s = 0.f;
        for (int l = 0; l < 256; l++) { float v = shx[tid * 256 + l]; s += v * v; }
        shn[tid] = sqrtf(s) + 1e-8f;
    }
    __syncthreads();
    for (int p = tid; p < 4096; p += 256) {
        int i = p >> 6, j = p & 63;
        float s = 0.f;
        for (int l = 0; l < 256; l++) s += shx[i * 256 + l] * shx[j * 256 + l];
        shc[p] = s / (shn[i] * shn[j]);
    }
    __syncthreads();
    for (int p = tid; p < 16384; p += 256) {
        int i = p >> 8, d = p & 255;
        float s = 2.0f * shx[i * 256 + d];
        for (int j = 0; j < 64; j++) s += shc[i * 64 + j] * shx[j * 256 + d];
        agg[(size_t)b * 16384 + p] = s * (1.0f / 66.0f);
    }
}

// ================== classifier + log_softmax (warp per class) ==================
__global__ void cls_kernel(const float* __restrict__ tago, const float* __restrict__ sFt,
                           const float* __restrict__ rFt, const float* __restrict__ W,
                           const float* __restrict__ bias, float* __restrict__ out)
{
    int bn = blockIdx.x;
    int tid = threadIdx.x;        // 256 threads, 8 warps
    int c = tid >> 5, lane = tid & 31;
    __shared__ float sh[8];
    const float* w = W + c * 286;
    const float* t = tago + (size_t)bn * 256;
    float s = 0.f;
    for (int l = lane; l < 256; l += 32) s += t[l] * w[l];
    if (lane < 15) {
        s += sFt[bn * 15 + lane] * w[256 + lane];
        s += rFt[bn * 15 + lane] * w[271 + lane];
    }
#pragma unroll
    for (int off = 16; off > 0; off >>= 1)
        s += __shfl_down_sync(0xFFFFFFFF, s, off);
    if (lane == 0) sh[c] = s + bias[c];
    __syncthreads();
    if (tid < 8) {
        float m = sh[0];
#pragma unroll
        for (int l = 1; l < 8; l++) m = fmaxf(m, sh[l]);
        float se = 0.f;
#pragma unroll
        for (int l = 0; l < 8; l++) se += expf(sh[l] - m);
        out[bn * 8 + tid] = sh[tid] - m - logf(se);
    }
}

// ================== launch ==================
extern "C" void kernel_launch(void* const* d_in, const int* in_sizes, int n_in,
                              void* d_out, int out_size)
{
    const float* documents = (const float*)d_in[0];
    const float* sw_ih_f = (const float*)d_in[1];
    const float* sw_hh_f = (const float*)d_in[2];
    const float* sb_f    = (const float*)d_in[3];
    const float* sw_ih_b = (const float*)d_in[4];
    const float* sw_hh_b = (const float*)d_in[5];
    const float* sb_b    = (const float*)d_in[6];
    const float* sf_Wq = (const float*)d_in[7];
    const float* sf_bq = (const float*)d_in[8];
    const float* sf_Wk = (const float*)d_in[9];
    const float* sf_bk = (const float*)d_in[10];
    const float* rf_Wq = (const float*)d_in[11];
    const float* rf_bq = (const float*)d_in[12];
    const float* rf_Wk = (const float*)d_in[13];
    const float* rf_bk = (const float*)d_in[14];
    const float* tw_ih_f = (const float*)d_in[15];
    const float* tw_hh_f = (const float*)d_in[16];
    const float* tb_f    = (const float*)d_in[17];
    const float* tw_ih_b = (const float*)d_in[18];
    const float* tw_hh_b = (const float*)d_in[19];
    const float* tb_b    = (const float*)d_in[20];
    const float* sage_W = (const float*)d_in[21];
    const float* sage_b = (const float*)d_in[22];
    const float* cls_W  = (const float*)d_in[23];
    const float* cls_b  = (const float*)d_in[24];

    float* out = (float*)d_out;
    float* result_out = out;
    float* gcn_out = out + B_ * N_ * C_;

    float *sentpres, *qb, *kb, *sFt, *rFt, *gtag, *tago, *agg;
    uint4 *wihp, *whhp, *whhtagp;
    cudaGetSymbolAddress((void**)&wihp, wih_pk_buf);
    cudaGetSymbolAddress((void**)&whhp, whh_pk_buf);
    cudaGetSymbolAddress((void**)&whhtagp, whh_tag_pk_buf);
    cudaGetSymbolAddress((void**)&sentpres, sentpres_buf);
    cudaGetSymbolAddress((void**)&qb, q_buf);
    cudaGetSymbolAddress((void**)&kb, k_buf);
    cudaGetSymbolAddress((void**)&sFt, sentFt_buf);
    cudaGetSymbolAddress((void**)&rFt, roleFt_buf);
    cudaGetSymbolAddress((void**)&gtag, g_tag_buf);
    cudaGetSymbolAddress((void**)&tago, tag_out_buf);
    cudaGetSymbolAddress((void**)&agg, agg_buf);

    cudaFuncSetAttribute(lstm_sent_fused, cudaFuncAttributeMaxDynamicSharedMemorySize, FUSED_SMEM);
    cudaFuncSetAttribute(lstm_tag_fused, cudaFuncAttributeMaxDynamicSharedMemorySize, TAG2_SMEM);
    cudaFuncSetAttribute(gcn_kernel, cudaFuncAttributeMaxDynamicSharedMemorySize, GCN_SMEM);

    // prep
    pack_wih_tf32<<<(2 * 13 * 64 * 32 + 255) / 256, 256>>>(sw_ih_f, sw_ih_b, wihp);
    pack_whh_tf32<<<128, 256>>>(sw_hh_f, sw_hh_b, whhp);
    pack_whh_tf32<<<128, 256>>>(tw_hh_f, tw_hh_b, whhtagp);

    // FUSED sentence BiLSTM v5 (index 3 — ncu capture slot)
    lstm_sent_fused<<<dim3(64, 2), 512, FUSED_SMEM>>>(documents, wihp, whhp, sb_f, sb_b, sentpres);

    // sentFt SPP
    sgemm_k<<<dim3(4, 32), 256>>>(sentpres, sf_Wq, sf_bq, qb, BN_, D2_, D2_, 0, 0);
    sgemm_k<<<dim3(4, 32), 256>>>(sentpres, sf_Wk, sf_bk, kb, BN_, D2_, D2_, 0, 0);
    spp_kernel<<<2048, 64>>>(qb, kb, sFt);

    // Tag LSTM input projections
    sgemm_k<<<dim3(8, 32), 256>>>(sentpres, tw_ih_f, tb_f, gtag,             BN_, D2_, G4_, 1, 0);
    sgemm_k<<<dim3(8, 32), 256>>>(sentpres, tw_ih_b, tb_b, gtag + BN_ * G4_, BN_, D2_, G4_, 1, 0);

    // FUSED tag BiLSTM v2 (1024 threads per direction)
    lstm_tag_fused<<<2, 1024, TAG2_SMEM>>>(gtag, whhtagp, tago);

    // GCN
    gcn_kernel<<<32, 256, GCN_SMEM>>>(tago, agg);
    sgemm_k<<<dim3(4, 32), 256>>>(agg, sage_W, sage_b, gcn_out, BN_, D2_, D2_, 0, 1);

    // roleFt SPP
    sgemm_k<<<dim3(4, 32), 256>>>(tago, rf_Wq, rf_bq, qb, BN_, D2_, D2_, 0, 0);
    sgemm_k<<<dim3(4, 32), 256>>>(tago, rf_Wk, rf_bk, kb, BN_, D2_, D2_, 0, 0);
    spp_kernel<<<2048, 64>>>(qb, kb, rFt);

    cls_kernel<<<2048, 256>>>(tago, sFt, rFt, cls_W, cls_b, result_out);

    (void)in_sizes; (void)n_in; (void)out_size;
}

// round 12
// speedup vs baseline: 1.3018x; 1.0126x over previous
#include <cuda_runtime.h>
#include <cuda_bf16.h>
#include <stdint.h>
#include <math.h>

// ---------------- problem constants ----------------
#define B_    32
#define N_    64
#define T_    50
#define WD_   200
#define H_    128
#define G4_   512
#define D2_   256
#define BN_   2048
#define C_    8

// ---------------- scratch ----------------
__device__ uint4 wih_pk_buf[2 * 13 * 64 * 32];
__device__ uint4 whh_pk_buf[2 * 8 * 64 * 32];
__device__ uint4 whh_tag_pk_buf[2 * 8 * 64 * 32];
__device__ float sentpres_buf[BN_ * D2_];
__device__ float q_buf[BN_ * D2_];
__device__ float k_buf[BN_ * D2_];
__device__ float sentFt_buf[BN_ * 15];
__device__ float roleFt_buf[BN_ * 15];
__device__ float g_tag_buf[2 * BN_ * G4_];
__device__ float tag_out_buf[BN_ * D2_];
__device__ float agg_buf[BN_ * D2_];

__device__ __forceinline__ float sigf(float x) { return __fdividef(1.0f, 1.0f + __expf(-x)); }

#define MMA_TF32(d, a, b) \
    asm volatile("mma.sync.aligned.m16n8k8.row.col.f32.tf32.tf32.f32 " \
                 "{%0,%1,%2,%3},{%4,%5,%6,%7},{%8,%9},{%0,%1,%2,%3};\n" \
                 : "+f"(d[0]), "+f"(d[1]), "+f"(d[2]), "+f"(d[3]) \
                 : "r"(a[0]), "r"(a[1]), "r"(a[2]), "r"(a[3]), "r"(b[0]), "r"(b[1]))

__device__ __forceinline__ void ldsm_x4_a(unsigned af[4], unsigned addr)
{
    asm volatile("ldmatrix.sync.aligned.m8n8.x4.shared.b16 {%0,%1,%2,%3}, [%4];"
                 : "=r"(af[0]), "=r"(af[1]), "=r"(af[2]), "=r"(af[3]) : "r"(addr));
}

__device__ __forceinline__ void ldsm_x4(unsigned& r0, unsigned& r1, unsigned& r2, unsigned& r3,
                                        const float* p)
{
    unsigned addr = (unsigned)__cvta_generic_to_shared(p);
    asm volatile("ldmatrix.sync.aligned.m8n8.x4.shared.b16 {%0,%1,%2,%3}, [%4];"
                 : "=r"(r0), "=r"(r1), "=r"(r2), "=r"(r3) : "r"(addr));
}

__device__ __forceinline__ void lda_frag(unsigned af[4], const float* base, int stride,
                                         int mrow0, int kcol0, int lane)
{
    int tile = lane >> 3, rin = lane & 7;
    int row = mrow0 + ((tile & 1) << 3) + rin;
    int col = kcol0 + ((tile >> 1) << 2);
    ldsm_x4(af[0], af[1], af[2], af[3], base + row * stride + col);
}

// ================== pack W_ih (512x200) into tf32 B-fragments ==================
__global__ void pack_wih_tf32(const float* __restrict__ wf, const float* __restrict__ wb,
                              uint4* __restrict__ out)
{
    int i = blockIdx.x * 256 + threadIdx.x;
    if (i >= 2 * 13 * 64 * 32) return;
    const int per = 13 * 64 * 32;
    int dir = i / per, rem = i % per;
    int kt = rem >> 11, ng = (rem >> 5) & 63, lane = rem & 31;
    const float* w = dir ? wb : wf;
    int n = ng * 8 + (lane >> 2);
    int k = kt * 16 + (lane & 3);
    uint4 v;
    v.x = (k      < WD_) ? __float_as_uint(w[n * WD_ + k])      : 0u;
    v.y = (k + 4  < WD_) ? __float_as_uint(w[n * WD_ + k + 4])  : 0u;
    v.z = (k + 8  < WD_) ? __float_as_uint(w[n * WD_ + k + 8])  : 0u;
    v.w = (k + 12 < WD_) ? __float_as_uint(w[n * WD_ + k + 12]) : 0u;
    out[i] = v;
}

// ================== pack a 512x128 W_hh into tf32 B-fragments ==================
__global__ void pack_whh_tf32(const float* __restrict__ wf, const float* __restrict__ wb,
                              uint4* __restrict__ out)
{
    int i = blockIdx.x * 256 + threadIdx.x;
    if (i >= 2 * 8 * 64 * 32) return;
    int lane = i & 31, ng = (i >> 5) & 63, kt = (i >> 11) & 7, dir = i >> 14;
    const float* w = dir ? wb : wf;
    int n = ng * 8 + (lane >> 2);
    int k = kt * 16 + (lane & 3);
    uint4 v;
    v.x = __float_as_uint(w[n * 128 + k]);
    v.y = __float_as_uint(w[n * 128 + k + 4]);
    v.z = __float_as_uint(w[n * 128 + k + 8]);
    v.w = __float_as_uint(w[n * 128 + k + 12]);
    out[i] = v;
}

// ================== FUSED sentence BiLSTM v6 ==================
// grid (64, 2), 512 threads / 16 warps. Block: 32 batch rows, 512 gates.
#define SD_STR 212
#define SH_STR 132
#define OFF_SD0   0
#define OFF_SD1   6784
#define OFF_H0    13568
#define OFF_H1    17792
#define OFF_BIAS  22016
#define FUSED_SMEM ((22016 + 512) * 4)
#define SD_BUFB   27136
#define SH_BUFB   16896

__global__ __launch_bounds__(512, 1)
void lstm_sent_fused(const float* __restrict__ doc,
                     const uint4* __restrict__ wih, const uint4* __restrict__ whh,
                     const float* __restrict__ biasf, const float* __restrict__ biasb,
                     float* __restrict__ sentpres)
{
    extern __shared__ __align__(16) float smf[];
    float* sbias = smf + OFF_BIAS;

    int dir = blockIdx.y;
    int r0 = blockIdx.x << 5;
    const float* bias = dir ? biasb : biasf;

    int tid = threadIdx.x, lane = tid & 31, w = tid >> 5;
    int gid = lane >> 2, qk = (lane & 3) << 1;

    // per-thread W fragment base pointers (g stride = 512 uint4, kt stride = 2048 uint4)
    const uint4* wp_ih = wih + dir * 13 * 64 * 32 + w * 32 + lane;
    const uint4* wp_hh = whh + dir * 8 * 64 * 32 + w * 32 + lane;

    // precomputed ldmatrix smem byte addresses
    unsigned smbase = (unsigned)__cvta_generic_to_shared(smf);
    int tile = lane >> 3, rin = lane & 7;
    int r_off = ((tile & 1) << 3) + rin;
    int c_off = (tile >> 1) << 2;
    unsigned sd_addr[2], sh_addr[2];
#pragma unroll
    for (int mt = 0; mt < 2; mt++) {
        sd_addr[mt] = smbase + ((unsigned)(OFF_SD0 + (mt * 16 + r_off) * SD_STR + c_off) << 2);
        sh_addr[mt] = smbase + ((unsigned)(OFF_H0 + (mt * 16 + r_off) * SH_STR + c_off) << 2);
    }

    float c_reg[8], hs_reg[8];
#pragma unroll
    for (int i = 0; i < 8; i++) { c_reg[i] = 0.f; hs_reg[i] = 0.f; }
    for (int i = tid; i < 2 * 32 * SH_STR; i += 512) smf[OFF_H0 + i] = 0.f;
    if (tid < 512) sbias[tid] = bias[tid];

    {
        int t0 = dir ? (T_ - 1) : 0;
        for (int idx = tid; idx < 32 * 52; idx += 512) {
            int rr = idx / 52, c4 = idx - rr * 52;
            int k = c4 << 2;
            float4 v = (k < WD_)
                ? *(const float4*)(doc + ((size_t)(r0 + rr) * T_ + t0) * WD_ + k)
                : make_float4(0.f, 0.f, 0.f, 0.f);
            *(float4*)&smf[OFF_SD0 + rr * SD_STR + k] = v;
        }
    }
    __syncthreads();

    for (int s = 0; s < T_; s++) {
        int p = s & 1;
        unsigned po = p ? SD_BUFB : 0u;
        unsigned ph = p ? SH_BUFB : 0u;

        float acc[2][4][4];
#pragma unroll
        for (int mt = 0; mt < 2; mt++)
#pragma unroll
            for (int g = 0; g < 4; g++) {
                int col = (g << 7) + (w << 3) + qk;
                float b0 = sbias[col], b1 = sbias[col + 1];
                acc[mt][g][0] = b0; acc[mt][g][1] = b1;
                acc[mt][g][2] = b0; acc[mt][g][3] = b1;
            }

        uint4 wv0[4], wv1[4], wv2[4];

#define LOADW(dst, ktv) do { \
            int _kt = (ktv); \
            if (_kt < 21) { \
                const uint4* _p = (_kt < 13) ? (wp_ih + _kt * 2048) \
                                             : (wp_hh + (_kt - 13) * 2048); \
                dst[0] = _p[0];    dst[1] = _p[512]; \
                dst[2] = _p[1024]; dst[3] = _p[1536]; \
            } \
        } while (0)

#define COMPUTE(ktv, wv) do { \
            int _kt = (ktv); \
            _Pragma("unroll") \
            for (int mt = 0; mt < 2; mt++) { \
                unsigned _a0 = (_kt < 13) ? (sd_addr[mt] + po + ((unsigned)_kt << 6)) \
                                          : (sh_addr[mt] + ph + ((unsigned)(_kt - 13) << 6)); \
                unsigned _af0[4], _af1[4]; \
                ldsm_x4_a(_af0, _a0); \
                ldsm_x4_a(_af1, _a0 + 32); \
                _Pragma("unroll") \
                for (int g = 0; g < 4; g++) { \
                    unsigned _b0[2] = { wv[g].x, wv[g].y }; \
                    unsigned _b1[2] = { wv[g].z, wv[g].w }; \
                    MMA_TF32(acc[mt][g], _af0, _b0); \
                    MMA_TF32(acc[mt][g], _af1, _b1); \
                } \
            } \
        } while (0)

        LOADW(wv0, 0);
        LOADW(wv1, 1);
#pragma unroll 1
        for (int k3 = 0; k3 < 21; k3 += 3) {
            LOADW(wv2, k3 + 2);
            COMPUTE(k3, wv0);
            LOADW(wv0, k3 + 3);
            COMPUTE(k3 + 1, wv1);
            LOADW(wv1, k3 + 4);
            COMPUTE(k3 + 2, wv2);
        }
#undef LOADW
#undef COMPUTE

        if (s + 1 < T_) {
            int tn = dir ? (T_ - 2 - s) : (s + 1);
            float* sdn = smf + (p ? OFF_SD0 : OFF_SD1);
            for (int idx = tid; idx < 32 * 52; idx += 512) {
                int rr = idx / 52, c4 = idx - rr * 52;
                int k = c4 << 2;
                float4 v = (k < WD_)
                    ? *(const float4*)(doc + ((size_t)(r0 + rr) * T_ + tn) * WD_ + k)
                    : make_float4(0.f, 0.f, 0.f, 0.f);
                *(float4*)&sdn[rr * SD_STR + k] = v;
            }
        }

        float* hw = smf + (p ? OFF_H0 : OFF_H1);
#pragma unroll
        for (int mt = 0; mt < 2; mt++)
#pragma unroll
            for (int e = 0; e < 4; e++) {
                int row = mt * 16 + gid + ((e >> 1) << 3);
                int col = (w << 3) + qk + (e & 1);
                int ix = mt * 4 + e;
                float iv = acc[mt][0][e];
                float fv = acc[mt][1][e];
                float gv = acc[mt][2][e];
                float ov = acc[mt][3][e];
                float cv = sigf(fv) * c_reg[ix] + sigf(iv) * tanhf(gv);
                c_reg[ix] = cv;
                float h = sigf(ov) * tanhf(cv);
                hs_reg[ix] += h;
                hw[row * SH_STR + col] = h;
            }
        __syncthreads();
    }

#pragma unroll
    for (int mt = 0; mt < 2; mt++)
#pragma unroll
        for (int e = 0; e < 4; e++) {
            int row = mt * 16 + gid + ((e >> 1) << 3);
            int col = (w << 3) + qk + (e & 1);
            sentpres[(size_t)(r0 + row) * 256 + dir * 128 + col] =
                tanhf(hs_reg[mt * 4 + e] * (1.0f / T_));
        }
}

// ================== FUSED tag BiLSTM v3: G prefetch double-buffer ==================
#define TAG2_SMEM ((32 * SH_STR + 32 * 520) * 4)
__global__ __launch_bounds__(1024, 1)
void lstm_tag_fused(const float* __restrict__ Gt, const uint4* __restrict__ whhtag,
                    float* __restrict__ tag_out)
{
    extern __shared__ __align__(16) float smt[];
    float* sh_h = smt;
    float* sh_g = smt + 32 * SH_STR;

    int dir = blockIdx.x;
    const uint4* wp0 = whhtag + dir * 8 * 64 * 32;
    const float* G0 = Gt + (size_t)dir * 2048 * 512;

    int tid = threadIdx.x, lane = tid & 31, w = tid >> 5;
    int gid = lane >> 2, qk = (lane & 3) << 1;
    int ur = tid >> 5;
    int uc0 = (tid & 31) << 2;

    float c_reg[4];
#pragma unroll
    for (int i = 0; i < 4; i++) c_reg[i] = 0.f;
    for (int i = tid; i < 32 * SH_STR; i += 1024) sh_h[i] = 0.f;
    __syncthreads();

#define LOADG(dst, nn) do { \
        const float* _Gn = G0 + (size_t)((nn) * 32) * 512; \
        _Pragma("unroll") \
        for (int mt = 0; mt < 2; mt++) { \
            const float* _gr = _Gn + (size_t)(mt * 16 + gid) * 512; \
            _Pragma("unroll") \
            for (int nt = 0; nt < 2; nt++) { \
                int _col = (w << 4) + nt * 8 + qk; \
                dst[mt][nt][0] = *(const float2*)(_gr + _col); \
                dst[mt][nt][1] = *(const float2*)(_gr + 8 * 512 + _col); \
            } \
        } \
    } while (0)

    float2 gcur[2][2][2], gnext[2][2][2];
    LOADG(gcur, dir ? 63 : 0);

    for (int s = 0; s < 64; s++) {
        int n = dir ? (63 - s) : s;

        // init acc from prefetched G (includes bias)
        float acc[2][2][4];
#pragma unroll
        for (int mt = 0; mt < 2; mt++)
#pragma unroll
            for (int nt = 0; nt < 2; nt++) {
                acc[mt][nt][0] = gcur[mt][nt][0].x; acc[mt][nt][1] = gcur[mt][nt][0].y;
                acc[mt][nt][2] = gcur[mt][nt][1].x; acc[mt][nt][3] = gcur[mt][nt][1].y;
            }

        // prefetch next step's G (overlaps with W mma loop)
        if (s + 1 < 64) {
            int nn = dir ? (62 - s) : (s + 1);
            LOADG(gnext, nn);
        }

        uint4 wv0[2], wv1[2];
        {
            const uint4* p = wp0 + (w * 2) * 32 + lane;
            wv0[0] = p[0]; wv0[1] = p[32];
        }
#pragma unroll 1
        for (int kt = 0; kt < 8; kt += 2) {
            {
                const uint4* p = wp0 + ((kt + 1) * 64 + w * 2) * 32 + lane;
                wv1[0] = p[0]; wv1[1] = p[32];
            }
            {
                unsigned af[2][2][4];
#pragma unroll
                for (int mt = 0; mt < 2; mt++) {
                    lda_frag(af[mt][0], sh_h, SH_STR, mt * 16, kt * 16,     lane);
                    lda_frag(af[mt][1], sh_h, SH_STR, mt * 16, kt * 16 + 8, lane);
                }
#pragma unroll
                for (int nt = 0; nt < 2; nt++) {
                    unsigned b0[2] = { wv0[nt].x, wv0[nt].y };
                    unsigned b1[2] = { wv0[nt].z, wv0[nt].w };
#pragma unroll
                    for (int mt = 0; mt < 2; mt++) {
                        MMA_TF32(acc[mt][nt], af[mt][0], b0);
                        MMA_TF32(acc[mt][nt], af[mt][1], b1);
                    }
                }
            }
            if (kt + 2 < 8) {
                const uint4* p = wp0 + ((kt + 2) * 64 + w * 2) * 32 + lane;
                wv0[0] = p[0]; wv0[1] = p[32];
            }
            {
                unsigned af[2][2][4];
#pragma unroll
                for (int mt = 0; mt < 2; mt++) {
                    lda_frag(af[mt][0], sh_h, SH_STR, mt * 16, (kt + 1) * 16,     lane);
                    lda_frag(af[mt][1], sh_h, SH_STR, mt * 16, (kt + 1) * 16 + 8, lane);
                }
#pragma unroll
                for (int nt = 0; nt < 2; nt++) {
                    unsigned b0[2] = { wv1[nt].x, wv1[nt].y };
                    unsigned b1[2] = { wv1[nt].z, wv1[nt].w };
#pragma unroll
                    for (int mt = 0; mt < 2; mt++) {
                        MMA_TF32(acc[mt][nt], af[mt][0], b0);
                        MMA_TF32(acc[mt][nt], af[mt][1], b1);
                    }
                }
            }
        }

#pragma unroll
        for (int mt = 0; mt < 2; mt++)
#pragma unroll
            for (int nt = 0; nt < 2; nt++) {
                int lrow = mt * 16 + gid;
                int col = (w << 4) + nt * 8 + qk;
                *(float2*)&sh_g[lrow * 520 + col] = make_float2(acc[mt][nt][0], acc[mt][nt][1]);
                *(float2*)&sh_g[(lrow + 8) * 520 + col] = make_float2(acc[mt][nt][2], acc[mt][nt][3]);
            }
        __syncthreads();

#pragma unroll
        for (int jj = 0; jj < 4; jj++) {
            int j = uc0 + jj;
            float ig = sh_g[ur * 520 + j];
            float fg = sh_g[ur * 520 + 128 + j];
            float gg = sh_g[ur * 520 + 256 + j];
            float og = sh_g[ur * 520 + 384 + j];
            float cv = sigf(fg) * c_reg[jj] + sigf(ig) * tanhf(gg);
            c_reg[jj] = cv;
            float h = sigf(og) * tanhf(cv);
            sh_h[ur * SH_STR + j] = h;
            tag_out[(size_t)(ur * 64 + n) * 256 + dir * 128 + j] = tanhf(h);
        }
        __syncthreads();

        // rotate prefetch buffer
#pragma unroll
        for (int mt = 0; mt < 2; mt++)
#pragma unroll
            for (int nt = 0; nt < 2; nt++) {
                gcur[mt][nt][0] = gnext[mt][nt][0];
                gcur[mt][nt][1] = gnext[mt][nt][1];
            }
    }
#undef LOADG
}

// ================== generic tiled SGEMM (small GEMMs, fp32) ==================
__global__ void sgemm_k(const float* __restrict__ A, const float* __restrict__ W,
                        const float* __restrict__ bias, float* __restrict__ C,
                        int M, int K, int G, int amode, int relu)
{
    __shared__ float As[8][64];
    __shared__ float Ws[8][64];
    int tid = threadIdx.x;
    int mb = blockIdx.y << 6;
    int gb = blockIdx.x << 6;
    int tx = tid & 15, ty = tid >> 4;
    int mi = tid & 63;
    int kh = (tid >> 6) << 1;

    int m = mb + mi;
    long arow;
    if (amode == 0) arow = (long)m * K;
    else { int b = m & 31; int n = m >> 5; arow = (long)((b << 6) + n) * K; }
    long wrow = (long)(gb + mi) * K;

    float acc[4][4];
#pragma unroll
    for (int i = 0; i < 4; i++)
#pragma unroll
        for (int j = 0; j < 4; j++) acc[i][j] = 0.0f;

    for (int k0 = 0; k0 < K; k0 += 8) {
        float2 av = *(const float2*)(A + arow + k0 + kh);
        float2 wv = *(const float2*)(W + wrow + k0 + kh);
        __syncthreads();
        As[kh][mi] = av.x; As[kh + 1][mi] = av.y;
        Ws[kh][mi] = wv.x; Ws[kh + 1][mi] = wv.y;
        __syncthreads();
#pragma unroll
        for (int kk = 0; kk < 8; kk++) {
            float4 a = *(float4*)(&As[kk][ty << 2]);
            float4 w = *(float4*)(&Ws[kk][tx << 2]);
            float aa[4] = {a.x, a.y, a.z, a.w};
            float ww[4] = {w.x, w.y, w.z, w.w};
#pragma unroll
            for (int i = 0; i < 4; i++)
#pragma unroll
                for (int j = 0; j < 4; j++) acc[i][j] += aa[i] * ww[j];
        }
    }

    float4 b4 = *(const float4*)(bias + gb + (tx << 2));
    float bb[4] = {b4.x, b4.y, b4.z, b4.w};
#pragma unroll
    for (int i = 0; i < 4; i++) {
        float4 r;
        r.x = acc[i][0] + bb[0];
        r.y = acc[i][1] + bb[1];
        r.z = acc[i][2] + bb[2];
        r.w = acc[i][3] + bb[3];
        if (relu) {
            r.x = fmaxf(r.x, 0.f); r.y = fmaxf(r.y, 0.f);
            r.z = fmaxf(r.z, 0.f); r.w = fmaxf(r.w, 0.f);
        }
        *(float4*)(C + (size_t)(mb + (ty << 2) + i) * G + gb + (tx << 2)) = r;
    }
}

// ================== SPP ==================
__global__ void spp_kernel(const float* __restrict__ q, const float* __restrict__ k,
                           float* __restrict__ out)
{
    int bn = blockIdx.x;
    int b = bn >> 6;
    __shared__ float shq[256];
    __shared__ float att[64];
    __shared__ float e8[8];
    int tid = threadIdx.x;
    for (int l = tid; l < 256; l += 64) shq[l] = q[(size_t)bn * 256 + l];
    __syncthreads();
    const float* kr = k + (size_t)(b * 64 + tid) * 256;
    float s = 0.f;
    for (int l = 0; l < 256; l += 4) {
        float4 qa = *(float4*)&shq[l];
        float4 ka = *(const float4*)&kr[l];
        s += qa.x * ka.x + qa.y * ka.y + qa.z * ka.z + qa.w * ka.w;
    }
    att[tid] = s * 0.0625f;
    __syncthreads();
    if (tid < 8) {
        float m = att[tid * 8];
#pragma unroll
        for (int l = 1; l < 8; l++) m = fmaxf(m, att[tid * 8 + l]);
        e8[tid] = m;
    }
    __syncthreads();
    if (tid == 0) {
        float q4[4];
#pragma unroll
        for (int l = 0; l < 4; l++) q4[l] = fmaxf(e8[2 * l], e8[2 * l + 1]);
        float h2a = fmaxf(q4[0], q4[1]);
        float h2b = fmaxf(q4[2], q4[3]);
        float* o = out + bn * 15;
        o[0] = fmaxf(h2a, h2b);
        o[1] = h2a; o[2] = h2b;
        o[3] = q4[0]; o[4] = q4[1]; o[5] = q4[2]; o[6] = q4[3];
#pragma unroll
        for (int l = 0; l < 8; l++) o[7 + l] = e8[l];
    }
}

// ================== GCN (bank-conflict-free: shx stride 257) ==================
#define XS 257
#define GCN_SMEM ((64 * XS + 64 * 64 + 64) * 4)
__global__ void gcn_kernel(const float* __restrict__ x, float* __restrict__ agg)
{
    extern __shared__ float gs[];
    float* shx = gs;                 // [64][257]
    float* shc = gs + 64 * XS;       // [64][64]
    float* shn = shc + 4096;         // [64]
    int b = blockIdx.x;
    int tid = threadIdx.x;
    for (int l = tid; l < 16384; l += 256) {
        int i = l >> 8, d = l & 255;
        shx[i * XS + d] = x[(size_t)b * 16384 + l];
    }
    __syncthreads();
    if (tid < 64) {
        float s = 0.f;
        for (int l = 0; l < 256; l++) { float v = shx[tid * XS + l]; s += v * v; }
        shn[tid] = sqrtf(s) + 1e-8f;
    }
    __syncthreads();
    for (int p = tid; p < 4096; p += 256) {
        int i = p >> 6, j = p & 63;
        float s = 0.f;
        for (int l = 0; l < 256; l++) s += shx[i * XS + l] * shx[j * XS + l];
        shc[p] = s / (shn[i] * shn[j]);
    }
    __syncthreads();
    for (int p = tid; p < 16384; p += 256) {
        int i = p >> 8, d = p & 255;
        float s = 2.0f * shx[i * XS + d];
        for (int j = 0; j < 64; j++) s += shc[i * 64 + j] * shx[j * XS + d];
        agg[(size_t)b * 16384 + p] = s * (1.0f / 66.0f);
    }
}

// ================== classifier + log_softmax (warp per class) ==================
__global__ void cls_kernel(const float* __restrict__ tago, const float* __restrict__ sFt,
                           const float* __restrict__ rFt, const float* __restrict__ W,
                           const float* __restrict__ bias, float* __restrict__ out)
{
    int bn = blockIdx.x;
    int tid = threadIdx.x;
    int c = tid >> 5, lane = tid & 31;
    __shared__ float sh[8];
    const float* w = W + c * 286;
    const float* t = tago + (size_t)bn * 256;
    float s = 0.f;
    for (int l = lane; l < 256; l += 32) s += t[l] * w[l];
    if (lane < 15) {
        s += sFt[bn * 15 + lane] * w[256 + lane];
        s += rFt[bn * 15 + lane] * w[271 + lane];
    }
#pragma unroll
    for (int off = 16; off > 0; off >>= 1)
        s += __shfl_down_sync(0xFFFFFFFF, s, off);
    if (lane == 0) sh[c] = s + bias[c];
    __syncthreads();
    if (tid < 8) {
        float m = sh[0];
#pragma unroll
        for (int l = 1; l < 8; l++) m = fmaxf(m, sh[l]);
        float se = 0.f;
#pragma unroll
        for (int l = 0; l < 8; l++) se += expf(sh[l] - m);
        out[bn * 8 + tid] = sh[tid] - m - logf(se);
    }
}

// ================== launch ==================
extern "C" void kernel_launch(void* const* d_in, const int* in_sizes, int n_in,
                              void* d_out, int out_size)
{
    const float* documents = (const float*)d_in[0];
    const float* sw_ih_f = (const float*)d_in[1];
    const float* sw_hh_f = (const float*)d_in[2];
    const float* sb_f    = (const float*)d_in[3];
    const float* sw_ih_b = (const float*)d_in[4];
    const float* sw_hh_b = (const float*)d_in[5];
    const float* sb_b    = (const float*)d_in[6];
    const float* sf_Wq = (const float*)d_in[7];
    const float* sf_bq = (const float*)d_in[8];
    const float* sf_Wk = (const float*)d_in[9];
    const float* sf_bk = (const float*)d_in[10];
    const float* rf_Wq = (const float*)d_in[11];
    const float* rf_bq = (const float*)d_in[12];
    const float* rf_Wk = (const float*)d_in[13];
    const float* rf_bk = (const float*)d_in[14];
    const float* tw_ih_f = (const float*)d_in[15];
    const float* tw_hh_f = (const float*)d_in[16];
    const float* tb_f    = (const float*)d_in[17];
    const float* tw_ih_b = (const float*)d_in[18];
    const float* tw_hh_b = (const float*)d_in[19];
    const float* tb_b    = (const float*)d_in[20];
    const float* sage_W = (const float*)d_in[21];
    const float* sage_b = (const float*)d_in[22];
    const float* cls_W  = (const float*)d_in[23];
    const float* cls_b  = (const float*)d_in[24];

    float* out = (float*)d_out;
    float* result_out = out;
    float* gcn_out = out + B_ * N_ * C_;

    float *sentpres, *qb, *kb, *sFt, *rFt, *gtag, *tago, *agg;
    uint4 *wihp, *whhp, *whhtagp;
    cudaGetSymbolAddress((void**)&wihp, wih_pk_buf);
    cudaGetSymbolAddress((void**)&whhp, whh_pk_buf);
    cudaGetSymbolAddress((void**)&whhtagp, whh_tag_pk_buf);
    cudaGetSymbolAddress((void**)&sentpres, sentpres_buf);
    cudaGetSymbolAddress((void**)&qb, q_buf);
    cudaGetSymbolAddress((void**)&kb, k_buf);
    cudaGetSymbolAddress((void**)&sFt, sentFt_buf);
    cudaGetSymbolAddress((void**)&rFt, roleFt_buf);
    cudaGetSymbolAddress((void**)&gtag, g_tag_buf);
    cudaGetSymbolAddress((void**)&tago, tag_out_buf);
    cudaGetSymbolAddress((void**)&agg, agg_buf);

    cudaFuncSetAttribute(lstm_sent_fused, cudaFuncAttributeMaxDynamicSharedMemorySize, FUSED_SMEM);
    cudaFuncSetAttribute(lstm_tag_fused, cudaFuncAttributeMaxDynamicSharedMemorySize, TAG2_SMEM);
    cudaFuncSetAttribute(gcn_kernel, cudaFuncAttributeMaxDynamicSharedMemorySize, GCN_SMEM);

    // prep
    pack_wih_tf32<<<(2 * 13 * 64 * 32 + 255) / 256, 256>>>(sw_ih_f, sw_ih_b, wihp);
    pack_whh_tf32<<<128, 256>>>(sw_hh_f, sw_hh_b, whhp);
    pack_whh_tf32<<<128, 256>>>(tw_hh_f, tw_hh_b, whhtagp);

    // FUSED sentence BiLSTM v6 (index 3 — ncu capture slot)
    lstm_sent_fused<<<dim3(64, 2), 512, FUSED_SMEM>>>(documents, wihp, whhp, sb_f, sb_b, sentpres);

    // sentFt SPP
    sgemm_k<<<dim3(4, 32), 256>>>(sentpres, sf_Wq, sf_bq, qb, BN_, D2_, D2_, 0, 0);
    sgemm_k<<<dim3(4, 32), 256>>>(sentpres, sf_Wk, sf_bk, kb, BN_, D2_, D2_, 0, 0);
    spp_kernel<<<2048, 64>>>(qb, kb, sFt);

    // Tag LSTM input projections
    sgemm_k<<<dim3(8, 32), 256>>>(sentpres, tw_ih_f, tb_f, gtag,             BN_, D2_, G4_, 1, 0);
    sgemm_k<<<dim3(8, 32), 256>>>(sentpres, tw_ih_b, tb_b, gtag + BN_ * G4_, BN_, D2_, G4_, 1, 0);

    // FUSED tag BiLSTM v3
    lstm_tag_fused<<<2, 1024, TAG2_SMEM>>>(gtag, whhtagp, tago);

    // GCN
    gcn_kernel<<<32, 256, GCN_SMEM>>>(tago, agg);
    sgemm_k<<<dim3(4, 32), 256>>>(agg, sage_W, sage_b, gcn_out, BN_, D2_, D2_, 0, 1);

    // roleFt SPP
    sgemm_k<<<dim3(4, 32), 256>>>(tago, rf_Wq, rf_bq, qb, BN_, D2_, D2_, 0, 0);
    sgemm_k<<<dim3(4, 32), 256>>>(tago, rf_Wk, rf_bk, kb, BN_, D2_, D2_, 0, 0);
    spp_kernel<<<2048, 64>>>(qb, kb, rFt);

    cls_kernel<<<2048, 256>>>(tago, sFt, rFt, cls_W, cls_b, result_out);

    (void)in_sizes; (void)n_in; (void)out_size;
}

// round 13
// speedup vs baseline: 1.3191x; 1.0133x over previous
#include <cuda_runtime.h>
#include <cuda_bf16.h>
#include <stdint.h>
#include <math.h>

// ---------------- problem constants ----------------
#define B_    32
#define N_    64
#define T_    50
#define WD_   200
#define H_    128
#define G4_   512
#define D2_   256
#define BN_   2048
#define C_    8

// ---------------- scratch ----------------
__device__ uint4 wih_pk_buf[2 * 13 * 64 * 32];
__device__ uint4 whh_pk_buf[2 * 8 * 64 * 32];
__device__ uint4 whh_tag_pk_buf[2 * 8 * 64 * 32];
__device__ float sentpres_buf[BN_ * D2_];
__device__ float q_buf[BN_ * D2_];
__device__ float k_buf[BN_ * D2_];
__device__ float sentFt_buf[BN_ * 15];
__device__ float roleFt_buf[BN_ * 15];
__device__ float g_tag_buf[2 * BN_ * G4_];
__device__ float tag_out_buf[BN_ * D2_];
__device__ float agg_buf[BN_ * D2_];

__device__ __forceinline__ float sigf(float x) { return __fdividef(1.0f, 1.0f + __expf(-x)); }

#define MMA_TF32(d, a, b) \
    asm volatile("mma.sync.aligned.m16n8k8.row.col.f32.tf32.tf32.f32 " \
                 "{%0,%1,%2,%3},{%4,%5,%6,%7},{%8,%9},{%0,%1,%2,%3};\n" \
                 : "+f"(d[0]), "+f"(d[1]), "+f"(d[2]), "+f"(d[3]) \
                 : "r"(a[0]), "r"(a[1]), "r"(a[2]), "r"(a[3]), "r"(b[0]), "r"(b[1]))

__device__ __forceinline__ void ldsm_x4_a(unsigned af[4], unsigned addr)
{
    asm volatile("ldmatrix.sync.aligned.m8n8.x4.shared.b16 {%0,%1,%2,%3}, [%4];"
                 : "=r"(af[0]), "=r"(af[1]), "=r"(af[2]), "=r"(af[3]) : "r"(addr));
}

__device__ __forceinline__ void ldsm_x4(unsigned& r0, unsigned& r1, unsigned& r2, unsigned& r3,
                                        const float* p)
{
    unsigned addr = (unsigned)__cvta_generic_to_shared(p);
    asm volatile("ldmatrix.sync.aligned.m8n8.x4.shared.b16 {%0,%1,%2,%3}, [%4];"
                 : "=r"(r0), "=r"(r1), "=r"(r2), "=r"(r3) : "r"(addr));
}

__device__ __forceinline__ void lda_frag(unsigned af[4], const float* base, int stride,
                                         int mrow0, int kcol0, int lane)
{
    int tile = lane >> 3, rin = lane & 7;
    int row = mrow0 + ((tile & 1) << 3) + rin;
    int col = kcol0 + ((tile >> 1) << 2);
    ldsm_x4(af[0], af[1], af[2], af[3], base + row * stride + col);
}

// ================== pack W_ih (512x200) into tf32 B-fragments ==================
__global__ void pack_wih_tf32(const float* __restrict__ wf, const float* __restrict__ wb,
                              uint4* __restrict__ out)
{
    int i = blockIdx.x * 256 + threadIdx.x;
    if (i >= 2 * 13 * 64 * 32) return;
    const int per = 13 * 64 * 32;
    int dir = i / per, rem = i % per;
    int kt = rem >> 11, ng = (rem >> 5) & 63, lane = rem & 31;
    const float* w = dir ? wb : wf;
    int n = ng * 8 + (lane >> 2);
    int k = kt * 16 + (lane & 3);
    uint4 v;
    v.x = (k      < WD_) ? __float_as_uint(w[n * WD_ + k])      : 0u;
    v.y = (k + 4  < WD_) ? __float_as_uint(w[n * WD_ + k + 4])  : 0u;
    v.z = (k + 8  < WD_) ? __float_as_uint(w[n * WD_ + k + 8])  : 0u;
    v.w = (k + 12 < WD_) ? __float_as_uint(w[n * WD_ + k + 12]) : 0u;
    out[i] = v;
}

// ================== pack a 512x128 W_hh into tf32 B-fragments ==================
__global__ void pack_whh_tf32(const float* __restrict__ wf, const float* __restrict__ wb,
                              uint4* __restrict__ out)
{
    int i = blockIdx.x * 256 + threadIdx.x;
    if (i >= 2 * 8 * 64 * 32) return;
    int lane = i & 31, ng = (i >> 5) & 63, kt = (i >> 11) & 7, dir = i >> 14;
    const float* w = dir ? wb : wf;
    int n = ng * 8 + (lane >> 2);
    int k = kt * 16 + (lane & 3);
    uint4 v;
    v.x = __float_as_uint(w[n * 128 + k]);
    v.y = __float_as_uint(w[n * 128 + k + 4]);
    v.z = __float_as_uint(w[n * 128 + k + 8]);
    v.w = __float_as_uint(w[n * 128 + k + 12]);
    out[i] = v;
}

// ================== FUSED sentence BiLSTM v6 ==================
#define SD_STR 212
#define SH_STR 132
#define OFF_SD0   0
#define OFF_SD1   6784
#define OFF_H0    13568
#define OFF_H1    17792
#define OFF_BIAS  22016
#define FUSED_SMEM ((22016 + 512) * 4)
#define SD_BUFB   27136
#define SH_BUFB   16896

__global__ __launch_bounds__(512, 1)
void lstm_sent_fused(const float* __restrict__ doc,
                     const uint4* __restrict__ wih, const uint4* __restrict__ whh,
                     const float* __restrict__ biasf, const float* __restrict__ biasb,
                     float* __restrict__ sentpres)
{
    extern __shared__ __align__(16) float smf[];
    float* sbias = smf + OFF_BIAS;

    int dir = blockIdx.y;
    int r0 = blockIdx.x << 5;
    const float* bias = dir ? biasb : biasf;

    int tid = threadIdx.x, lane = tid & 31, w = tid >> 5;
    int gid = lane >> 2, qk = (lane & 3) << 1;

    const uint4* wp_ih = wih + dir * 13 * 64 * 32 + w * 32 + lane;
    const uint4* wp_hh = whh + dir * 8 * 64 * 32 + w * 32 + lane;

    unsigned smbase = (unsigned)__cvta_generic_to_shared(smf);
    int tile = lane >> 3, rin = lane & 7;
    int r_off = ((tile & 1) << 3) + rin;
    int c_off = (tile >> 1) << 2;
    unsigned sd_addr[2], sh_addr[2];
#pragma unroll
    for (int mt = 0; mt < 2; mt++) {
        sd_addr[mt] = smbase + ((unsigned)(OFF_SD0 + (mt * 16 + r_off) * SD_STR + c_off) << 2);
        sh_addr[mt] = smbase + ((unsigned)(OFF_H0 + (mt * 16 + r_off) * SH_STR + c_off) << 2);
    }

    float c_reg[8], hs_reg[8];
#pragma unroll
    for (int i = 0; i < 8; i++) { c_reg[i] = 0.f; hs_reg[i] = 0.f; }
    for (int i = tid; i < 2 * 32 * SH_STR; i += 512) smf[OFF_H0 + i] = 0.f;
    if (tid < 512) sbias[tid] = bias[tid];

    {
        int t0 = dir ? (T_ - 1) : 0;
        for (int idx = tid; idx < 32 * 52; idx += 512) {
            int rr = idx / 52, c4 = idx - rr * 52;
            int k = c4 << 2;
            float4 v = (k < WD_)
                ? *(const float4*)(doc + ((size_t)(r0 + rr) * T_ + t0) * WD_ + k)
                : make_float4(0.f, 0.f, 0.f, 0.f);
            *(float4*)&smf[OFF_SD0 + rr * SD_STR + k] = v;
        }
    }
    __syncthreads();

    for (int s = 0; s < T_; s++) {
        int p = s & 1;
        unsigned po = p ? SD_BUFB : 0u;
        unsigned ph = p ? SH_BUFB : 0u;

        float acc[2][4][4];
#pragma unroll
        for (int mt = 0; mt < 2; mt++)
#pragma unroll
            for (int g = 0; g < 4; g++) {
                int col = (g << 7) + (w << 3) + qk;
                float b0 = sbias[col], b1 = sbias[col + 1];
                acc[mt][g][0] = b0; acc[mt][g][1] = b1;
                acc[mt][g][2] = b0; acc[mt][g][3] = b1;
            }

        uint4 wv0[4], wv1[4], wv2[4];

#define LOADW(dst, ktv) do { \
            int _kt = (ktv); \
            if (_kt < 21) { \
                const uint4* _p = (_kt < 13) ? (wp_ih + _kt * 2048) \
                                             : (wp_hh + (_kt - 13) * 2048); \
                dst[0] = _p[0];    dst[1] = _p[512]; \
                dst[2] = _p[1024]; dst[3] = _p[1536]; \
            } \
        } while (0)

#define COMPUTE(ktv, wv) do { \
            int _kt = (ktv); \
            _Pragma("unroll") \
            for (int mt = 0; mt < 2; mt++) { \
                unsigned _a0 = (_kt < 13) ? (sd_addr[mt] + po + ((unsigned)_kt << 6)) \
                                          : (sh_addr[mt] + ph + ((unsigned)(_kt - 13) << 6)); \
                unsigned _af0[4], _af1[4]; \
                ldsm_x4_a(_af0, _a0); \
                ldsm_x4_a(_af1, _a0 + 32); \
                _Pragma("unroll") \
                for (int g = 0; g < 4; g++) { \
                    unsigned _b0[2] = { wv[g].x, wv[g].y }; \
                    unsigned _b1[2] = { wv[g].z, wv[g].w }; \
                    MMA_TF32(acc[mt][g], _af0, _b0); \
                    MMA_TF32(acc[mt][g], _af1, _b1); \
                } \
            } \
        } while (0)

        LOADW(wv0, 0);
        LOADW(wv1, 1);
#pragma unroll 1
        for (int k3 = 0; k3 < 21; k3 += 3) {
            LOADW(wv2, k3 + 2);
            COMPUTE(k3, wv0);
            LOADW(wv0, k3 + 3);
            COMPUTE(k3 + 1, wv1);
            LOADW(wv1, k3 + 4);
            COMPUTE(k3 + 2, wv2);
        }
#undef LOADW
#undef COMPUTE

        if (s + 1 < T_) {
            int tn = dir ? (T_ - 2 - s) : (s + 1);
            float* sdn = smf + (p ? OFF_SD0 : OFF_SD1);
            for (int idx = tid; idx < 32 * 52; idx += 512) {
                int rr = idx / 52, c4 = idx - rr * 52;
                int k = c4 << 2;
                float4 v = (k < WD_)
                    ? *(const float4*)(doc + ((size_t)(r0 + rr) * T_ + tn) * WD_ + k)
                    : make_float4(0.f, 0.f, 0.f, 0.f);
                *(float4*)&sdn[rr * SD_STR + k] = v;
            }
        }

        float* hw = smf + (p ? OFF_H0 : OFF_H1);
#pragma unroll
        for (int mt = 0; mt < 2; mt++)
#pragma unroll
            for (int e = 0; e < 4; e++) {
                int row = mt * 16 + gid + ((e >> 1) << 3);
                int col = (w << 3) + qk + (e & 1);
                int ix = mt * 4 + e;
                float iv = acc[mt][0][e];
                float fv = acc[mt][1][e];
                float gv = acc[mt][2][e];
                float ov = acc[mt][3][e];
                float cv = sigf(fv) * c_reg[ix] + sigf(iv) * tanhf(gv);
                c_reg[ix] = cv;
                float h = sigf(ov) * tanhf(cv);
                hs_reg[ix] += h;
                hw[row * SH_STR + col] = h;
            }
        __syncthreads();
    }

#pragma unroll
    for (int mt = 0; mt < 2; mt++)
#pragma unroll
        for (int e = 0; e < 4; e++) {
            int row = mt * 16 + gid + ((e >> 1) << 3);
            int col = (w << 3) + qk + (e & 1);
            sentpres[(size_t)(r0 + row) * 256 + dir * 128 + col] =
                tanhf(hs_reg[mt * 4 + e] * (1.0f / T_));
        }
}

// ================== FUSED tag BiLSTM v3 ==================
#define TAG2_SMEM ((32 * SH_STR + 32 * 520) * 4)
__global__ __launch_bounds__(1024, 1)
void lstm_tag_fused(const float* __restrict__ Gt, const uint4* __restrict__ whhtag,
                    float* __restrict__ tag_out)
{
    extern __shared__ __align__(16) float smt[];
    float* sh_h = smt;
    float* sh_g = smt + 32 * SH_STR;

    int dir = blockIdx.x;
    const uint4* wp0 = whhtag + dir * 8 * 64 * 32;
    const float* G0 = Gt + (size_t)dir * 2048 * 512;

    int tid = threadIdx.x, lane = tid & 31, w = tid >> 5;
    int gid = lane >> 2, qk = (lane & 3) << 1;
    int ur = tid >> 5;
    int uc0 = (tid & 31) << 2;

    float c_reg[4];
#pragma unroll
    for (int i = 0; i < 4; i++) c_reg[i] = 0.f;
    for (int i = tid; i < 32 * SH_STR; i += 1024) sh_h[i] = 0.f;
    __syncthreads();

#define LOADG(dst, nn) do { \
        const float* _Gn = G0 + (size_t)((nn) * 32) * 512; \
        _Pragma("unroll") \
        for (int mt = 0; mt < 2; mt++) { \
            const float* _gr = _Gn + (size_t)(mt * 16 + gid) * 512; \
            _Pragma("unroll") \
            for (int nt = 0; nt < 2; nt++) { \
                int _col = (w << 4) + nt * 8 + qk; \
                dst[mt][nt][0] = *(const float2*)(_gr + _col); \
                dst[mt][nt][1] = *(const float2*)(_gr + 8 * 512 + _col); \
            } \
        } \
    } while (0)

    float2 gcur[2][2][2], gnext[2][2][2];
    LOADG(gcur, dir ? 63 : 0);

    for (int s = 0; s < 64; s++) {
        int n = dir ? (63 - s) : s;

        float acc[2][2][4];
#pragma unroll
        for (int mt = 0; mt < 2; mt++)
#pragma unroll
            for (int nt = 0; nt < 2; nt++) {
                acc[mt][nt][0] = gcur[mt][nt][0].x; acc[mt][nt][1] = gcur[mt][nt][0].y;
                acc[mt][nt][2] = gcur[mt][nt][1].x; acc[mt][nt][3] = gcur[mt][nt][1].y;
            }

        if (s + 1 < 64) {
            int nn = dir ? (62 - s) : (s + 1);
            LOADG(gnext, nn);
        }

        uint4 wv0[2], wv1[2];
        {
            const uint4* p = wp0 + (w * 2) * 32 + lane;
            wv0[0] = p[0]; wv0[1] = p[32];
        }
#pragma unroll 1
        for (int kt = 0; kt < 8; kt += 2) {
            {
                const uint4* p = wp0 + ((kt + 1) * 64 + w * 2) * 32 + lane;
                wv1[0] = p[0]; wv1[1] = p[32];
            }
            {
                unsigned af[2][2][4];
#pragma unroll
                for (int mt = 0; mt < 2; mt++) {
                    lda_frag(af[mt][0], sh_h, SH_STR, mt * 16, kt * 16,     lane);
                    lda_frag(af[mt][1], sh_h, SH_STR, mt * 16, kt * 16 + 8, lane);
                }
#pragma unroll
                for (int nt = 0; nt < 2; nt++) {
                    unsigned b0[2] = { wv0[nt].x, wv0[nt].y };
                    unsigned b1[2] = { wv0[nt].z, wv0[nt].w };
#pragma unroll
                    for (int mt = 0; mt < 2; mt++) {
                        MMA_TF32(acc[mt][nt], af[mt][0], b0);
                        MMA_TF32(acc[mt][nt], af[mt][1], b1);
                    }
                }
            }
            if (kt + 2 < 8) {
                const uint4* p = wp0 + ((kt + 2) * 64 + w * 2) * 32 + lane;
                wv0[0] = p[0]; wv0[1] = p[32];
            }
            {
                unsigned af[2][2][4];
#pragma unroll
                for (int mt = 0; mt < 2; mt++) {
                    lda_frag(af[mt][0], sh_h, SH_STR, mt * 16, (kt + 1) * 16,     lane);
                    lda_frag(af[mt][1], sh_h, SH_STR, mt * 16, (kt + 1) * 16 + 8, lane);
                }
#pragma unroll
                for (int nt = 0; nt < 2; nt++) {
                    unsigned b0[2] = { wv1[nt].x, wv1[nt].y };
                    unsigned b1[2] = { wv1[nt].z, wv1[nt].w };
#pragma unroll
                    for (int mt = 0; mt < 2; mt++) {
                        MMA_TF32(acc[mt][nt], af[mt][0], b0);
                        MMA_TF32(acc[mt][nt], af[mt][1], b1);
                    }
                }
            }
        }

#pragma unroll
        for (int mt = 0; mt < 2; mt++)
#pragma unroll
            for (int nt = 0; nt < 2; nt++) {
                int lrow = mt * 16 + gid;
                int col = (w << 4) + nt * 8 + qk;
                *(float2*)&sh_g[lrow * 520 + col] = make_float2(acc[mt][nt][0], acc[mt][nt][1]);
                *(float2*)&sh_g[(lrow + 8) * 520 + col] = make_float2(acc[mt][nt][2], acc[mt][nt][3]);
            }
        __syncthreads();

#pragma unroll
        for (int jj = 0; jj < 4; jj++) {
            int j = uc0 + jj;
            float ig = sh_g[ur * 520 + j];
            float fg = sh_g[ur * 520 + 128 + j];
            float gg = sh_g[ur * 520 + 256 + j];
            float og = sh_g[ur * 520 + 384 + j];
            float cv = sigf(fg) * c_reg[jj] + sigf(ig) * tanhf(gg);
            c_reg[jj] = cv;
            float h = sigf(og) * tanhf(cv);
            sh_h[ur * SH_STR + j] = h;
            tag_out[(size_t)(ur * 64 + n) * 256 + dir * 128 + j] = tanhf(h);
        }
        __syncthreads();

#pragma unroll
        for (int mt = 0; mt < 2; mt++)
#pragma unroll
            for (int nt = 0; nt < 2; nt++) {
                gcur[mt][nt][0] = gnext[mt][nt][0];
                gcur[mt][nt][1] = gnext[mt][nt][1];
            }
    }
#undef LOADG
}

// ================== tf32 mma GEMM, K=256: C[M,G] = A @ W^T + bias ==================
// BM=128, BN=128, BK=16, 256 threads / 8 warps. amode=1: A row m -> ((m&31)<<6)+(m>>5).
__global__ __launch_bounds__(256, 2)
void mma_gemm256(const float* __restrict__ A, const float* __restrict__ W,
                 const float* __restrict__ bias, float* __restrict__ C,
                 int amode, int relu)
{
    __shared__ __align__(16) float smf[5120];   // sA[128][20] | sB[128][20]; aliased sC[32][128]
    float* sA = smf;
    float* sB = smf + 2560;
    float* sC = smf;

    int tid = threadIdx.x;
    int lane = tid & 31, wid = tid >> 5;
    int wm = wid & 3, wn = wid >> 2;
    int mb = blockIdx.y << 7, nb = blockIdx.x << 7;
    int lrow = tid >> 1, lhalf = tid & 1;
    int r = lane >> 2, tc = lane & 3, c2 = tc << 1;

    int am = mb + lrow;
    long arow = amode ? ((long)(((am & 31) << 6) + (am >> 5)) << 8) : ((long)am << 8);
    const float* ap = A + arow + lhalf * 8;
    const float* bp = W + ((size_t)(nb + lrow) << 8) + lhalf * 8;

    float acc[2][8][4];
#pragma unroll
    for (int mi = 0; mi < 2; mi++)
#pragma unroll
        for (int ni = 0; ni < 8; ni++)
#pragma unroll
            for (int e = 0; e < 4; e++) acc[mi][ni][e] = 0.f;

#pragma unroll 1
    for (int kb = 0; kb < 256; kb += 16) {
        float4 va0 = *(const float4*)(ap + kb);
        float4 va1 = *(const float4*)(ap + kb + 4);
        float4 vb0 = *(const float4*)(bp + kb);
        float4 vb1 = *(const float4*)(bp + kb + 4);
        __syncthreads();
        *(float4*)&sA[lrow * 20 + lhalf * 8]     = va0;
        *(float4*)&sA[lrow * 20 + lhalf * 8 + 4] = va1;
        *(float4*)&sB[lrow * 20 + lhalf * 8]     = vb0;
        *(float4*)&sB[lrow * 20 + lhalf * 8 + 4] = vb1;
        __syncthreads();

        unsigned af[2][2][4];
#pragma unroll
        for (int mi = 0; mi < 2; mi++) {
            int rb = (wm * 32 + mi * 16 + r) * 20;
#pragma unroll
            for (int kh = 0; kh < 2; kh++) {
                af[mi][kh][0] = __float_as_uint(sA[rb + kh * 8 + tc]);
                af[mi][kh][1] = __float_as_uint(sA[rb + 160 + kh * 8 + tc]);
                af[mi][kh][2] = __float_as_uint(sA[rb + kh * 8 + tc + 4]);
                af[mi][kh][3] = __float_as_uint(sA[rb + 160 + kh * 8 + tc + 4]);
            }
        }
#pragma unroll
        for (int ni = 0; ni < 8; ni++) {
            int nrb = (wn * 64 + ni * 8 + r) * 20;
#pragma unroll
            for (int kh = 0; kh < 2; kh++) {
                unsigned bf[2];
                bf[0] = __float_as_uint(sB[nrb + kh * 8 + tc]);
                bf[1] = __float_as_uint(sB[nrb + kh * 8 + tc + 4]);
#pragma unroll
                for (int mi = 0; mi < 2; mi++)
                    MMA_TF32(acc[mi][ni], af[mi][kh], bf);
            }
        }
    }
    // staged coalesced epilogue
    int G = gridDim.x << 7;
    for (int wmc = 0; wmc < 4; wmc++) {
        __syncthreads();
        if (wm == wmc) {
#pragma unroll
            for (int mi = 0; mi < 2; mi++)
#pragma unroll
                for (int ni = 0; ni < 8; ni++) {
                    int lr2 = mi * 16 + r;
                    int col = wn * 64 + ni * 8 + c2;
                    float b0 = bias[nb + col], b1 = bias[nb + col + 1];
                    float v0 = acc[mi][ni][0] + b0, v1 = acc[mi][ni][1] + b1;
                    float v2 = acc[mi][ni][2] + b0, v3 = acc[mi][ni][3] + b1;
                    if (relu) {
                        v0 = fmaxf(v0, 0.f); v1 = fmaxf(v1, 0.f);
                        v2 = fmaxf(v2, 0.f); v3 = fmaxf(v3, 0.f);
                    }
                    *(float2*)&sC[lr2 * 128 + col] = make_float2(v0, v1);
                    *(float2*)&sC[(lr2 + 8) * 128 + col] = make_float2(v2, v3);
                }
        }
        __syncthreads();
#pragma unroll
        for (int l = 0; l < 4; l++) {
            int idx = tid + l * 256;
            int row = idx >> 5, c4 = idx & 31;
            *(float4*)&C[(size_t)(mb + wmc * 32 + row) * G + nb + c4 * 4] =
                ((float4*)sC)[idx];
        }
    }
}

// ================== SPP ==================
__global__ void spp_kernel(const float* __restrict__ q, const float* __restrict__ k,
                           float* __restrict__ out)
{
    int bn = blockIdx.x;
    int b = bn >> 6;
    __shared__ float shq[256];
    __shared__ float att[64];
    __shared__ float e8[8];
    int tid = threadIdx.x;
    for (int l = tid; l < 256; l += 64) shq[l] = q[(size_t)bn * 256 + l];
    __syncthreads();
    const float* kr = k + (size_t)(b * 64 + tid) * 256;
    float s = 0.f;
    for (int l = 0; l < 256; l += 4) {
        float4 qa = *(float4*)&shq[l];
        float4 ka = *(const float4*)&kr[l];
        s += qa.x * ka.x + qa.y * ka.y + qa.z * ka.z + qa.w * ka.w;
    }
    att[tid] = s * 0.0625f;
    __syncthreads();
    if (tid < 8) {
        float m = att[tid * 8];
#pragma unroll
        for (int l = 1; l < 8; l++) m = fmaxf(m, att[tid * 8 + l]);
        e8[tid] = m;
    }
    __syncthreads();
    if (tid == 0) {
        float q4[4];
#pragma unroll
        for (int l = 0; l < 4; l++) q4[l] = fmaxf(e8[2 * l], e8[2 * l + 1]);
        float h2a = fmaxf(q4[0], q4[1]);
        float h2b = fmaxf(q4[2], q4[3]);
        float* o = out + bn * 15;
        o[0] = fmaxf(h2a, h2b);
        o[1] = h2a; o[2] = h2b;
        o[3] = q4[0]; o[4] = q4[1]; o[5] = q4[2]; o[6] = q4[3];
#pragma unroll
        for (int l = 0; l < 8; l++) o[7 + l] = e8[l];
    }
}

// ================== GCN (bank-conflict-free) ==================
#define XS 257
#define GCN_SMEM ((64 * XS + 64 * 64 + 64) * 4)
__global__ void gcn_kernel(const float* __restrict__ x, float* __restrict__ agg)
{
    extern __shared__ float gs[];
    float* shx = gs;
    float* shc = gs + 64 * XS;
    float* shn = shc + 4096;
    int b = blockIdx.x;
    int tid = threadIdx.x;
    for (int l = tid; l < 16384; l += 256) {
        int i = l >> 8, d = l & 255;
        shx[i * XS + d] = x[(size_t)b * 16384 + l];
    }
    __syncthreads();
    if (tid < 64) {
        float s = 0.f;
        for (int l = 0; l < 256; l++) { float v = shx[tid * XS + l]; s += v * v; }
        shn[tid] = sqrtf(s) + 1e-8f;
    }
    __syncthreads();
    for (int p = tid; p < 4096; p += 256) {
        int i = p >> 6, j = p & 63;
        float s = 0.f;
        for (int l = 0; l < 256; l++) s += shx[i * XS + l] * shx[j * XS + l];
        shc[p] = s / (shn[i] * shn[j]);
    }
    __syncthreads();
    for (int p = tid; p < 16384; p += 256) {
        int i = p >> 8, d = p & 255;
        float s = 2.0f * shx[i * XS + d];
        for (int j = 0; j < 64; j++) s += shc[i * 64 + j] * shx[j * XS + d];
        agg[(size_t)b * 16384 + p] = s * (1.0f / 66.0f);
    }
}

// ================== classifier + log_softmax ==================
__global__ void cls_kernel(const float* __restrict__ tago, const float* __restrict__ sFt,
                           const float* __restrict__ rFt, const float* __restrict__ W,
                           const float* __restrict__ bias, float* __restrict__ out)
{
    int bn = blockIdx.x;
    int tid = threadIdx.x;
    int c = tid >> 5, lane = tid & 31;
    __shared__ float sh[8];
    const float* w = W + c * 286;
    const float* t = tago + (size_t)bn * 256;
    float s = 0.f;
    for (int l = lane; l < 256; l += 32) s += t[l] * w[l];
    if (lane < 15) {
        s += sFt[bn * 15 + lane] * w[256 + lane];
        s += rFt[bn * 15 + lane] * w[271 + lane];
    }
#pragma unroll
    for (int off = 16; off > 0; off >>= 1)
        s += __shfl_down_sync(0xFFFFFFFF, s, off);
    if (lane == 0) sh[c] = s + bias[c];
    __syncthreads();
    if (tid < 8) {
        float m = sh[0];
#pragma unroll
        for (int l = 1; l < 8; l++) m = fmaxf(m, sh[l]);
        float se = 0.f;
#pragma unroll
        for (int l = 0; l < 8; l++) se += expf(sh[l] - m);
        out[bn * 8 + tid] = sh[tid] - m - logf(se);
    }
}

// ================== launch ==================
extern "C" void kernel_launch(void* const* d_in, const int* in_sizes, int n_in,
                              void* d_out, int out_size)
{
    const float* documents = (const float*)d_in[0];
    const float* sw_ih_f = (const float*)d_in[1];
    const float* sw_hh_f = (const float*)d_in[2];
    const float* sb_f    = (const float*)d_in[3];
    const float* sw_ih_b = (const float*)d_in[4];
    const float* sw_hh_b = (const float*)d_in[5];
    const float* sb_b    = (const float*)d_in[6];
    const float* sf_Wq = (const float*)d_in[7];
    const float* sf_bq = (const float*)d_in[8];
    const float* sf_Wk = (const float*)d_in[9];
    const float* sf_bk = (const float*)d_in[10];
    const float* rf_Wq = (const float*)d_in[11];
    const float* rf_bq = (const float*)d_in[12];
    const float* rf_Wk = (const float*)d_in[13];
    const float* rf_bk = (const float*)d_in[14];
    const float* tw_ih_f = (const float*)d_in[15];
    const float* tw_hh_f = (const float*)d_in[16];
    const float* tb_f    = (const float*)d_in[17];
    const float* tw_ih_b = (const float*)d_in[18];
    const float* tw_hh_b = (const float*)d_in[19];
    const float* tb_b    = (const float*)d_in[20];
    const float* sage_W = (const float*)d_in[21];
    const float* sage_b = (const float*)d_in[22];
    const float* cls_W  = (const float*)d_in[23];
    const float* cls_b  = (const float*)d_in[24];

    float* out = (float*)d_out;
    float* result_out = out;
    float* gcn_out = out + B_ * N_ * C_;

    float *sentpres, *qb, *kb, *sFt, *rFt, *gtag, *tago, *agg;
    uint4 *wihp, *whhp, *whhtagp;
    cudaGetSymbolAddress((void**)&wihp, wih_pk_buf);
    cudaGetSymbolAddress((void**)&whhp, whh_pk_buf);
    cudaGetSymbolAddress((void**)&whhtagp, whh_tag_pk_buf);
    cudaGetSymbolAddress((void**)&sentpres, sentpres_buf);
    cudaGetSymbolAddress((void**)&qb, q_buf);
    cudaGetSymbolAddress((void**)&kb, k_buf);
    cudaGetSymbolAddress((void**)&sFt, sentFt_buf);
    cudaGetSymbolAddress((void**)&rFt, roleFt_buf);
    cudaGetSymbolAddress((void**)&gtag, g_tag_buf);
    cudaGetSymbolAddress((void**)&tago, tag_out_buf);
    cudaGetSymbolAddress((void**)&agg, agg_buf);

    cudaFuncSetAttribute(lstm_sent_fused, cudaFuncAttributeMaxDynamicSharedMemorySize, FUSED_SMEM);
    cudaFuncSetAttribute(lstm_tag_fused, cudaFuncAttributeMaxDynamicSharedMemorySize, TAG2_SMEM);
    cudaFuncSetAttribute(gcn_kernel, cudaFuncAttributeMaxDynamicSharedMemorySize, GCN_SMEM);

    // prep
    pack_wih_tf32<<<(2 * 13 * 64 * 32 + 255) / 256, 256>>>(sw_ih_f, sw_ih_b, wihp);
    pack_whh_tf32<<<128, 256>>>(sw_hh_f, sw_hh_b, whhp);
    pack_whh_tf32<<<128, 256>>>(tw_hh_f, tw_hh_b, whhtagp);

    // FUSED sentence BiLSTM (index 3 — ncu capture slot)
    lstm_sent_fused<<<dim3(64, 2), 512, FUSED_SMEM>>>(documents, wihp, whhp, sb_f, sb_b, sentpres);

    // sentFt SPP (tf32 mma projections)
    mma_gemm256<<<dim3(2, 16), 256>>>(sentpres, sf_Wq, sf_bq, qb, 0, 0);
    mma_gemm256<<<dim3(2, 16), 256>>>(sentpres, sf_Wk, sf_bk, kb, 0, 0);
    spp_kernel<<<2048, 64>>>(qb, kb, sFt);

    // Tag LSTM input projections (amode=1 row permute)
    mma_gemm256<<<dim3(4, 16), 256>>>(sentpres, tw_ih_f, tb_f, gtag,             1, 0);
    mma_gemm256<<<dim3(4, 16), 256>>>(sentpres, tw_ih_b, tb_b, gtag + BN_ * G4_, 1, 0);

    // FUSED tag BiLSTM
    lstm_tag_fused<<<2, 1024, TAG2_SMEM>>>(gtag, whhtagp, tago);

    // GCN
    gcn_kernel<<<32, 256, GCN_SMEM>>>(tago, agg);
    mma_gemm256<<<dim3(2, 16), 256>>>(agg, sage_W, sage_b, gcn_out, 0, 1);

    // roleFt SPP
    mma_gemm256<<<dim3(2, 16), 256>>>(tago, rf_Wq, rf_bq, qb, 0, 0);
    mma_gemm256<<<dim3(2, 16), 256>>>(tago, rf_Wk, rf_bk, kb, 0, 0);
    spp_kernel<<<2048, 64>>>(qb, kb, rFt);

    cls_kernel<<<2048, 256>>>(tago, sFt, rFt, cls_W, cls_b, result_out);

    (void)in_sizes; (void)n_in; (void)out_size;
}

// round 14
// speedup vs baseline: 1.6136x; 1.2233x over previous
#include <cuda_runtime.h>
#include <cuda_bf16.h>
#include <stdint.h>
#include <math.h>

// ---------------- problem constants ----------------
#define B_    32
#define N_    64
#define T_    50
#define WD_   200
#define H_    128
#define G4_   512
#define D2_   256
#define BN_   2048
#define C_    8

// ---------------- scratch ----------------
__device__ uint4 wih_pk_buf[2 * 13 * 64 * 32];
__device__ uint4 whh_pk_buf[2 * 8 * 64 * 32];
__device__ uint4 whh_tag_pk_buf[2 * 8 * 64 * 32];
__device__ float sentpres_buf[BN_ * D2_];
__device__ float q_buf[BN_ * D2_];
__device__ float k_buf[BN_ * D2_];
__device__ float sentFt_buf[BN_ * 15];
__device__ float roleFt_buf[BN_ * 15];
__device__ float g_tag_buf[2 * BN_ * G4_];
__device__ float tag_out_buf[BN_ * D2_];
__device__ float agg_buf[BN_ * D2_];

__device__ __forceinline__ float sigf(float x) { return __fdividef(1.0f, 1.0f + __expf(-x)); }

#define MMA_TF32(d, a, b) \
    asm volatile("mma.sync.aligned.m16n8k8.row.col.f32.tf32.tf32.f32 " \
                 "{%0,%1,%2,%3},{%4,%5,%6,%7},{%8,%9},{%0,%1,%2,%3};\n" \
                 : "+f"(d[0]), "+f"(d[1]), "+f"(d[2]), "+f"(d[3]) \
                 : "r"(a[0]), "r"(a[1]), "r"(a[2]), "r"(a[3]), "r"(b[0]), "r"(b[1]))

__device__ __forceinline__ void ldsm_x4_a(unsigned af[4], unsigned addr)
{
    asm volatile("ldmatrix.sync.aligned.m8n8.x4.shared.b16 {%0,%1,%2,%3}, [%4];"
                 : "=r"(af[0]), "=r"(af[1]), "=r"(af[2]), "=r"(af[3]) : "r"(addr));
}

// ================== pack W_ih (512x200) into tf32 B-fragments ==================
__global__ void pack_wih_tf32(const float* __restrict__ wf, const float* __restrict__ wb,
                              uint4* __restrict__ out)
{
    int i = blockIdx.x * 256 + threadIdx.x;
    if (i >= 2 * 13 * 64 * 32) return;
    const int per = 13 * 64 * 32;
    int dir = i / per, rem = i % per;
    int kt = rem >> 11, ng = (rem >> 5) & 63, lane = rem & 31;
    const float* w = dir ? wb : wf;
    int n = ng * 8 + (lane >> 2);
    int k = kt * 16 + (lane & 3);
    uint4 v;
    v.x = (k      < WD_) ? __float_as_uint(w[n * WD_ + k])      : 0u;
    v.y = (k + 4  < WD_) ? __float_as_uint(w[n * WD_ + k + 4])  : 0u;
    v.z = (k + 8  < WD_) ? __float_as_uint(w[n * WD_ + k + 8])  : 0u;
    v.w = (k + 12 < WD_) ? __float_as_uint(w[n * WD_ + k + 12]) : 0u;
    out[i] = v;
}

// ================== pack a 512x128 W_hh into tf32 B-fragments ==================
__global__ void pack_whh_tf32(const float* __restrict__ wf, const float* __restrict__ wb,
                              uint4* __restrict__ out)
{
    int i = blockIdx.x * 256 + threadIdx.x;
    if (i >= 2 * 8 * 64 * 32) return;
    int lane = i & 31, ng = (i >> 5) & 63, kt = (i >> 11) & 7, dir = i >> 14;
    const float* w = dir ? wb : wf;
    int n = ng * 8 + (lane >> 2);
    int k = kt * 16 + (lane & 3);
    uint4 v;
    v.x = __float_as_uint(w[n * 128 + k]);
    v.y = __float_as_uint(w[n * 128 + k + 4]);
    v.z = __float_as_uint(w[n * 128 + k + 8]);
    v.w = __float_as_uint(w[n * 128 + k + 12]);
    out[i] = v;
}

// ================== FUSED sentence BiLSTM (unchanged from R12) ==================
#define SD_STR 212
#define SH_STR 132
#define OFF_SD0   0
#define OFF_SD1   6784
#define OFF_H0    13568
#define OFF_H1    17792
#define OFF_BIAS  22016
#define FUSED_SMEM ((22016 + 512) * 4)
#define SD_BUFB   27136
#define SH_BUFB   16896

__global__ __launch_bounds__(512, 1)
void lstm_sent_fused(const float* __restrict__ doc,
                     const uint4* __restrict__ wih, const uint4* __restrict__ whh,
                     const float* __restrict__ biasf, const float* __restrict__ biasb,
                     float* __restrict__ sentpres)
{
    extern __shared__ __align__(16) float smf[];
    float* sbias = smf + OFF_BIAS;

    int dir = blockIdx.y;
    int r0 = blockIdx.x << 5;
    const float* bias = dir ? biasb : biasf;

    int tid = threadIdx.x, lane = tid & 31, w = tid >> 5;
    int gid = lane >> 2, qk = (lane & 3) << 1;

    const uint4* wp_ih = wih + dir * 13 * 64 * 32 + w * 32 + lane;
    const uint4* wp_hh = whh + dir * 8 * 64 * 32 + w * 32 + lane;

    unsigned smbase = (unsigned)__cvta_generic_to_shared(smf);
    int tile = lane >> 3, rin = lane & 7;
    int r_off = ((tile & 1) << 3) + rin;
    int c_off = (tile >> 1) << 2;
    unsigned sd_addr[2], sh_addr[2];
#pragma unroll
    for (int mt = 0; mt < 2; mt++) {
        sd_addr[mt] = smbase + ((unsigned)(OFF_SD0 + (mt * 16 + r_off) * SD_STR + c_off) << 2);
        sh_addr[mt] = smbase + ((unsigned)(OFF_H0 + (mt * 16 + r_off) * SH_STR + c_off) << 2);
    }

    float c_reg[8], hs_reg[8];
#pragma unroll
    for (int i = 0; i < 8; i++) { c_reg[i] = 0.f; hs_reg[i] = 0.f; }
    for (int i = tid; i < 2 * 32 * SH_STR; i += 512) smf[OFF_H0 + i] = 0.f;
    if (tid < 512) sbias[tid] = bias[tid];

    {
        int t0 = dir ? (T_ - 1) : 0;
        for (int idx = tid; idx < 32 * 52; idx += 512) {
            int rr = idx / 52, c4 = idx - rr * 52;
            int k = c4 << 2;
            float4 v = (k < WD_)
                ? *(const float4*)(doc + ((size_t)(r0 + rr) * T_ + t0) * WD_ + k)
                : make_float4(0.f, 0.f, 0.f, 0.f);
            *(float4*)&smf[OFF_SD0 + rr * SD_STR + k] = v;
        }
    }
    __syncthreads();

    for (int s = 0; s < T_; s++) {
        int p = s & 1;
        unsigned po = p ? SD_BUFB : 0u;
        unsigned ph = p ? SH_BUFB : 0u;

        float acc[2][4][4];
#pragma unroll
        for (int mt = 0; mt < 2; mt++)
#pragma unroll
            for (int g = 0; g < 4; g++) {
                int col = (g << 7) + (w << 3) + qk;
                float b0 = sbias[col], b1 = sbias[col + 1];
                acc[mt][g][0] = b0; acc[mt][g][1] = b1;
                acc[mt][g][2] = b0; acc[mt][g][3] = b1;
            }

        uint4 wv0[4], wv1[4], wv2[4];

#define LOADW(dst, ktv) do { \
            int _kt = (ktv); \
            if (_kt < 21) { \
                const uint4* _p = (_kt < 13) ? (wp_ih + _kt * 2048) \
                                             : (wp_hh + (_kt - 13) * 2048); \
                dst[0] = _p[0];    dst[1] = _p[512]; \
                dst[2] = _p[1024]; dst[3] = _p[1536]; \
            } \
        } while (0)

#define COMPUTE(ktv, wv) do { \
            int _kt = (ktv); \
            _Pragma("unroll") \
            for (int mt = 0; mt < 2; mt++) { \
                unsigned _a0 = (_kt < 13) ? (sd_addr[mt] + po + ((unsigned)_kt << 6)) \
                                          : (sh_addr[mt] + ph + ((unsigned)(_kt - 13) << 6)); \
                unsigned _af0[4], _af1[4]; \
                ldsm_x4_a(_af0, _a0); \
                ldsm_x4_a(_af1, _a0 + 32); \
                _Pragma("unroll") \
                for (int g = 0; g < 4; g++) { \
                    unsigned _b0[2] = { wv[g].x, wv[g].y }; \
                    unsigned _b1[2] = { wv[g].z, wv[g].w }; \
                    MMA_TF32(acc[mt][g], _af0, _b0); \
                    MMA_TF32(acc[mt][g], _af1, _b1); \
                } \
            } \
        } while (0)

        LOADW(wv0, 0);
        LOADW(wv1, 1);
#pragma unroll 1
        for (int k3 = 0; k3 < 21; k3 += 3) {
            LOADW(wv2, k3 + 2);
            COMPUTE(k3, wv0);
            LOADW(wv0, k3 + 3);
            COMPUTE(k3 + 1, wv1);
            LOADW(wv1, k3 + 4);
            COMPUTE(k3 + 2, wv2);
        }
#undef LOADW
#undef COMPUTE

        if (s + 1 < T_) {
            int tn = dir ? (T_ - 2 - s) : (s + 1);
            float* sdn = smf + (p ? OFF_SD0 : OFF_SD1);
            for (int idx = tid; idx < 32 * 52; idx += 512) {
                int rr = idx / 52, c4 = idx - rr * 52;
                int k = c4 << 2;
                float4 v = (k < WD_)
                    ? *(const float4*)(doc + ((size_t)(r0 + rr) * T_ + tn) * WD_ + k)
                    : make_float4(0.f, 0.f, 0.f, 0.f);
                *(float4*)&sdn[rr * SD_STR + k] = v;
            }
        }

        float* hw = smf + (p ? OFF_H0 : OFF_H1);
#pragma unroll
        for (int mt = 0; mt < 2; mt++)
#pragma unroll
            for (int e = 0; e < 4; e++) {
                int row = mt * 16 + gid + ((e >> 1) << 3);
                int col = (w << 3) + qk + (e & 1);
                int ix = mt * 4 + e;
                float iv = acc[mt][0][e];
                float fv = acc[mt][1][e];
                float gv = acc[mt][2][e];
                float ov = acc[mt][3][e];
                float cv = sigf(fv) * c_reg[ix] + sigf(iv) * tanhf(gv);
                c_reg[ix] = cv;
                float h = sigf(ov) * tanhf(cv);
                hs_reg[ix] += h;
                hw[row * SH_STR + col] = h;
            }
        __syncthreads();
    }

#pragma unroll
    for (int mt = 0; mt < 2; mt++)
#pragma unroll
        for (int e = 0; e < 4; e++) {
            int row = mt * 16 + gid + ((e >> 1) << 3);
            int col = (w << 3) + qk + (e & 1);
            sentpres[(size_t)(r0 + row) * 256 + dir * 128 + col] =
                tanhf(hs_reg[mt * 4 + e] * (1.0f / T_));
        }
}

// ================== device GEMM body, K=256, 512 threads (first 8 warps do mma) ==================
__device__ void gemm256_body(const float* __restrict__ A, const float* __restrict__ W,
                             const float* __restrict__ bias, float* __restrict__ Cc,
                             int amode, int relu, int bx, int by, int Gcols, float* smf)
{
    float* sA = smf;
    float* sB = smf + 2560;
    float* sC = smf;

    int tid = threadIdx.x;
    int lane = tid & 31, wid = tid >> 5;
    int wm = wid & 3, wn = (wid >> 2) & 1;
    int mb = by << 7, nb = bx << 7;
    int lrow = tid >> 2, lq = tid & 3;
    int r = lane >> 2, tc = lane & 3, c2 = tc << 1;

    int am = mb + lrow;
    long arow = amode ? ((long)(((am & 31) << 6) + (am >> 5)) << 8) : ((long)am << 8);
    const float* ap = A + arow + lq * 4;
    const float* bp = W + ((size_t)(nb + lrow) << 8) + lq * 4;

    float acc[2][8][4];
#pragma unroll
    for (int mi = 0; mi < 2; mi++)
#pragma unroll
        for (int ni = 0; ni < 8; ni++)
#pragma unroll
            for (int e = 0; e < 4; e++) acc[mi][ni][e] = 0.f;

#pragma unroll 1
    for (int kb = 0; kb < 256; kb += 16) {
        float4 va = *(const float4*)(ap + kb);
        float4 vb = *(const float4*)(bp + kb);
        __syncthreads();
        *(float4*)&sA[lrow * 20 + lq * 4] = va;
        *(float4*)&sB[lrow * 20 + lq * 4] = vb;
        __syncthreads();

        if (wid < 8) {
            unsigned af[2][2][4];
#pragma unroll
            for (int mi = 0; mi < 2; mi++) {
                int rb = (wm * 32 + mi * 16 + r) * 20;
#pragma unroll
                for (int kh = 0; kh < 2; kh++) {
                    af[mi][kh][0] = __float_as_uint(sA[rb + kh * 8 + tc]);
                    af[mi][kh][1] = __float_as_uint(sA[rb + 160 + kh * 8 + tc]);
                    af[mi][kh][2] = __float_as_uint(sA[rb + kh * 8 + tc + 4]);
                    af[mi][kh][3] = __float_as_uint(sA[rb + 160 + kh * 8 + tc + 4]);
                }
            }
#pragma unroll
            for (int ni = 0; ni < 8; ni++) {
                int nrb = (wn * 64 + ni * 8 + r) * 20;
#pragma unroll
                for (int kh = 0; kh < 2; kh++) {
                    unsigned bf[2];
                    bf[0] = __float_as_uint(sB[nrb + kh * 8 + tc]);
                    bf[1] = __float_as_uint(sB[nrb + kh * 8 + tc + 4]);
#pragma unroll
                    for (int mi = 0; mi < 2; mi++)
                        MMA_TF32(acc[mi][ni], af[mi][kh], bf);
                }
            }
        }
    }
    for (int wmc = 0; wmc < 4; wmc++) {
        __syncthreads();
        if (wid < 8 && wm == wmc) {
#pragma unroll
            for (int mi = 0; mi < 2; mi++)
#pragma unroll
                for (int ni = 0; ni < 8; ni++) {
                    int lr2 = mi * 16 + r;
                    int col = wn * 64 + ni * 8 + c2;
                    float b0 = bias[nb + col], b1 = bias[nb + col + 1];
                    float v0 = acc[mi][ni][0] + b0, v1 = acc[mi][ni][1] + b1;
                    float v2 = acc[mi][ni][2] + b0, v3 = acc[mi][ni][3] + b1;
                    if (relu) {
                        v0 = fmaxf(v0, 0.f); v1 = fmaxf(v1, 0.f);
                        v2 = fmaxf(v2, 0.f); v3 = fmaxf(v3, 0.f);
                    }
                    *(float2*)&sC[lr2 * 128 + col] = make_float2(v0, v1);
                    *(float2*)&sC[(lr2 + 8) * 128 + col] = make_float2(v2, v3);
                }
        }
        __syncthreads();
#pragma unroll
        for (int l = 0; l < 2; l++) {
            int idx = tid + l * 512;
            int row = idx >> 5, c4 = idx & 31;
            *(float4*)&Cc[(size_t)(mb + wmc * 32 + row) * Gcols + nb + c4 * 4] =
                ((float4*)sC)[idx];
        }
    }
}

// ================== tag recurrence role: 512 threads, register-local gates ==================
__device__ void tag_role(const float* __restrict__ Gt, const uint4* __restrict__ whhtag,
                         float* __restrict__ tag_out, int dir, float* smt)
{
    float* h0 = smt;   // [2][32][SH_STR]
    const uint4* wp0 = whhtag + dir * 8 * 64 * 32;
    const float* G0 = Gt + (size_t)dir * 2048 * 512;

    int tid = threadIdx.x, lane = tid & 31, w = tid >> 5;   // w: 0..15
    int gid = lane >> 2, qk = (lane & 3) << 1;

    float c_reg[8];
#pragma unroll
    for (int i = 0; i < 8; i++) c_reg[i] = 0.f;
    for (int i = tid; i < 2 * 32 * SH_STR; i += 512) h0[i] = 0.f;

    unsigned smbase = (unsigned)__cvta_generic_to_shared(h0);
    int tile = lane >> 3, rin = lane & 7;
    int r_off = ((tile & 1) << 3) + rin;
    int c_off = (tile >> 1) << 2;
    unsigned h_addr[2];
#pragma unroll
    for (int mt = 0; mt < 2; mt++)
        h_addr[mt] = smbase + ((unsigned)((mt * 16 + r_off) * SH_STR + c_off) << 2);
    const unsigned HBUF = 32 * SH_STR * 4;
    __syncthreads();

    for (int s = 0; s < 64; s++) {
        int n = dir ? (63 - s) : s;
        int p = s & 1;
        unsigned ph = p ? HBUF : 0u;
        const float* Gn = G0 + (size_t)(n * 32) * 512;

        // acc init from input projection (bias folded in)
        float acc[2][4][4];
#pragma unroll
        for (int mt = 0; mt < 2; mt++) {
            const float* gr = Gn + (size_t)(mt * 16 + gid) * 512;
#pragma unroll
            for (int g = 0; g < 4; g++) {
                int col = (g << 7) + (w << 3) + qk;
                float2 v0 = *(const float2*)(gr + col);
                float2 v1 = *(const float2*)(gr + 8 * 512 + col);
                acc[mt][g][0] = v0.x; acc[mt][g][1] = v0.y;
                acc[mt][g][2] = v1.x; acc[mt][g][3] = v1.y;
            }
        }

        // h @ W_hh^T over 8 k-tiles, double-buffered W frags. ng = g*16 + w.
        uint4 wv0[4], wv1[4];
        {
            const uint4* pptr = wp0 + w * 32 + lane;   // kt=0
#pragma unroll
            for (int g = 0; g < 4; g++) wv0[g] = pptr[(g << 4) * 32];
        }
#pragma unroll 1
        for (int kt = 0; kt < 8; kt += 2) {
            {
                const uint4* pptr = wp0 + ((kt + 1) * 64 + w) * 32 + lane;
#pragma unroll
                for (int g = 0; g < 4; g++) wv1[g] = pptr[(g << 4) * 32];
            }
            {
                unsigned af0[2][4], af1[2][4];
#pragma unroll
                for (int mt = 0; mt < 2; mt++) {
                    unsigned a0 = h_addr[mt] + ph + ((unsigned)kt << 6);
                    ldsm_x4_a(af0[mt], a0);
                    ldsm_x4_a(af1[mt], a0 + 32);
                }
#pragma unroll
                for (int g = 0; g < 4; g++) {
                    unsigned b0[2] = { wv0[g].x, wv0[g].y };
                    unsigned b1[2] = { wv0[g].z, wv0[g].w };
#pragma unroll
                    for (int mt = 0; mt < 2; mt++) {
                        MMA_TF32(acc[mt][g], af0[mt], b0);
                        MMA_TF32(acc[mt][g], af1[mt], b1);
                    }
                }
            }
            if (kt + 2 < 8) {
                const uint4* pptr = wp0 + ((kt + 2) * 64 + w) * 32 + lane;
#pragma unroll
                for (int g = 0; g < 4; g++) wv0[g] = pptr[(g << 4) * 32];
            }
            {
                unsigned af0[2][4], af1[2][4];
#pragma unroll
                for (int mt = 0; mt < 2; mt++) {
                    unsigned a0 = h_addr[mt] + ph + ((unsigned)(kt + 1) << 6);
                    ldsm_x4_a(af0[mt], a0);
                    ldsm_x4_a(af1[mt], a0 + 32);
                }
#pragma unroll
                for (int g = 0; g < 4; g++) {
                    unsigned b0[2] = { wv1[g].x, wv1[g].y };
                    unsigned b1[2] = { wv1[g].z, wv1[g].w };
#pragma unroll
                    for (int mt = 0; mt < 2; mt++) {
                        MMA_TF32(acc[mt][g], af0[mt], b0);
                        MMA_TF32(acc[mt][g], af1[mt], b1);
                    }
                }
            }
        }

        // register-local cell update -> write h into the OTHER buffer
        float* hw = h0 + (p ? 0 : 32 * SH_STR);
#pragma unroll
        for (int mt = 0; mt < 2; mt++)
#pragma unroll
            for (int e = 0; e < 4; e++) {
                int row = mt * 16 + gid + ((e >> 1) << 3);
                int col = (w << 3) + qk + (e & 1);
                int ix = mt * 4 + e;
                float iv = acc[mt][0][e];
                float fv = acc[mt][1][e];
                float gv = acc[mt][2][e];
                float ov = acc[mt][3][e];
                float cv = sigf(fv) * c_reg[ix] + sigf(iv) * tanhf(gv);
                c_reg[ix] = cv;
                float h = sigf(ov) * tanhf(cv);
                hw[row * SH_STR + col] = h;
                tag_out[(size_t)(row * 64 + n) * 256 + dir * 128 + col] = tanhf(h);
            }
        __syncthreads();
    }
}

// ================== combined launch: tag recurrence + sentFt Q/K projections ==================
#define COMB_SMEM (2 * 32 * SH_STR * 4)
__global__ __launch_bounds__(512, 1)
void tag_sentft_combined(const float* __restrict__ Gt, const uint4* __restrict__ whhtag,
                         float* __restrict__ tag_out, const float* __restrict__ sentpres,
                         const float* __restrict__ Wq, const float* __restrict__ bq,
                         float* __restrict__ qout,
                         const float* __restrict__ Wk, const float* __restrict__ bk,
                         float* __restrict__ kout)
{
    extern __shared__ __align__(16) float smc[];
    int blk = blockIdx.x;
    if (blk < 2) {
        tag_role(Gt, whhtag, tag_out, blk, smc);
    } else if (blk < 34) {
        int id = blk - 2;
        gemm256_body(sentpres, Wq, bq, qout, 0, 0, id & 1, id >> 1, 256, smc);
    } else {
        int id = blk - 34;
        gemm256_body(sentpres, Wk, bk, kout, 0, 0, id & 1, id >> 1, 256, smc);
    }
}

// ================== standalone tf32 GEMM K=256 (256 threads) ==================
__global__ __launch_bounds__(256, 2)
void mma_gemm256(const float* __restrict__ A, const float* __restrict__ W,
                 const float* __restrict__ bias, float* __restrict__ C,
                 int amode, int relu)
{
    __shared__ __align__(16) float smf[5120];
    float* sA = smf;
    float* sB = smf + 2560;
    float* sC = smf;

    int tid = threadIdx.x;
    int lane = tid & 31, wid = tid >> 5;
    int wm = wid & 3, wn = wid >> 2;
    int mb = blockIdx.y << 7, nb = blockIdx.x << 7;
    int lrow = tid >> 1, lhalf = tid & 1;
    int r = lane >> 2, tc = lane & 3, c2 = tc << 1;

    int am = mb + lrow;
    long arow = amode ? ((long)(((am & 31) << 6) + (am >> 5)) << 8) : ((long)am << 8);
    const float* ap = A + arow + lhalf * 8;
    const float* bp = W + ((size_t)(nb + lrow) << 8) + lhalf * 8;

    float acc[2][8][4];
#pragma unroll
    for (int mi = 0; mi < 2; mi++)
#pragma unroll
        for (int ni = 0; ni < 8; ni++)
#pragma unroll
            for (int e = 0; e < 4; e++) acc[mi][ni][e] = 0.f;

#pragma unroll 1
    for (int kb = 0; kb < 256; kb += 16) {
        float4 va0 = *(const float4*)(ap + kb);
        float4 va1 = *(const float4*)(ap + kb + 4);
        float4 vb0 = *(const float4*)(bp + kb);
        float4 vb1 = *(const float4*)(bp + kb + 4);
        __syncthreads();
        *(float4*)&sA[lrow * 20 + lhalf * 8]     = va0;
        *(float4*)&sA[lrow * 20 + lhalf * 8 + 4] = va1;
        *(float4*)&sB[lrow * 20 + lhalf * 8]     = vb0;
        *(float4*)&sB[lrow * 20 + lhalf * 8 + 4] = vb1;
        __syncthreads();

        unsigned af[2][2][4];
#pragma unroll
        for (int mi = 0; mi < 2; mi++) {
            int rb = (wm * 32 + mi * 16 + r) * 20;
#pragma unroll
            for (int kh = 0; kh < 2; kh++) {
                af[mi][kh][0] = __float_as_uint(sA[rb + kh * 8 + tc]);
                af[mi][kh][1] = __float_as_uint(sA[rb + 160 + kh * 8 + tc]);
                af[mi][kh][2] = __float_as_uint(sA[rb + kh * 8 + tc + 4]);
                af[mi][kh][3] = __float_as_uint(sA[rb + 160 + kh * 8 + tc + 4]);
            }
        }
#pragma unroll
        for (int ni = 0; ni < 8; ni++) {
            int nrb = (wn * 64 + ni * 8 + r) * 20;
#pragma unroll
            for (int kh = 0; kh < 2; kh++) {
                unsigned bf[2];
                bf[0] = __float_as_uint(sB[nrb + kh * 8 + tc]);
                bf[1] = __float_as_uint(sB[nrb + kh * 8 + tc + 4]);
#pragma unroll
                for (int mi = 0; mi < 2; mi++)
                    MMA_TF32(acc[mi][ni], af[mi][kh], bf);
            }
        }
    }
    int G = gridDim.x << 7;
    for (int wmc = 0; wmc < 4; wmc++) {
        __syncthreads();
        if (wm == wmc) {
#pragma unroll
            for (int mi = 0; mi < 2; mi++)
#pragma unroll
                for (int ni = 0; ni < 8; ni++) {
                    int lr2 = mi * 16 + r;
                    int col = wn * 64 + ni * 8 + c2;
                    float b0 = bias[nb + col], b1 = bias[nb + col + 1];
                    float v0 = acc[mi][ni][0] + b0, v1 = acc[mi][ni][1] + b1;
                    float v2 = acc[mi][ni][2] + b0, v3 = acc[mi][ni][3] + b1;
                    if (relu) {
                        v0 = fmaxf(v0, 0.f); v1 = fmaxf(v1, 0.f);
                        v2 = fmaxf(v2, 0.f); v3 = fmaxf(v3, 0.f);
                    }
                    *(float2*)&sC[lr2 * 128 + col] = make_float2(v0, v1);
                    *(float2*)&sC[(lr2 + 8) * 128 + col] = make_float2(v2, v3);
                }
        }
        __syncthreads();
#pragma unroll
        for (int l = 0; l < 4; l++) {
            int idx = tid + l * 256;
            int row = idx >> 5, c4 = idx & 31;
            *(float4*)&C[(size_t)(mb + wmc * 32 + row) * G + nb + c4 * 4] =
                ((float4*)sC)[idx];
        }
    }
}

// ================== SPP ==================
__global__ void spp_kernel(const float* __restrict__ q, const float* __restrict__ k,
                           float* __restrict__ out)
{
    int bn = blockIdx.x;
    int b = bn >> 6;
    __shared__ float shq[256];
    __shared__ float att[64];
    __shared__ float e8[8];
    int tid = threadIdx.x;
    for (int l = tid; l < 256; l += 64) shq[l] = q[(size_t)bn * 256 + l];
    __syncthreads();
    const float* kr = k + (size_t)(b * 64 + tid) * 256;
    float s = 0.f;
    for (int l = 0; l < 256; l += 4) {
        float4 qa = *(float4*)&shq[l];
        float4 ka = *(const float4*)&kr[l];
        s += qa.x * ka.x + qa.y * ka.y + qa.z * ka.z + qa.w * ka.w;
    }
    att[tid] = s * 0.0625f;
    __syncthreads();
    if (tid < 8) {
        float m = att[tid * 8];
#pragma unroll
        for (int l = 1; l < 8; l++) m = fmaxf(m, att[tid * 8 + l]);
        e8[tid] = m;
    }
    __syncthreads();
    if (tid == 0) {
        float q4[4];
#pragma unroll
        for (int l = 0; l < 4; l++) q4[l] = fmaxf(e8[2 * l], e8[2 * l + 1]);
        float h2a = fmaxf(q4[0], q4[1]);
        float h2b = fmaxf(q4[2], q4[3]);
        float* o = out + bn * 15;
        o[0] = fmaxf(h2a, h2b);
        o[1] = h2a; o[2] = h2b;
        o[3] = q4[0]; o[4] = q4[1]; o[5] = q4[2]; o[6] = q4[3];
#pragma unroll
        for (int l = 0; l < 8; l++) o[7 + l] = e8[l];
    }
}

// ================== GCN (bank-conflict-free) ==================
#define XS 257
#define GCN_SMEM ((64 * XS + 64 * 64 + 64) * 4)
__global__ void gcn_kernel(const float* __restrict__ x, float* __restrict__ agg)
{
    extern __shared__ float gs[];
    float* shx = gs;
    float* shc = gs + 64 * XS;
    float* shn = shc + 4096;
    int b = blockIdx.x;
    int tid = threadIdx.x;
    for (int l = tid; l < 16384; l += 256) {
        int i = l >> 8, d = l & 255;
        shx[i * XS + d] = x[(size_t)b * 16384 + l];
    }
    __syncthreads();
    if (tid < 64) {
        float s = 0.f;
        for (int l = 0; l < 256; l++) { float v = shx[tid * XS + l]; s += v * v; }
        shn[tid] = sqrtf(s) + 1e-8f;
    }
    __syncthreads();
    for (int p = tid; p < 4096; p += 256) {
        int i = p >> 6, j = p & 63;
        float s = 0.f;
        for (int l = 0; l < 256; l++) s += shx[i * XS + l] * shx[j * XS + l];
        shc[p] = s / (shn[i] * shn[j]);
    }
    __syncthreads();
    for (int p = tid; p < 16384; p += 256) {
        int i = p >> 8, d = p & 255;
        float s = 2.0f * shx[i * XS + d];
        for (int j = 0; j < 64; j++) s += shc[i * 64 + j] * shx[j * XS + d];
        agg[(size_t)b * 16384 + p] = s * (1.0f / 66.0f);
    }
}

// ================== classifier + log_softmax ==================
__global__ void cls_kernel(const float* __restrict__ tago, const float* __restrict__ sFt,
                           const float* __restrict__ rFt, const float* __restrict__ W,
                           const float* __restrict__ bias, float* __restrict__ out)
{
    int bn = blockIdx.x;
    int tid = threadIdx.x;
    int c = tid >> 5, lane = tid & 31;
    __shared__ float sh[8];
    const float* w = W + c * 286;
    const float* t = tago + (size_t)bn * 256;
    float s = 0.f;
    for (int l = lane; l < 256; l += 32) s += t[l] * w[l];
    if (lane < 15) {
        s += sFt[bn * 15 + lane] * w[256 + lane];
        s += rFt[bn * 15 + lane] * w[271 + lane];
    }
#pragma unroll
    for (int off = 16; off > 0; off >>= 1)
        s += __shfl_down_sync(0xFFFFFFFF, s, off);
    if (lane == 0) sh[c] = s + bias[c];
    __syncthreads();
    if (tid < 8) {
        float m = sh[0];
#pragma unroll
        for (int l = 1; l < 8; l++) m = fmaxf(m, sh[l]);
        float se = 0.f;
#pragma unroll
        for (int l = 0; l < 8; l++) se += expf(sh[l] - m);
        out[bn * 8 + tid] = sh[tid] - m - logf(se);
    }
}

// ================== launch ==================
extern "C" void kernel_launch(void* const* d_in, const int* in_sizes, int n_in,
                              void* d_out, int out_size)
{
    const float* documents = (const float*)d_in[0];
    const float* sw_ih_f = (const float*)d_in[1];
    const float* sw_hh_f = (const float*)d_in[2];
    const float* sb_f    = (const float*)d_in[3];
    const float* sw_ih_b = (const float*)d_in[4];
    const float* sw_hh_b = (const float*)d_in[5];
    const float* sb_b    = (const float*)d_in[6];
    const float* sf_Wq = (const float*)d_in[7];
    const float* sf_bq = (const float*)d_in[8];
    const float* sf_Wk = (const float*)d_in[9];
    const float* sf_bk = (const float*)d_in[10];
    const float* rf_Wq = (const float*)d_in[11];
    const float* rf_bq = (const float*)d_in[12];
    const float* rf_Wk = (const float*)d_in[13];
    const float* rf_bk = (const float*)d_in[14];
    const float* tw_ih_f = (const float*)d_in[15];
    const float* tw_hh_f = (const float*)d_in[16];
    const float* tb_f    = (const float*)d_in[17];
    const float* tw_ih_b = (const float*)d_in[18];
    const float* tw_hh_b = (const float*)d_in[19];
    const float* tb_b    = (const float*)d_in[20];
    const float* sage_W = (const float*)d_in[21];
    const float* sage_b = (const float*)d_in[22];
    const float* cls_W  = (const float*)d_in[23];
    const float* cls_b  = (const float*)d_in[24];

    float* out = (float*)d_out;
    float* result_out = out;
    float* gcn_out = out + B_ * N_ * C_;

    float *sentpres, *qb, *kb, *sFt, *rFt, *gtag, *tago, *agg;
    uint4 *wihp, *whhp, *whhtagp;
    cudaGetSymbolAddress((void**)&wihp, wih_pk_buf);
    cudaGetSymbolAddress((void**)&whhp, whh_pk_buf);
    cudaGetSymbolAddress((void**)&whhtagp, whh_tag_pk_buf);
    cudaGetSymbolAddress((void**)&sentpres, sentpres_buf);
    cudaGetSymbolAddress((void**)&qb, q_buf);
    cudaGetSymbolAddress((void**)&kb, k_buf);
    cudaGetSymbolAddress((void**)&sFt, sentFt_buf);
    cudaGetSymbolAddress((void**)&rFt, roleFt_buf);
    cudaGetSymbolAddress((void**)&gtag, g_tag_buf);
    cudaGetSymbolAddress((void**)&tago, tag_out_buf);
    cudaGetSymbolAddress((void**)&agg, agg_buf);

    cudaFuncSetAttribute(lstm_sent_fused, cudaFuncAttributeMaxDynamicSharedMemorySize, FUSED_SMEM);
    cudaFuncSetAttribute(tag_sentft_combined, cudaFuncAttributeMaxDynamicSharedMemorySize, COMB_SMEM);
    cudaFuncSetAttribute(gcn_kernel, cudaFuncAttributeMaxDynamicSharedMemorySize, GCN_SMEM);

    // prep
    pack_wih_tf32<<<(2 * 13 * 64 * 32 + 255) / 256, 256>>>(sw_ih_f, sw_ih_b, wihp);
    pack_whh_tf32<<<128, 256>>>(sw_hh_f, sw_hh_b, whhp);
    pack_whh_tf32<<<128, 256>>>(tw_hh_f, tw_hh_b, whhtagp);

    // FUSED sentence BiLSTM
    lstm_sent_fused<<<dim3(64, 2), 512, FUSED_SMEM>>>(documents, wihp, whhp, sb_f, sb_b, sentpres);

    // Tag LSTM input projections
    mma_gemm256<<<dim3(4, 16), 256>>>(sentpres, tw_ih_f, tb_f, gtag,             1, 0);
    mma_gemm256<<<dim3(4, 16), 256>>>(sentpres, tw_ih_b, tb_b, gtag + BN_ * G4_, 1, 0);

    // COMBINED: tag recurrence (blocks 0-1) + sentFt Q/K projections (blocks 2-65)
    tag_sentft_combined<<<66, 512, COMB_SMEM>>>(gtag, whhtagp, tago, sentpres,
                                                sf_Wq, sf_bq, qb, sf_Wk, sf_bk, kb);

    // sentFt SPP (Q/K produced inside combined launch)
    spp_kernel<<<2048, 64>>>(qb, kb, sFt);

    // GCN
    gcn_kernel<<<32, 256, GCN_SMEM>>>(tago, agg);
    mma_gemm256<<<dim3(2, 16), 256>>>(agg, sage_W, sage_b, gcn_out, 0, 1);

    // roleFt SPP
    mma_gemm256<<<dim3(2, 16), 256>>>(tago, rf_Wq, rf_bq, qb, 0, 0);
    mma_gemm256<<<dim3(2, 16), 256>>>(tago, rf_Wk, rf_bk, kb, 0, 0);
    spp_kernel<<<2048, 64>>>(qb, kb, rFt);

    cls_kernel<<<2048, 256>>>(tago, sFt, rFt, cls_W, cls_b, result_out);

    (void)in_sizes; (void)n_in; (void)out_size;
}

// round 15
// speedup vs baseline: 1.7634x; 1.0928x over previous
#include <cuda_runtime.h>
#include <cuda_bf16.h>
#include <stdint.h>
#include <math.h>

// ---------------- problem constants ----------------
#define B_    32
#define N_    64
#define T_    50
#define WD_   200
#define H_    128
#define G4_   512
#define D2_   256
#define BN_   2048
#define C_    8

// ---------------- scratch ----------------
__device__ uint4 wih_pk_buf[2 * 13 * 64 * 32];
__device__ uint4 whh_pk_buf[2 * 8 * 64 * 32];
__device__ uint4 whh_tag_pk_buf[2 * 8 * 64 * 32];
__device__ float sentpres_buf[BN_ * D2_];
__device__ float q_buf[BN_ * D2_];
__device__ float k_buf[BN_ * D2_];
__device__ float q2_buf[BN_ * D2_];
__device__ float k2_buf[BN_ * D2_];
__device__ float sentFt_buf[BN_ * 15];
__device__ float roleFt_buf[BN_ * 15];
__device__ float g_tag_buf[2 * BN_ * G4_];
__device__ float tag_out_buf[BN_ * D2_];
__device__ float agg_buf[BN_ * D2_];

__device__ __forceinline__ float sigf(float x) { return __fdividef(1.0f, 1.0f + __expf(-x)); }

#define MMA_TF32(d, a, b) \
    asm volatile("mma.sync.aligned.m16n8k8.row.col.f32.tf32.tf32.f32 " \
                 "{%0,%1,%2,%3},{%4,%5,%6,%7},{%8,%9},{%0,%1,%2,%3};\n" \
                 : "+f"(d[0]), "+f"(d[1]), "+f"(d[2]), "+f"(d[3]) \
                 : "r"(a[0]), "r"(a[1]), "r"(a[2]), "r"(a[3]), "r"(b[0]), "r"(b[1]))

__device__ __forceinline__ void ldsm_x4_a(unsigned af[4], unsigned addr)
{
    asm volatile("ldmatrix.sync.aligned.m8n8.x4.shared.b16 {%0,%1,%2,%3}, [%4];"
                 : "=r"(af[0]), "=r"(af[1]), "=r"(af[2]), "=r"(af[3]) : "r"(addr));
}

// ================== pack W_ih (512x200) into tf32 B-fragments ==================
__global__ void pack_wih_tf32(const float* __restrict__ wf, const float* __restrict__ wb,
                              uint4* __restrict__ out)
{
    int i = blockIdx.x * 256 + threadIdx.x;
    if (i >= 2 * 13 * 64 * 32) return;
    const int per = 13 * 64 * 32;
    int dir = i / per, rem = i % per;
    int kt = rem >> 11, ng = (rem >> 5) & 63, lane = rem & 31;
    const float* w = dir ? wb : wf;
    int n = ng * 8 + (lane >> 2);
    int k = kt * 16 + (lane & 3);
    uint4 v;
    v.x = (k      < WD_) ? __float_as_uint(w[n * WD_ + k])      : 0u;
    v.y = (k + 4  < WD_) ? __float_as_uint(w[n * WD_ + k + 4])  : 0u;
    v.z = (k + 8  < WD_) ? __float_as_uint(w[n * WD_ + k + 8])  : 0u;
    v.w = (k + 12 < WD_) ? __float_as_uint(w[n * WD_ + k + 12]) : 0u;
    out[i] = v;
}

// ================== pack a 512x128 W_hh into tf32 B-fragments ==================
__global__ void pack_whh_tf32(const float* __restrict__ wf, const float* __restrict__ wb,
                              uint4* __restrict__ out)
{
    int i = blockIdx.x * 256 + threadIdx.x;
    if (i >= 2 * 8 * 64 * 32) return;
    int lane = i & 31, ng = (i >> 5) & 63, kt = (i >> 11) & 7, dir = i >> 14;
    const float* w = dir ? wb : wf;
    int n = ng * 8 + (lane >> 2);
    int k = kt * 16 + (lane & 3);
    uint4 v;
    v.x = __float_as_uint(w[n * 128 + k]);
    v.y = __float_as_uint(w[n * 128 + k + 4]);
    v.z = __float_as_uint(w[n * 128 + k + 8]);
    v.w = __float_as_uint(w[n * 128 + k + 12]);
    out[i] = v;
}

// ================== FUSED sentence BiLSTM (unchanged) ==================
#define SD_STR 212
#define SH_STR 132
#define OFF_SD0   0
#define OFF_SD1   6784
#define OFF_H0    13568
#define OFF_H1    17792
#define OFF_BIAS  22016
#define FUSED_SMEM ((22016 + 512) * 4)
#define SD_BUFB   27136
#define SH_BUFB   16896

__global__ __launch_bounds__(512, 1)
void lstm_sent_fused(const float* __restrict__ doc,
                     const uint4* __restrict__ wih, const uint4* __restrict__ whh,
                     const float* __restrict__ biasf, const float* __restrict__ biasb,
                     float* __restrict__ sentpres)
{
    extern __shared__ __align__(16) float smf[];
    float* sbias = smf + OFF_BIAS;

    int dir = blockIdx.y;
    int r0 = blockIdx.x << 5;
    const float* bias = dir ? biasb : biasf;

    int tid = threadIdx.x, lane = tid & 31, w = tid >> 5;
    int gid = lane >> 2, qk = (lane & 3) << 1;

    const uint4* wp_ih = wih + dir * 13 * 64 * 32 + w * 32 + lane;
    const uint4* wp_hh = whh + dir * 8 * 64 * 32 + w * 32 + lane;

    unsigned smbase = (unsigned)__cvta_generic_to_shared(smf);
    int tile = lane >> 3, rin = lane & 7;
    int r_off = ((tile & 1) << 3) + rin;
    int c_off = (tile >> 1) << 2;
    unsigned sd_addr[2], sh_addr[2];
#pragma unroll
    for (int mt = 0; mt < 2; mt++) {
        sd_addr[mt] = smbase + ((unsigned)(OFF_SD0 + (mt * 16 + r_off) * SD_STR + c_off) << 2);
        sh_addr[mt] = smbase + ((unsigned)(OFF_H0 + (mt * 16 + r_off) * SH_STR + c_off) << 2);
    }

    float c_reg[8], hs_reg[8];
#pragma unroll
    for (int i = 0; i < 8; i++) { c_reg[i] = 0.f; hs_reg[i] = 0.f; }
    for (int i = tid; i < 2 * 32 * SH_STR; i += 512) smf[OFF_H0 + i] = 0.f;
    if (tid < 512) sbias[tid] = bias[tid];

    {
        int t0 = dir ? (T_ - 1) : 0;
        for (int idx = tid; idx < 32 * 52; idx += 512) {
            int rr = idx / 52, c4 = idx - rr * 52;
            int k = c4 << 2;
            float4 v = (k < WD_)
                ? *(const float4*)(doc + ((size_t)(r0 + rr) * T_ + t0) * WD_ + k)
                : make_float4(0.f, 0.f, 0.f, 0.f);
            *(float4*)&smf[OFF_SD0 + rr * SD_STR + k] = v;
        }
    }
    __syncthreads();

    for (int s = 0; s < T_; s++) {
        int p = s & 1;
        unsigned po = p ? SD_BUFB : 0u;
        unsigned ph = p ? SH_BUFB : 0u;

        float acc[2][4][4];
#pragma unroll
        for (int mt = 0; mt < 2; mt++)
#pragma unroll
            for (int g = 0; g < 4; g++) {
                int col = (g << 7) + (w << 3) + qk;
                float b0 = sbias[col], b1 = sbias[col + 1];
                acc[mt][g][0] = b0; acc[mt][g][1] = b1;
                acc[mt][g][2] = b0; acc[mt][g][3] = b1;
            }

        uint4 wv0[4], wv1[4], wv2[4];

#define LOADW(dst, ktv) do { \
            int _kt = (ktv); \
            if (_kt < 21) { \
                const uint4* _p = (_kt < 13) ? (wp_ih + _kt * 2048) \
                                             : (wp_hh + (_kt - 13) * 2048); \
                dst[0] = _p[0];    dst[1] = _p[512]; \
                dst[2] = _p[1024]; dst[3] = _p[1536]; \
            } \
        } while (0)

#define COMPUTE(ktv, wv) do { \
            int _kt = (ktv); \
            _Pragma("unroll") \
            for (int mt = 0; mt < 2; mt++) { \
                unsigned _a0 = (_kt < 13) ? (sd_addr[mt] + po + ((unsigned)_kt << 6)) \
                                          : (sh_addr[mt] + ph + ((unsigned)(_kt - 13) << 6)); \
                unsigned _af0[4], _af1[4]; \
                ldsm_x4_a(_af0, _a0); \
                ldsm_x4_a(_af1, _a0 + 32); \
                _Pragma("unroll") \
                for (int g = 0; g < 4; g++) { \
                    unsigned _b0[2] = { wv[g].x, wv[g].y }; \
                    unsigned _b1[2] = { wv[g].z, wv[g].w }; \
                    MMA_TF32(acc[mt][g], _af0, _b0); \
                    MMA_TF32(acc[mt][g], _af1, _b1); \
                } \
            } \
        } while (0)

        LOADW(wv0, 0);
        LOADW(wv1, 1);
#pragma unroll 1
        for (int k3 = 0; k3 < 21; k3 += 3) {
            LOADW(wv2, k3 + 2);
            COMPUTE(k3, wv0);
            LOADW(wv0, k3 + 3);
            COMPUTE(k3 + 1, wv1);
            LOADW(wv1, k3 + 4);
            COMPUTE(k3 + 2, wv2);
        }
#undef LOADW
#undef COMPUTE

        if (s + 1 < T_) {
            int tn = dir ? (T_ - 2 - s) : (s + 1);
            float* sdn = smf + (p ? OFF_SD0 : OFF_SD1);
            for (int idx = tid; idx < 32 * 52; idx += 512) {
                int rr = idx / 52, c4 = idx - rr * 52;
                int k = c4 << 2;
                float4 v = (k < WD_)
                    ? *(const float4*)(doc + ((size_t)(r0 + rr) * T_ + tn) * WD_ + k)
                    : make_float4(0.f, 0.f, 0.f, 0.f);
                *(float4*)&sdn[rr * SD_STR + k] = v;
            }
        }

        float* hw = smf + (p ? OFF_H0 : OFF_H1);
#pragma unroll
        for (int mt = 0; mt < 2; mt++)
#pragma unroll
            for (int e = 0; e < 4; e++) {
                int row = mt * 16 + gid + ((e >> 1) << 3);
                int col = (w << 3) + qk + (e & 1);
                int ix = mt * 4 + e;
                float iv = acc[mt][0][e];
                float fv = acc[mt][1][e];
                float gv = acc[mt][2][e];
                float ov = acc[mt][3][e];
                float cv = sigf(fv) * c_reg[ix] + sigf(iv) * tanhf(gv);
                c_reg[ix] = cv;
                float h = sigf(ov) * tanhf(cv);
                hs_reg[ix] += h;
                hw[row * SH_STR + col] = h;
            }
        __syncthreads();
    }

#pragma unroll
    for (int mt = 0; mt < 2; mt++)
#pragma unroll
        for (int e = 0; e < 4; e++) {
            int row = mt * 16 + gid + ((e >> 1) << 3);
            int col = (w << 3) + qk + (e & 1);
            sentpres[(size_t)(r0 + row) * 256 + dir * 128 + col] =
                tanhf(hs_reg[mt * 4 + e] * (1.0f / T_));
        }
}

// ================== device GEMM body, K=256, 512 threads ==================
__device__ void gemm256_body(const float* __restrict__ A, const float* __restrict__ W,
                             const float* __restrict__ bias, float* __restrict__ Cc,
                             int amode, int relu, int bx, int by, int Gcols, float* smf)
{
    float* sA = smf;
    float* sB = smf + 2560;
    float* sC = smf;

    int tid = threadIdx.x;
    int lane = tid & 31, wid = tid >> 5;
    int wm = wid & 3, wn = (wid >> 2) & 1;
    int mb = by << 7, nb = bx << 7;
    int lrow = tid >> 2, lq = tid & 3;
    int r = lane >> 2, tc = lane & 3, c2 = tc << 1;

    int am = mb + lrow;
    long arow = amode ? ((long)(((am & 31) << 6) + (am >> 5)) << 8) : ((long)am << 8);
    const float* ap = A + arow + lq * 4;
    const float* bp = W + ((size_t)(nb + lrow) << 8) + lq * 4;

    float acc[2][8][4];
#pragma unroll
    for (int mi = 0; mi < 2; mi++)
#pragma unroll
        for (int ni = 0; ni < 8; ni++)
#pragma unroll
            for (int e = 0; e < 4; e++) acc[mi][ni][e] = 0.f;

#pragma unroll 1
    for (int kb = 0; kb < 256; kb += 16) {
        float4 va = *(const float4*)(ap + kb);
        float4 vb = *(const float4*)(bp + kb);
        __syncthreads();
        *(float4*)&sA[lrow * 20 + lq * 4] = va;
        *(float4*)&sB[lrow * 20 + lq * 4] = vb;
        __syncthreads();

        if (wid < 8) {
            unsigned af[2][2][4];
#pragma unroll
            for (int mi = 0; mi < 2; mi++) {
                int rb = (wm * 32 + mi * 16 + r) * 20;
#pragma unroll
                for (int kh = 0; kh < 2; kh++) {
                    af[mi][kh][0] = __float_as_uint(sA[rb + kh * 8 + tc]);
                    af[mi][kh][1] = __float_as_uint(sA[rb + 160 + kh * 8 + tc]);
                    af[mi][kh][2] = __float_as_uint(sA[rb + kh * 8 + tc + 4]);
                    af[mi][kh][3] = __float_as_uint(sA[rb + 160 + kh * 8 + tc + 4]);
                }
            }
#pragma unroll
            for (int ni = 0; ni < 8; ni++) {
                int nrb = (wn * 64 + ni * 8 + r) * 20;
#pragma unroll
                for (int kh = 0; kh < 2; kh++) {
                    unsigned bf[2];
                    bf[0] = __float_as_uint(sB[nrb + kh * 8 + tc]);
                    bf[1] = __float_as_uint(sB[nrb + kh * 8 + tc + 4]);
#pragma unroll
                    for (int mi = 0; mi < 2; mi++)
                        MMA_TF32(acc[mi][ni], af[mi][kh], bf);
                }
            }
        }
    }
    for (int wmc = 0; wmc < 4; wmc++) {
        __syncthreads();
        if (wid < 8 && wm == wmc) {
#pragma unroll
            for (int mi = 0; mi < 2; mi++)
#pragma unroll
                for (int ni = 0; ni < 8; ni++) {
                    int lr2 = mi * 16 + r;
                    int col = wn * 64 + ni * 8 + c2;
                    float b0 = bias[nb + col], b1 = bias[nb + col + 1];
                    float v0 = acc[mi][ni][0] + b0, v1 = acc[mi][ni][1] + b1;
                    float v2 = acc[mi][ni][2] + b0, v3 = acc[mi][ni][3] + b1;
                    if (relu) {
                        v0 = fmaxf(v0, 0.f); v1 = fmaxf(v1, 0.f);
                        v2 = fmaxf(v2, 0.f); v3 = fmaxf(v3, 0.f);
                    }
                    *(float2*)&sC[lr2 * 128 + col] = make_float2(v0, v1);
                    *(float2*)&sC[(lr2 + 8) * 128 + col] = make_float2(v2, v3);
                }
        }
        __syncthreads();
#pragma unroll
        for (int l = 0; l < 2; l++) {
            int idx = tid + l * 512;
            int row = idx >> 5, c4 = idx & 31;
            *(float4*)&Cc[(size_t)(mb + wmc * 32 + row) * Gcols + nb + c4 * 4] =
                ((float4*)sC)[idx];
        }
    }
}

// ================== tag recurrence role (512 threads, register-local gates) ==================
__device__ void tag_role(const float* __restrict__ Gt, const uint4* __restrict__ whhtag,
                         float* __restrict__ tag_out, int dir, float* smt)
{
    float* h0 = smt;
    const uint4* wp0 = whhtag + dir * 8 * 64 * 32;
    const float* G0 = Gt + (size_t)dir * 2048 * 512;

    int tid = threadIdx.x, lane = tid & 31, w = tid >> 5;
    int gid = lane >> 2, qk = (lane & 3) << 1;

    float c_reg[8];
#pragma unroll
    for (int i = 0; i < 8; i++) c_reg[i] = 0.f;
    for (int i = tid; i < 2 * 32 * SH_STR; i += 512) h0[i] = 0.f;

    unsigned smbase = (unsigned)__cvta_generic_to_shared(h0);
    int tile = lane >> 3, rin = lane & 7;
    int r_off = ((tile & 1) << 3) + rin;
    int c_off = (tile >> 1) << 2;
    unsigned h_addr[2];
#pragma unroll
    for (int mt = 0; mt < 2; mt++)
        h_addr[mt] = smbase + ((unsigned)((mt * 16 + r_off) * SH_STR + c_off) << 2);
    const unsigned HBUF = 32 * SH_STR * 4;
    __syncthreads();

    for (int s = 0; s < 64; s++) {
        int n = dir ? (63 - s) : s;
        int p = s & 1;
        unsigned ph = p ? HBUF : 0u;
        const float* Gn = G0 + (size_t)(n * 32) * 512;

        float acc[2][4][4];
#pragma unroll
        for (int mt = 0; mt < 2; mt++) {
            const float* gr = Gn + (size_t)(mt * 16 + gid) * 512;
#pragma unroll
            for (int g = 0; g < 4; g++) {
                int col = (g << 7) + (w << 3) + qk;
                float2 v0 = *(const float2*)(gr + col);
                float2 v1 = *(const float2*)(gr + 8 * 512 + col);
                acc[mt][g][0] = v0.x; acc[mt][g][1] = v0.y;
                acc[mt][g][2] = v1.x; acc[mt][g][3] = v1.y;
            }
        }

        uint4 wv0[4], wv1[4];
        {
            const uint4* pptr = wp0 + w * 32 + lane;
#pragma unroll
            for (int g = 0; g < 4; g++) wv0[g] = pptr[(g << 4) * 32];
        }
#pragma unroll 1
        for (int kt = 0; kt < 8; kt += 2) {
            {
                const uint4* pptr = wp0 + ((kt + 1) * 64 + w) * 32 + lane;
#pragma unroll
                for (int g = 0; g < 4; g++) wv1[g] = pptr[(g << 4) * 32];
            }
            {
                unsigned af0[2][4], af1[2][4];
#pragma unroll
                for (int mt = 0; mt < 2; mt++) {
                    unsigned a0 = h_addr[mt] + ph + ((unsigned)kt << 6);
                    ldsm_x4_a(af0[mt], a0);
                    ldsm_x4_a(af1[mt], a0 + 32);
                }
#pragma unroll
                for (int g = 0; g < 4; g++) {
                    unsigned b0[2] = { wv0[g].x, wv0[g].y };
                    unsigned b1[2] = { wv0[g].z, wv0[g].w };
#pragma unroll
                    for (int mt = 0; mt < 2; mt++) {
                        MMA_TF32(acc[mt][g], af0[mt], b0);
                        MMA_TF32(acc[mt][g], af1[mt], b1);
                    }
                }
            }
            if (kt + 2 < 8) {
                const uint4* pptr = wp0 + ((kt + 2) * 64 + w) * 32 + lane;
#pragma unroll
                for (int g = 0; g < 4; g++) wv0[g] = pptr[(g << 4) * 32];
            }
            {
                unsigned af0[2][4], af1[2][4];
#pragma unroll
                for (int mt = 0; mt < 2; mt++) {
                    unsigned a0 = h_addr[mt] + ph + ((unsigned)(kt + 1) << 6);
                    ldsm_x4_a(af0[mt], a0);
                    ldsm_x4_a(af1[mt], a0 + 32);
                }
#pragma unroll
                for (int g = 0; g < 4; g++) {
                    unsigned b0[2] = { wv1[g].x, wv1[g].y };
                    unsigned b1[2] = { wv1[g].z, wv1[g].w };
#pragma unroll
                    for (int mt = 0; mt < 2; mt++) {
                        MMA_TF32(acc[mt][g], af0[mt], b0);
                        MMA_TF32(acc[mt][g], af1[mt], b1);
                    }
                }
            }
        }

        float* hw = h0 + (p ? 0 : 32 * SH_STR);
#pragma unroll
        for (int mt = 0; mt < 2; mt++)
#pragma unroll
            for (int e = 0; e < 4; e++) {
                int row = mt * 16 + gid + ((e >> 1) << 3);
                int col = (w << 3) + qk + (e & 1);
                int ix = mt * 4 + e;
                float iv = acc[mt][0][e];
                float fv = acc[mt][1][e];
                float gv = acc[mt][2][e];
                float ov = acc[mt][3][e];
                float cv = sigf(fv) * c_reg[ix] + sigf(iv) * tanhf(gv);
                c_reg[ix] = cv;
                float h = sigf(ov) * tanhf(cv);
                hw[row * SH_STR + col] = h;
                tag_out[(size_t)(row * 64 + n) * 256 + dir * 128 + col] = tanhf(h);
            }
        __syncthreads();
    }
}

// ================== SPP body: 512 threads, 8 bn per block ==================
// smem layout: shq[8][256] | att[8][64] | e8[8][8]  (floats)
__device__ void spp_body(const float* __restrict__ q, const float* __restrict__ k,
                         float* __restrict__ out, int bn_base, float* sm)
{
    float* shq = sm;            // [8][256]
    float* att = sm + 2048;     // [8][64]
    float* e8  = sm + 2560;     // [8][8]
    int tid = threadIdx.x;
    int g = tid >> 6, t = tid & 63;
    int bn = bn_base + g;
    int b = bn >> 6;
    for (int l = t; l < 256; l += 64) shq[g * 256 + l] = q[(size_t)bn * 256 + l];
    __syncthreads();
    const float* kr = k + (size_t)(b * 64 + t) * 256;
    float s = 0.f;
    for (int l = 0; l < 256; l += 4) {
        float4 qa = *(float4*)&shq[g * 256 + l];
        float4 ka = *(const float4*)&kr[l];
        s += qa.x * ka.x + qa.y * ka.y + qa.z * ka.z + qa.w * ka.w;
    }
    att[g * 64 + t] = s * 0.0625f;
    __syncthreads();
    if (t < 8) {
        float m = att[g * 64 + t * 8];
#pragma unroll
        for (int l = 1; l < 8; l++) m = fmaxf(m, att[g * 64 + t * 8 + l]);
        e8[g * 8 + t] = m;
    }
    __syncthreads();
    if (t == 0) {
        float q4[4];
#pragma unroll
        for (int l = 0; l < 4; l++) q4[l] = fmaxf(e8[g * 8 + 2 * l], e8[g * 8 + 2 * l + 1]);
        float h2a = fmaxf(q4[0], q4[1]);
        float h2b = fmaxf(q4[2], q4[3]);
        float* o = out + bn * 15;
        o[0] = fmaxf(h2a, h2b);
        o[1] = h2a; o[2] = h2b;
        o[3] = q4[0]; o[4] = q4[1]; o[5] = q4[2]; o[6] = q4[3];
#pragma unroll
        for (int l = 0; l < 8; l++) o[7 + l] = e8[g * 8 + l];
    }
}

// ================== GCN body: 512 threads ==================
#define XS 257
#define GCN_SMEM ((64 * XS + 64 * 64 + 64) * 4)
__device__ void gcn_body(const float* __restrict__ x, float* __restrict__ agg, int b, float* gs)
{
    float* shx = gs;
    float* shc = gs + 64 * XS;
    float* shn = shc + 4096;
    int tid = threadIdx.x;
    for (int l = tid; l < 16384; l += 512) {
        int i = l >> 8, d = l & 255;
        shx[i * XS + d] = x[(size_t)b * 16384 + l];
    }
    __syncthreads();
    if (tid < 64) {
        float s = 0.f;
        for (int l = 0; l < 256; l++) { float v = shx[tid * XS + l]; s += v * v; }
        shn[tid] = sqrtf(s) + 1e-8f;
    }
    __syncthreads();
    for (int p = tid; p < 4096; p += 512) {
        int i = p >> 6, j = p & 63;
        float s = 0.f;
        for (int l = 0; l < 256; l++) s += shx[i * XS + l] * shx[j * XS + l];
        shc[p] = s / (shn[i] * shn[j]);
    }
    __syncthreads();
    for (int p = tid; p < 16384; p += 512) {
        int i = p >> 8, d = p & 255;
        float s = 2.0f * shx[i * XS + d];
        for (int j = 0; j < 64; j++) s += shc[i * 64 + j] * shx[j * XS + d];
        agg[(size_t)b * 16384 + p] = s * (1.0f / 66.0f);
    }
}

// ================== FAT LAUNCHES ==================
// proj4: gtag_f (64 blocks) | gtag_b (64) | sentQ (32) | sentK (32)
#define PROJ_SMEM (5120 * 4)
__global__ __launch_bounds__(512, 1)
void proj4_kernel(const float* __restrict__ sentpres,
                  const float* __restrict__ twf, const float* __restrict__ tbf,
                  const float* __restrict__ twb, const float* __restrict__ tbb,
                  float* __restrict__ gtag,
                  const float* __restrict__ Wq, const float* __restrict__ bq, float* __restrict__ qout,
                  const float* __restrict__ Wk, const float* __restrict__ bk, float* __restrict__ kout)
{
    extern __shared__ __align__(16) float smc[];
    int blk = blockIdx.x;
    if (blk < 64) {
        gemm256_body(sentpres, twf, tbf, gtag, 1, 0, blk & 3, blk >> 2, 512, smc);
    } else if (blk < 128) {
        int id = blk - 64;
        gemm256_body(sentpres, twb, tbb, gtag + BN_ * G4_, 1, 0, id & 3, id >> 2, 512, smc);
    } else if (blk < 160) {
        int id = blk - 128;
        gemm256_body(sentpres, Wq, bq, qout, 0, 0, id & 1, id >> 1, 256, smc);
    } else {
        int id = blk - 160;
        gemm256_body(sentpres, Wk, bk, kout, 0, 0, id & 1, id >> 1, 256, smc);
    }
}

// combined: tag (2 blocks) + sentFt SPP (256 blocks)
#define COMB_SMEM (2 * 32 * SH_STR * 4)
__global__ __launch_bounds__(512, 1)
void tag_spp_combined(const float* __restrict__ Gt, const uint4* __restrict__ whhtag,
                      float* __restrict__ tag_out,
                      const float* __restrict__ qb, const float* __restrict__ kb,
                      float* __restrict__ sFt)
{
    extern __shared__ __align__(16) float smc[];
    int blk = blockIdx.x;
    if (blk < 2) tag_role(Gt, whhtag, tag_out, blk, smc);
    else         spp_body(qb, kb, sFt, (blk - 2) * 8, smc);
}

// fat3: gcn (32) | roleQ (32) | roleK (32)
__global__ __launch_bounds__(512, 1)
void fat3_kernel(const float* __restrict__ tago, float* __restrict__ agg,
                 const float* __restrict__ Wq, const float* __restrict__ bq, float* __restrict__ qout,
                 const float* __restrict__ Wk, const float* __restrict__ bk, float* __restrict__ kout)
{
    extern __shared__ __align__(16) float smc[];
    int blk = blockIdx.x;
    if (blk < 32) {
        gcn_body(tago, agg, blk, smc);
    } else if (blk < 64) {
        int id = blk - 32;
        gemm256_body(tago, Wq, bq, qout, 0, 0, id & 1, id >> 1, 256, smc);
    } else {
        int id = blk - 64;
        gemm256_body(tago, Wk, bk, kout, 0, 0, id & 1, id >> 1, 256, smc);
    }
}

// fat4: sage (32) | roleFt SPP (256)
__global__ __launch_bounds__(512, 1)
void fat4_kernel(const float* __restrict__ agg,
                 const float* __restrict__ sW, const float* __restrict__ sb, float* __restrict__ gcn_out,
                 const float* __restrict__ qb, const float* __restrict__ kb, float* __restrict__ rFt)
{
    extern __shared__ __align__(16) float smc[];
    int blk = blockIdx.x;
    if (blk < 32) {
        gemm256_body(agg, sW, sb, gcn_out, 0, 1, blk & 1, blk >> 1, 256, smc);
    } else {
        spp_body(qb, kb, rFt, (blk - 32) * 8, smc);
    }
}

// ================== classifier + log_softmax ==================
__global__ void cls_kernel(const float* __restrict__ tago, const float* __restrict__ sFt,
                           const float* __restrict__ rFt, const float* __restrict__ W,
                           const float* __restrict__ bias, float* __restrict__ out)
{
    int bn = blockIdx.x;
    int tid = threadIdx.x;
    int c = tid >> 5, lane = tid & 31;
    __shared__ float sh[8];
    const float* w = W + c * 286;
    const float* t = tago + (size_t)bn * 256;
    float s = 0.f;
    for (int l = lane; l < 256; l += 32) s += t[l] * w[l];
    if (lane < 15) {
        s += sFt[bn * 15 + lane] * w[256 + lane];
        s += rFt[bn * 15 + lane] * w[271 + lane];
    }
#pragma unroll
    for (int off = 16; off > 0; off >>= 1)
        s += __shfl_down_sync(0xFFFFFFFF, s, off);
    if (lane == 0) sh[c] = s + bias[c];
    __syncthreads();
    if (tid < 8) {
        float m = sh[0];
#pragma unroll
        for (int l = 1; l < 8; l++) m = fmaxf(m, sh[l]);
        float se = 0.f;
#pragma unroll
        for (int l = 0; l < 8; l++) se += expf(sh[l] - m);
        out[bn * 8 + tid] = sh[tid] - m - logf(se);
    }
}

// ================== launch ==================
extern "C" void kernel_launch(void* const* d_in, const int* in_sizes, int n_in,
                              void* d_out, int out_size)
{
    const float* documents = (const float*)d_in[0];
    const float* sw_ih_f = (const float*)d_in[1];
    const float* sw_hh_f = (const float*)d_in[2];
    const float* sb_f    = (const float*)d_in[3];
    const float* sw_ih_b = (const float*)d_in[4];
    const float* sw_hh_b = (const float*)d_in[5];
    const float* sb_b    = (const float*)d_in[6];
    const float* sf_Wq = (const float*)d_in[7];
    const float* sf_bq = (const float*)d_in[8];
    const float* sf_Wk = (const float*)d_in[9];
    const float* sf_bk = (const float*)d_in[10];
    const float* rf_Wq = (const float*)d_in[11];
    const float* rf_bq = (const float*)d_in[12];
    const float* rf_Wk = (const float*)d_in[13];
    const float* rf_bk = (const float*)d_in[14];
    const float* tw_ih_f = (const float*)d_in[15];
    const float* tw_hh_f = (const float*)d_in[16];
    const float* tb_f    = (const float*)d_in[17];
    const float* tw_ih_b = (const float*)d_in[18];
    const float* tw_hh_b = (const float*)d_in[19];
    const float* tb_b    = (const float*)d_in[20];
    const float* sage_W = (const float*)d_in[21];
    const float* sage_b = (const float*)d_in[22];
    const float* cls_W  = (const float*)d_in[23];
    const float* cls_b  = (const float*)d_in[24];

    float* out = (float*)d_out;
    float* result_out = out;
    float* gcn_out = out + B_ * N_ * C_;

    float *sentpres, *qb, *kb, *q2, *k2, *sFt, *rFt, *gtag, *tago, *agg;
    uint4 *wihp, *whhp, *whhtagp;
    cudaGetSymbolAddress((void**)&wihp, wih_pk_buf);
    cudaGetSymbolAddress((void**)&whhp, whh_pk_buf);
    cudaGetSymbolAddress((void**)&whhtagp, whh_tag_pk_buf);
    cudaGetSymbolAddress((void**)&sentpres, sentpres_buf);
    cudaGetSymbolAddress((void**)&qb, q_buf);
    cudaGetSymbolAddress((void**)&kb, k_buf);
    cudaGetSymbolAddress((void**)&q2, q2_buf);
    cudaGetSymbolAddress((void**)&k2, k2_buf);
    cudaGetSymbolAddress((void**)&sFt, sentFt_buf);
    cudaGetSymbolAddress((void**)&rFt, roleFt_buf);
    cudaGetSymbolAddress((void**)&gtag, g_tag_buf);
    cudaGetSymbolAddress((void**)&tago, tag_out_buf);
    cudaGetSymbolAddress((void**)&agg, agg_buf);

    cudaFuncSetAttribute(lstm_sent_fused, cudaFuncAttributeMaxDynamicSharedMemorySize, FUSED_SMEM);
    cudaFuncSetAttribute(proj4_kernel, cudaFuncAttributeMaxDynamicSharedMemorySize, PROJ_SMEM);
    cudaFuncSetAttribute(tag_spp_combined, cudaFuncAttributeMaxDynamicSharedMemorySize, COMB_SMEM);
    cudaFuncSetAttribute(fat3_kernel, cudaFuncAttributeMaxDynamicSharedMemorySize, GCN_SMEM);
    cudaFuncSetAttribute(fat4_kernel, cudaFuncAttributeMaxDynamicSharedMemorySize, PROJ_SMEM);

    // prep
    pack_wih_tf32<<<(2 * 13 * 64 * 32 + 255) / 256, 256>>>(sw_ih_f, sw_ih_b, wihp);
    pack_whh_tf32<<<128, 256>>>(sw_hh_f, sw_hh_b, whhp);
    pack_whh_tf32<<<128, 256>>>(tw_hh_f, tw_hh_b, whhtagp);

    // FUSED sentence BiLSTM
    lstm_sent_fused<<<dim3(64, 2), 512, FUSED_SMEM>>>(documents, wihp, whhp, sb_f, sb_b, sentpres);

    // proj4: gtag f/b + sentFt Q/K
    proj4_kernel<<<192, 512, PROJ_SMEM>>>(sentpres, tw_ih_f, tb_f, tw_ih_b, tb_b, gtag,
                                          sf_Wq, sf_bq, qb, sf_Wk, sf_bk, kb);

    // combined: tag recurrence + sentFt SPP
    tag_spp_combined<<<258, 512, COMB_SMEM>>>(gtag, whhtagp, tago, qb, kb, sFt);

    // fat3: gcn + roleFt Q/K
    fat3_kernel<<<96, 512, GCN_SMEM>>>(tago, agg, rf_Wq, rf_bq, q2, rf_Wk, rf_bk, k2);

    // fat4: sage + roleFt SPP
    fat4_kernel<<<288, 512, PROJ_SMEM>>>(agg, sage_W, sage_b, gcn_out, q2, k2, rFt);

    cls_kernel<<<2048, 256>>>(tago, sFt, rFt, cls_W, cls_b, result_out);

    (void)in_sizes; (void)n_in; (void)out_size;
}

// round 16
// speedup vs baseline: 2.0157x; 1.1431x over previous
#include <cuda_runtime.h>
#include <cuda_bf16.h>
#include <stdint.h>
#include <math.h>

// ---------------- problem constants ----------------
#define B_    32
#define N_    64
#define T_    50
#define WD_   200
#define H_    128
#define G4_   512
#define D2_   256
#define BN_   2048
#define C_    8

// ---------------- scratch ----------------
__device__ uint4 wih_pk_buf[2 * 13 * 64 * 32];
__device__ uint4 whh_pk_buf[2 * 8 * 64 * 32];
__device__ uint4 whh_tag_pk_buf[2 * 8 * 64 * 32];
__device__ float sentpres_buf[BN_ * D2_];
__device__ float q_buf[BN_ * D2_];
__device__ float k_buf[BN_ * D2_];
__device__ float q2_buf[BN_ * D2_];
__device__ float k2_buf[BN_ * D2_];
__device__ float sentFt_buf[BN_ * 15];
__device__ float roleFt_buf[BN_ * 15];
__device__ float g_tag_buf[2 * BN_ * G4_];
__device__ float tag_out_buf[BN_ * D2_];
__device__ float agg_buf[BN_ * D2_];

__device__ __forceinline__ float sigf(float x) { return __fdividef(1.0f, 1.0f + __expf(-x)); }

#define MMA_TF32(d, a, b) \
    asm volatile("mma.sync.aligned.m16n8k8.row.col.f32.tf32.tf32.f32 " \
                 "{%0,%1,%2,%3},{%4,%5,%6,%7},{%8,%9},{%0,%1,%2,%3};\n" \
                 : "+f"(d[0]), "+f"(d[1]), "+f"(d[2]), "+f"(d[3]) \
                 : "r"(a[0]), "r"(a[1]), "r"(a[2]), "r"(a[3]), "r"(b[0]), "r"(b[1]))

__device__ __forceinline__ void ldsm_x4_a(unsigned af[4], unsigned addr)
{
    asm volatile("ldmatrix.sync.aligned.m8n8.x4.shared.b16 {%0,%1,%2,%3}, [%4];"
                 : "=r"(af[0]), "=r"(af[1]), "=r"(af[2]), "=r"(af[3]) : "r"(addr));
}

// ================== merged weight packing (one launch) ==================
// blocks [0,208): W_ih; [208,336): sent W_hh; [336,464): tag W_hh
__global__ void pack_all(const float* __restrict__ wihf, const float* __restrict__ wihb,
                         uint4* __restrict__ owih,
                         const float* __restrict__ whf, const float* __restrict__ whb,
                         uint4* __restrict__ owhh,
                         const float* __restrict__ wtf, const float* __restrict__ wtb,
                         uint4* __restrict__ owtag)
{
    int blk = blockIdx.x;
    int tid = threadIdx.x;
    if (blk < 208) {
        int i = blk * 256 + tid;
        if (i >= 2 * 13 * 64 * 32) return;
        const int per = 13 * 64 * 32;
        int dir = i / per, rem = i % per;
        int kt = rem >> 11, ng = (rem >> 5) & 63, lane = rem & 31;
        const float* w = dir ? wihb : wihf;
        int n = ng * 8 + (lane >> 2);
        int k = kt * 16 + (lane & 3);
        uint4 v;
        v.x = (k      < WD_) ? __float_as_uint(w[n * WD_ + k])      : 0u;
        v.y = (k + 4  < WD_) ? __float_as_uint(w[n * WD_ + k + 4])  : 0u;
        v.z = (k + 8  < WD_) ? __float_as_uint(w[n * WD_ + k + 8])  : 0u;
        v.w = (k + 12 < WD_) ? __float_as_uint(w[n * WD_ + k + 12]) : 0u;
        owih[i] = v;
    } else {
        int src = (blk < 336) ? 0 : 1;
        int i = (blk - (src ? 336 : 208)) * 256 + tid;
        int lane = i & 31, ng = (i >> 5) & 63, kt = (i >> 11) & 7, dir = i >> 14;
        const float* w = src ? (dir ? wtb : wtf) : (dir ? whb : whf);
        int n = ng * 8 + (lane >> 2);
        int k = kt * 16 + (lane & 3);
        uint4 v;
        v.x = __float_as_uint(w[n * 128 + k]);
        v.y = __float_as_uint(w[n * 128 + k + 4]);
        v.z = __float_as_uint(w[n * 128 + k + 8]);
        v.w = __float_as_uint(w[n * 128 + k + 12]);
        (src ? owtag : owhh)[i] = v;
    }
}

// ================== FUSED sentence BiLSTM (unchanged) ==================
#define SD_STR 212
#define SH_STR 132
#define OFF_SD0   0
#define OFF_SD1   6784
#define OFF_H0    13568
#define OFF_H1    17792
#define OFF_BIAS  22016
#define FUSED_SMEM ((22016 + 512) * 4)
#define SD_BUFB   27136
#define SH_BUFB   16896

__global__ __launch_bounds__(512, 1)
void lstm_sent_fused(const float* __restrict__ doc,
                     const uint4* __restrict__ wih, const uint4* __restrict__ whh,
                     const float* __restrict__ biasf, const float* __restrict__ biasb,
                     float* __restrict__ sentpres)
{
    extern __shared__ __align__(16) float smf[];
    float* sbias = smf + OFF_BIAS;

    int dir = blockIdx.y;
    int r0 = blockIdx.x << 5;
    const float* bias = dir ? biasb : biasf;

    int tid = threadIdx.x, lane = tid & 31, w = tid >> 5;
    int gid = lane >> 2, qk = (lane & 3) << 1;

    const uint4* wp_ih = wih + dir * 13 * 64 * 32 + w * 32 + lane;
    const uint4* wp_hh = whh + dir * 8 * 64 * 32 + w * 32 + lane;

    unsigned smbase = (unsigned)__cvta_generic_to_shared(smf);
    int tile = lane >> 3, rin = lane & 7;
    int r_off = ((tile & 1) << 3) + rin;
    int c_off = (tile >> 1) << 2;
    unsigned sd_addr[2], sh_addr[2];
#pragma unroll
    for (int mt = 0; mt < 2; mt++) {
        sd_addr[mt] = smbase + ((unsigned)(OFF_SD0 + (mt * 16 + r_off) * SD_STR + c_off) << 2);
        sh_addr[mt] = smbase + ((unsigned)(OFF_H0 + (mt * 16 + r_off) * SH_STR + c_off) << 2);
    }

    float c_reg[8], hs_reg[8];
#pragma unroll
    for (int i = 0; i < 8; i++) { c_reg[i] = 0.f; hs_reg[i] = 0.f; }
    for (int i = tid; i < 2 * 32 * SH_STR; i += 512) smf[OFF_H0 + i] = 0.f;
    if (tid < 512) sbias[tid] = bias[tid];

    {
        int t0 = dir ? (T_ - 1) : 0;
        for (int idx = tid; idx < 32 * 52; idx += 512) {
            int rr = idx / 52, c4 = idx - rr * 52;
            int k = c4 << 2;
            float4 v = (k < WD_)
                ? *(const float4*)(doc + ((size_t)(r0 + rr) * T_ + t0) * WD_ + k)
                : make_float4(0.f, 0.f, 0.f, 0.f);
            *(float4*)&smf[OFF_SD0 + rr * SD_STR + k] = v;
        }
    }
    __syncthreads();

    for (int s = 0; s < T_; s++) {
        int p = s & 1;
        unsigned po = p ? SD_BUFB : 0u;
        unsigned ph = p ? SH_BUFB : 0u;

        float acc[2][4][4];
#pragma unroll
        for (int mt = 0; mt < 2; mt++)
#pragma unroll
            for (int g = 0; g < 4; g++) {
                int col = (g << 7) + (w << 3) + qk;
                float b0 = sbias[col], b1 = sbias[col + 1];
                acc[mt][g][0] = b0; acc[mt][g][1] = b1;
                acc[mt][g][2] = b0; acc[mt][g][3] = b1;
            }

        uint4 wv0[4], wv1[4], wv2[4];

#define LOADW(dst, ktv) do { \
            int _kt = (ktv); \
            if (_kt < 21) { \
                const uint4* _p = (_kt < 13) ? (wp_ih + _kt * 2048) \
                                             : (wp_hh + (_kt - 13) * 2048); \
                dst[0] = _p[0];    dst[1] = _p[512]; \
                dst[2] = _p[1024]; dst[3] = _p[1536]; \
            } \
        } while (0)

#define COMPUTE(ktv, wv) do { \
            int _kt = (ktv); \
            _Pragma("unroll") \
            for (int mt = 0; mt < 2; mt++) { \
                unsigned _a0 = (_kt < 13) ? (sd_addr[mt] + po + ((unsigned)_kt << 6)) \
                                          : (sh_addr[mt] + ph + ((unsigned)(_kt - 13) << 6)); \
                unsigned _af0[4], _af1[4]; \
                ldsm_x4_a(_af0, _a0); \
                ldsm_x4_a(_af1, _a0 + 32); \
                _Pragma("unroll") \
                for (int g = 0; g < 4; g++) { \
                    unsigned _b0[2] = { wv[g].x, wv[g].y }; \
                    unsigned _b1[2] = { wv[g].z, wv[g].w }; \
                    MMA_TF32(acc[mt][g], _af0, _b0); \
                    MMA_TF32(acc[mt][g], _af1, _b1); \
                } \
            } \
        } while (0)

        LOADW(wv0, 0);
        LOADW(wv1, 1);
#pragma unroll 1
        for (int k3 = 0; k3 < 21; k3 += 3) {
            LOADW(wv2, k3 + 2);
            COMPUTE(k3, wv0);
            LOADW(wv0, k3 + 3);
            COMPUTE(k3 + 1, wv1);
            LOADW(wv1, k3 + 4);
            COMPUTE(k3 + 2, wv2);
        }
#undef LOADW
#undef COMPUTE

        if (s + 1 < T_) {
            int tn = dir ? (T_ - 2 - s) : (s + 1);
            float* sdn = smf + (p ? OFF_SD0 : OFF_SD1);
            for (int idx = tid; idx < 32 * 52; idx += 512) {
                int rr = idx / 52, c4 = idx - rr * 52;
                int k = c4 << 2;
                float4 v = (k < WD_)
                    ? *(const float4*)(doc + ((size_t)(r0 + rr) * T_ + tn) * WD_ + k)
                    : make_float4(0.f, 0.f, 0.f, 0.f);
                *(float4*)&sdn[rr * SD_STR + k] = v;
            }
        }

        float* hw = smf + (p ? OFF_H0 : OFF_H1);
#pragma unroll
        for (int mt = 0; mt < 2; mt++)
#pragma unroll
            for (int e = 0; e < 4; e++) {
                int row = mt * 16 + gid + ((e >> 1) << 3);
                int col = (w << 3) + qk + (e & 1);
                int ix = mt * 4 + e;
                float iv = acc[mt][0][e];
                float fv = acc[mt][1][e];
                float gv = acc[mt][2][e];
                float ov = acc[mt][3][e];
                float cv = sigf(fv) * c_reg[ix] + sigf(iv) * tanhf(gv);
                c_reg[ix] = cv;
                float h = sigf(ov) * tanhf(cv);
                hs_reg[ix] += h;
                hw[row * SH_STR + col] = h;
            }
        __syncthreads();
    }

#pragma unroll
    for (int mt = 0; mt < 2; mt++)
#pragma unroll
        for (int e = 0; e < 4; e++) {
            int row = mt * 16 + gid + ((e >> 1) << 3);
            int col = (w << 3) + qk + (e & 1);
            sentpres[(size_t)(r0 + row) * 256 + dir * 128 + col] =
                tanhf(hs_reg[mt * 4 + e] * (1.0f / T_));
        }
}

// ================== device GEMM body, K=256, 512 threads ==================
__device__ void gemm256_body(const float* __restrict__ A, const float* __restrict__ W,
                             const float* __restrict__ bias, float* __restrict__ Cc,
                             int amode, int relu, int bx, int by, int Gcols, float* smf)
{
    float* sA = smf;
    float* sB = smf + 2560;
    float* sC = smf;

    int tid = threadIdx.x;
    int lane = tid & 31, wid = tid >> 5;
    int wm = wid & 3, wn = (wid >> 2) & 1;
    int mb = by << 7, nb = bx << 7;
    int lrow = tid >> 2, lq = tid & 3;
    int r = lane >> 2, tc = lane & 3, c2 = tc << 1;

    int am = mb + lrow;
    long arow = amode ? ((long)(((am & 31) << 6) + (am >> 5)) << 8) : ((long)am << 8);
    const float* ap = A + arow + lq * 4;
    const float* bp = W + ((size_t)(nb + lrow) << 8) + lq * 4;

    float acc[2][8][4];
#pragma unroll
    for (int mi = 0; mi < 2; mi++)
#pragma unroll
        for (int ni = 0; ni < 8; ni++)
#pragma unroll
            for (int e = 0; e < 4; e++) acc[mi][ni][e] = 0.f;

#pragma unroll 1
    for (int kb = 0; kb < 256; kb += 16) {
        float4 va = *(const float4*)(ap + kb);
        float4 vb = *(const float4*)(bp + kb);
        __syncthreads();
        *(float4*)&sA[lrow * 20 + lq * 4] = va;
        *(float4*)&sB[lrow * 20 + lq * 4] = vb;
        __syncthreads();

        if (wid < 8) {
            unsigned af[2][2][4];
#pragma unroll
            for (int mi = 0; mi < 2; mi++) {
                int rb = (wm * 32 + mi * 16 + r) * 20;
#pragma unroll
                for (int kh = 0; kh < 2; kh++) {
                    af[mi][kh][0] = __float_as_uint(sA[rb + kh * 8 + tc]);
                    af[mi][kh][1] = __float_as_uint(sA[rb + 160 + kh * 8 + tc]);
                    af[mi][kh][2] = __float_as_uint(sA[rb + kh * 8 + tc + 4]);
                    af[mi][kh][3] = __float_as_uint(sA[rb + 160 + kh * 8 + tc + 4]);
                }
            }
#pragma unroll
            for (int ni = 0; ni < 8; ni++) {
                int nrb = (wn * 64 + ni * 8 + r) * 20;
#pragma unroll
                for (int kh = 0; kh < 2; kh++) {
                    unsigned bf[2];
                    bf[0] = __float_as_uint(sB[nrb + kh * 8 + tc]);
                    bf[1] = __float_as_uint(sB[nrb + kh * 8 + tc + 4]);
#pragma unroll
                    for (int mi = 0; mi < 2; mi++)
                        MMA_TF32(acc[mi][ni], af[mi][kh], bf);
                }
            }
        }
    }
    for (int wmc = 0; wmc < 4; wmc++) {
        __syncthreads();
        if (wid < 8 && wm == wmc) {
#pragma unroll
            for (int mi = 0; mi < 2; mi++)
#pragma unroll
                for (int ni = 0; ni < 8; ni++) {
                    int lr2 = mi * 16 + r;
                    int col = wn * 64 + ni * 8 + c2;
                    float b0 = bias[nb + col], b1 = bias[nb + col + 1];
                    float v0 = acc[mi][ni][0] + b0, v1 = acc[mi][ni][1] + b1;
                    float v2 = acc[mi][ni][2] + b0, v3 = acc[mi][ni][3] + b1;
                    if (relu) {
                        v0 = fmaxf(v0, 0.f); v1 = fmaxf(v1, 0.f);
                        v2 = fmaxf(v2, 0.f); v3 = fmaxf(v3, 0.f);
                    }
                    *(float2*)&sC[lr2 * 128 + col] = make_float2(v0, v1);
                    *(float2*)&sC[(lr2 + 8) * 128 + col] = make_float2(v2, v3);
                }
        }
        __syncthreads();
#pragma unroll
        for (int l = 0; l < 2; l++) {
            int idx = tid + l * 512;
            int row = idx >> 5, c4 = idx & 31;
            *(float4*)&Cc[(size_t)(mb + wmc * 32 + row) * Gcols + nb + c4 * 4] =
                ((float4*)sC)[idx];
        }
    }
}

// ================== tag recurrence half: 16 batch rows, 512 threads, G reg prefetch ==================
__device__ void tag_role_half(const float* __restrict__ Gt, const uint4* __restrict__ whhtag,
                              float* __restrict__ tag_out, int dir, int half, float* smt)
{
    float* h0 = smt;   // [2][16][SH_STR]
    const uint4* wp0 = whhtag + dir * 8 * 64 * 32;
    const float* G0 = Gt + (size_t)dir * 2048 * 512;
    int rbase = half << 4;

    int tid = threadIdx.x, lane = tid & 31, w = tid >> 5;
    int gid = lane >> 2, qk = (lane & 3) << 1;

    float c_reg[4];
#pragma unroll
    for (int i = 0; i < 4; i++) c_reg[i] = 0.f;
    for (int i = tid; i < 2 * 16 * SH_STR; i += 512) h0[i] = 0.f;

    unsigned smbase = (unsigned)__cvta_generic_to_shared(h0);
    int tile = lane >> 3, rin = lane & 7;
    int r_off = ((tile & 1) << 3) + rin;
    int c_off = (tile >> 1) << 2;
    unsigned h_addr = smbase + ((unsigned)(r_off * SH_STR + c_off) << 2);
    const unsigned HBUF = 16 * SH_STR * 4;
    __syncthreads();

#define LOADG(dst, nn) do { \
        const float* _gr = G0 + (size_t)((nn) * 32 + rbase + gid) * 512; \
        _Pragma("unroll") \
        for (int g = 0; g < 4; g++) { \
            int _col = (g << 7) + (w << 3) + qk; \
            dst[g][0] = *(const float2*)(_gr + _col); \
            dst[g][1] = *(const float2*)(_gr + 8 * 512 + _col); \
        } \
    } while (0)

    float2 gc[4][2], gn[4][2];
    LOADG(gc, dir ? 63 : 0);

    for (int s = 0; s < 64; s++) {
        int n = dir ? (63 - s) : s;
        int p = s & 1;
        unsigned ph = p ? HBUF : 0u;

        float acc[4][4];
#pragma unroll
        for (int g = 0; g < 4; g++) {
            acc[g][0] = gc[g][0].x; acc[g][1] = gc[g][0].y;
            acc[g][2] = gc[g][1].x; acc[g][3] = gc[g][1].y;
        }

        // prefetch next step's G into registers (hides DRAM latency behind mma loop)
        if (s + 1 < 64) {
            int nn = dir ? (62 - s) : (s + 1);
            LOADG(gn, nn);
        }

        uint4 wv0[4], wv1[4];
        {
            const uint4* pptr = wp0 + w * 32 + lane;
#pragma unroll
            for (int g = 0; g < 4; g++) wv0[g] = pptr[(g << 4) * 32];
        }
#pragma unroll 1
        for (int kt = 0; kt < 8; kt += 2) {
            {
                const uint4* pptr = wp0 + ((kt + 1) * 64 + w) * 32 + lane;
#pragma unroll
                for (int g = 0; g < 4; g++) wv1[g] = pptr[(g << 4) * 32];
            }
            {
                unsigned af0[4], af1[4];
                unsigned a0 = h_addr + ph + ((unsigned)kt << 6);
                ldsm_x4_a(af0, a0);
                ldsm_x4_a(af1, a0 + 32);
#pragma unroll
                for (int g = 0; g < 4; g++) {
                    unsigned b0[2] = { wv0[g].x, wv0[g].y };
                    unsigned b1[2] = { wv0[g].z, wv0[g].w };
                    MMA_TF32(acc[g], af0, b0);
                    MMA_TF32(acc[g], af1, b1);
                }
            }
            if (kt + 2 < 8) {
                const uint4* pptr = wp0 + ((kt + 2) * 64 + w) * 32 + lane;
#pragma unroll
                for (int g = 0; g < 4; g++) wv0[g] = pptr[(g << 4) * 32];
            }
            {
                unsigned af0[4], af1[4];
                unsigned a0 = h_addr + ph + ((unsigned)(kt + 1) << 6);
                ldsm_x4_a(af0, a0);
                ldsm_x4_a(af1, a0 + 32);
#pragma unroll
                for (int g = 0; g < 4; g++) {
                    unsigned b0[2] = { wv1[g].x, wv1[g].y };
                    unsigned b1[2] = { wv1[g].z, wv1[g].w };
                    MMA_TF32(acc[g], af0, b0);
                    MMA_TF32(acc[g], af1, b1);
                }
            }
        }

        // register-local cell update -> write h into the OTHER buffer
        float* hw = h0 + (p ? 0 : 16 * SH_STR);
#pragma unroll
        for (int e = 0; e < 4; e++) {
            int lrow = gid + ((e >> 1) << 3);
            int col = (w << 3) + qk + (e & 1);
            float iv = acc[0][e];
            float fv = acc[1][e];
            float gv = acc[2][e];
            float ov = acc[3][e];
            float cv = sigf(fv) * c_reg[e] + sigf(iv) * tanhf(gv);
            c_reg[e] = cv;
            float h = sigf(ov) * tanhf(cv);
            hw[lrow * SH_STR + col] = h;
            tag_out[(size_t)((rbase + lrow) * 64 + n) * 256 + dir * 128 + col] = tanhf(h);
        }
        __syncthreads();

#pragma unroll
        for (int g = 0; g < 4; g++) { gc[g][0] = gn[g][0]; gc[g][1] = gn[g][1]; }
    }
#undef LOADG
}

// ================== SPP body: 512 threads, 8 bn per block ==================
__device__ void spp_body(const float* __restrict__ q, const float* __restrict__ k,
                         float* __restrict__ out, int bn_base, float* sm)
{
    float* shq = sm;
    float* att = sm + 2048;
    float* e8  = sm + 2560;
    int tid = threadIdx.x;
    int g = tid >> 6, t = tid & 63;
    int bn = bn_base + g;
    int b = bn >> 6;
    for (int l = t; l < 256; l += 64) shq[g * 256 + l] = q[(size_t)bn * 256 + l];
    __syncthreads();
    const float* kr = k + (size_t)(b * 64 + t) * 256;
    float s = 0.f;
    for (int l = 0; l < 256; l += 4) {
        float4 qa = *(float4*)&shq[g * 256 + l];
        float4 ka = *(const float4*)&kr[l];
        s += qa.x * ka.x + qa.y * ka.y + qa.z * ka.z + qa.w * ka.w;
    }
    att[g * 64 + t] = s * 0.0625f;
    __syncthreads();
    if (t < 8) {
        float m = att[g * 64 + t * 8];
#pragma unroll
        for (int l = 1; l < 8; l++) m = fmaxf(m, att[g * 64 + t * 8 + l]);
        e8[g * 8 + t] = m;
    }
    __syncthreads();
    if (t == 0) {
        float q4[4];
#pragma unroll
        for (int l = 0; l < 4; l++) q4[l] = fmaxf(e8[g * 8 + 2 * l], e8[g * 8 + 2 * l + 1]);
        float h2a = fmaxf(q4[0], q4[1]);
        float h2b = fmaxf(q4[2], q4[3]);
        float* o = out + bn * 15;
        o[0] = fmaxf(h2a, h2b);
        o[1] = h2a; o[2] = h2b;
        o[3] = q4[0]; o[4] = q4[1]; o[5] = q4[2]; o[6] = q4[3];
#pragma unroll
        for (int l = 0; l < 8; l++) o[7 + l] = e8[g * 8 + l];
    }
}

// ================== GCN body: 512 threads ==================
#define XS 257
#define GCN_SMEM ((64 * XS + 64 * 64 + 64) * 4)
__device__ void gcn_body(const float* __restrict__ x, float* __restrict__ agg, int b, float* gs)
{
    float* shx = gs;
    float* shc = gs + 64 * XS;
    float* shn = shc + 4096;
    int tid = threadIdx.x;
    for (int l = tid; l < 16384; l += 512) {
        int i = l >> 8, d = l & 255;
        shx[i * XS + d] = x[(size_t)b * 16384 + l];
    }
    __syncthreads();
    if (tid < 64) {
        float s = 0.f;
        for (int l = 0; l < 256; l++) { float v = shx[tid * XS + l]; s += v * v; }
        shn[tid] = sqrtf(s) + 1e-8f;
    }
    __syncthreads();
    for (int p = tid; p < 4096; p += 512) {
        int i = p >> 6, j = p & 63;
        float s = 0.f;
        for (int l = 0; l < 256; l++) s += shx[i * XS + l] * shx[j * XS + l];
        shc[p] = s / (shn[i] * shn[j]);
    }
    __syncthreads();
    for (int p = tid; p < 16384; p += 512) {
        int i = p >> 8, d = p & 255;
        float s = 2.0f * shx[i * XS + d];
        for (int j = 0; j < 64; j++) s += shc[i * 64 + j] * shx[j * XS + d];
        agg[(size_t)b * 16384 + p] = s * (1.0f / 66.0f);
    }
}

// ================== FAT LAUNCHES ==================
#define PROJ_SMEM (5120 * 4)
__global__ __launch_bounds__(512, 1)
void proj4_kernel(const float* __restrict__ sentpres,
                  const float* __restrict__ twf, const float* __restrict__ tbf,
                  const float* __restrict__ twb, const float* __restrict__ tbb,
                  float* __restrict__ gtag,
                  const float* __restrict__ Wq, const float* __restrict__ bq, float* __restrict__ qout,
                  const float* __restrict__ Wk, const float* __restrict__ bk, float* __restrict__ kout)
{
    extern __shared__ __align__(16) float smc[];
    int blk = blockIdx.x;
    if (blk < 64) {
        gemm256_body(sentpres, twf, tbf, gtag, 1, 0, blk & 3, blk >> 2, 512, smc);
    } else if (blk < 128) {
        int id = blk - 64;
        gemm256_body(sentpres, twb, tbb, gtag + BN_ * G4_, 1, 0, id & 3, id >> 2, 512, smc);
    } else if (blk < 160) {
        int id = blk - 128;
        gemm256_body(sentpres, Wq, bq, qout, 0, 0, id & 1, id >> 1, 256, smc);
    } else {
        int id = blk - 160;
        gemm256_body(sentpres, Wk, bk, kout, 0, 0, id & 1, id >> 1, 256, smc);
    }
}

// combined: tag (4 blocks: dir = blk>>1, half = blk&1) + sentFt SPP (256 blocks)
#define COMB_SMEM (2 * 16 * SH_STR * 4)
__global__ __launch_bounds__(512, 1)
void tag_spp_combined(const float* __restrict__ Gt, const uint4* __restrict__ whhtag,
                      float* __restrict__ tag_out,
                      const float* __restrict__ qb, const float* __restrict__ kb,
                      float* __restrict__ sFt)
{
    extern __shared__ __align__(16) float smc[];
    int blk = blockIdx.x;
    if (blk < 4) tag_role_half(Gt, whhtag, tag_out, blk >> 1, blk & 1, smc);
    else         spp_body(qb, kb, sFt, (blk - 4) * 8, smc);
}

// fat3: gcn (32) | roleQ (32) | roleK (32)
__global__ __launch_bounds__(512, 1)
void fat3_kernel(const float* __restrict__ tago, float* __restrict__ agg,
                 const float* __restrict__ Wq, const float* __restrict__ bq, float* __restrict__ qout,
                 const float* __restrict__ Wk, const float* __restrict__ bk, float* __restrict__ kout)
{
    extern __shared__ __align__(16) float smc[];
    int blk = blockIdx.x;
    if (blk < 32) {
        gcn_body(tago, agg, blk, smc);
    } else if (blk < 64) {
        int id = blk - 32;
        gemm256_body(tago, Wq, bq, qout, 0, 0, id & 1, id >> 1, 256, smc);
    } else {
        int id = blk - 64;
        gemm256_body(tago, Wk, bk, kout, 0, 0, id & 1, id >> 1, 256, smc);
    }
}

// fat4: sage (32) | roleFt SPP (256)
__global__ __launch_bounds__(512, 1)
void fat4_kernel(const float* __restrict__ agg,
                 const float* __restrict__ sW, const float* __restrict__ sb, float* __restrict__ gcn_out,
                 const float* __restrict__ qb, const float* __restrict__ kb, float* __restrict__ rFt)
{
    extern __shared__ __align__(16) float smc[];
    int blk = blockIdx.x;
    if (blk < 32) {
        gemm256_body(agg, sW, sb, gcn_out, 0, 1, blk & 1, blk >> 1, 256, smc);
    } else {
        spp_body(qb, kb, rFt, (blk - 32) * 8, smc);
    }
}

// ================== classifier + log_softmax ==================
__global__ void cls_kernel(const float* __restrict__ tago, const float* __restrict__ sFt,
                           const float* __restrict__ rFt, const float* __restrict__ W,
                           const float* __restrict__ bias, float* __restrict__ out)
{
    int bn = blockIdx.x;
    int tid = threadIdx.x;
    int c = tid >> 5, lane = tid & 31;
    __shared__ float sh[8];
    const float* w = W + c * 286;
    const float* t = tago + (size_t)bn * 256;
    float s = 0.f;
    for (int l = lane; l < 256; l += 32) s += t[l] * w[l];
    if (lane < 15) {
        s += sFt[bn * 15 + lane] * w[256 + lane];
        s += rFt[bn * 15 + lane] * w[271 + lane];
    }
#pragma unroll
    for (int off = 16; off > 0; off >>= 1)
        s += __shfl_down_sync(0xFFFFFFFF, s, off);
    if (lane == 0) sh[c] = s + bias[c];
    __syncthreads();
    if (tid < 8) {
        float m = sh[0];
#pragma unroll
        for (int l = 1; l < 8; l++) m = fmaxf(m, sh[l]);
        float se = 0.f;
#pragma unroll
        for (int l = 0; l < 8; l++) se += expf(sh[l] - m);
        out[bn * 8 + tid] = sh[tid] - m - logf(se);
    }
}

// ================== launch ==================
extern "C" void kernel_launch(void* const* d_in, const int* in_sizes, int n_in,
                              void* d_out, int out_size)
{
    const float* documents = (const float*)d_in[0];
    const float* sw_ih_f = (const float*)d_in[1];
    const float* sw_hh_f = (const float*)d_in[2];
    const float* sb_f    = (const float*)d_in[3];
    const float* sw_ih_b = (const float*)d_in[4];
    const float* sw_hh_b = (const float*)d_in[5];
    const float* sb_b    = (const float*)d_in[6];
    const float* sf_Wq = (const float*)d_in[7];
    const float* sf_bq = (const float*)d_in[8];
    const float* sf_Wk = (const float*)d_in[9];
    const float* sf_bk = (const float*)d_in[10];
    const float* rf_Wq = (const float*)d_in[11];
    const float* rf_bq = (const float*)d_in[12];
    const float* rf_Wk = (const float*)d_in[13];
    const float* rf_bk = (const float*)d_in[14];
    const float* tw_ih_f = (const float*)d_in[15];
    const float* tw_hh_f = (const float*)d_in[16];
    const float* tb_f    = (const float*)d_in[17];
    const float* tw_ih_b = (const float*)d_in[18];
    const float* tw_hh_b = (const float*)d_in[19];
    const float* tb_b    = (const float*)d_in[20];
    const float* sage_W = (const float*)d_in[21];
    const float* sage_b = (const float*)d_in[22];
    const float* cls_W  = (const float*)d_in[23];
    const float* cls_b  = (const float*)d_in[24];

    float* out = (float*)d_out;
    float* result_out = out;
    float* gcn_out = out + B_ * N_ * C_;

    float *sentpres, *qb, *kb, *q2, *k2, *sFt, *rFt, *gtag, *tago, *agg;
    uint4 *wihp, *whhp, *whhtagp;
    cudaGetSymbolAddress((void**)&wihp, wih_pk_buf);
    cudaGetSymbolAddress((void**)&whhp, whh_pk_buf);
    cudaGetSymbolAddress((void**)&whhtagp, whh_tag_pk_buf);
    cudaGetSymbolAddress((void**)&sentpres, sentpres_buf);
    cudaGetSymbolAddress((void**)&qb, q_buf);
    cudaGetSymbolAddress((void**)&kb, k_buf);
    cudaGetSymbolAddress((void**)&q2, q2_buf);
    cudaGetSymbolAddress((void**)&k2, k2_buf);
    cudaGetSymbolAddress((void**)&sFt, sentFt_buf);
    cudaGetSymbolAddress((void**)&rFt, roleFt_buf);
    cudaGetSymbolAddress((void**)&gtag, g_tag_buf);
    cudaGetSymbolAddress((void**)&tago, tag_out_buf);
    cudaGetSymbolAddress((void**)&agg, agg_buf);

    cudaFuncSetAttribute(lstm_sent_fused, cudaFuncAttributeMaxDynamicSharedMemorySize, FUSED_SMEM);
    cudaFuncSetAttribute(proj4_kernel, cudaFuncAttributeMaxDynamicSharedMemorySize, PROJ_SMEM);
    cudaFuncSetAttribute(tag_spp_combined, cudaFuncAttributeMaxDynamicSharedMemorySize, COMB_SMEM);
    cudaFuncSetAttribute(fat3_kernel, cudaFuncAttributeMaxDynamicSharedMemorySize, GCN_SMEM);
    cudaFuncSetAttribute(fat4_kernel, cudaFuncAttributeMaxDynamicSharedMemorySize, PROJ_SMEM);

    // merged weight packing (1 launch)
    pack_all<<<464, 256>>>(sw_ih_f, sw_ih_b, wihp, sw_hh_f, sw_hh_b, whhp,
                           tw_hh_f, tw_hh_b, whhtagp);

    // FUSED sentence BiLSTM
    lstm_sent_fused<<<dim3(64, 2), 512, FUSED_SMEM>>>(documents, wihp, whhp, sb_f, sb_b, sentpres);

    // proj4: gtag f/b + sentFt Q/K
    proj4_kernel<<<192, 512, PROJ_SMEM>>>(sentpres, tw_ih_f, tb_f, tw_ih_b, tb_b, gtag,
                                          sf_Wq, sf_bq, qb, sf_Wk, sf_bk, kb);

    // combined: tag recurrence (4 blocks) + sentFt SPP
    tag_spp_combined<<<260, 512, COMB_SMEM>>>(gtag, whhtagp, tago, qb, kb, sFt);

    // fat3: gcn + roleFt Q/K
    fat3_kernel<<<96, 512, GCN_SMEM>>>(tago, agg, rf_Wq, rf_bq, q2, rf_Wk, rf_bk, k2);

    // fat4: sage + roleFt SPP
    fat4_kernel<<<288, 512, PROJ_SMEM>>>(agg, sage_W, sage_b, gcn_out, q2, k2, rFt);

    cls_kernel<<<2048, 256>>>(tago, sFt, rFt, cls_W, cls_b, result_out);

    (void)in_sizes; (void)n_in; (void)out_size;
}

// round 17
// speedup vs baseline: 2.0415x; 1.0128x over previous
#include <cuda_runtime.h>
#include <cuda_bf16.h>
#include <stdint.h>
#include <math.h>

// ---------------- problem constants ----------------
#define B_    32
#define N_    64
#define T_    50
#define WD_   200
#define H_    128
#define G4_   512
#define D2_   256
#define BN_   2048
#define C_    8

// ---------------- scratch ----------------
__device__ uint4 wih_pk_buf[2 * 13 * 64 * 32];
__device__ uint4 whh_pk_buf[2 * 8 * 64 * 32];
__device__ uint4 whh_tag_pk_buf[2 * 8 * 64 * 32];
__device__ float sentpres_buf[BN_ * D2_];
__device__ float q_buf[BN_ * D2_];
__device__ float k_buf[BN_ * D2_];
__device__ float q2_buf[BN_ * D2_];
__device__ float k2_buf[BN_ * D2_];
__device__ float sentFt_buf[BN_ * 15];
__device__ float roleFt_buf[BN_ * 15];
__device__ float g_tag_buf[2 * BN_ * G4_];
__device__ float tag_out_buf[BN_ * D2_];
__device__ float agg_buf[BN_ * D2_];

__device__ __forceinline__ float tanh_ap(float x)
{
    float y;
    asm("tanh.approx.f32 %0, %1;" : "=f"(y) : "f"(x));
    return y;
}
__device__ __forceinline__ float sigf(float x) { return __fdividef(1.0f, 1.0f + __expf(-x)); }

#define MMA_TF32(d, a, b) \
    asm volatile("mma.sync.aligned.m16n8k8.row.col.f32.tf32.tf32.f32 " \
                 "{%0,%1,%2,%3},{%4,%5,%6,%7},{%8,%9},{%0,%1,%2,%3};\n" \
                 : "+f"(d[0]), "+f"(d[1]), "+f"(d[2]), "+f"(d[3]) \
                 : "r"(a[0]), "r"(a[1]), "r"(a[2]), "r"(a[3]), "r"(b[0]), "r"(b[1]))

__device__ __forceinline__ void ldsm_x4_a(unsigned af[4], unsigned addr)
{
    asm volatile("ldmatrix.sync.aligned.m8n8.x4.shared.b16 {%0,%1,%2,%3}, [%4];"
                 : "=r"(af[0]), "=r"(af[1]), "=r"(af[2]), "=r"(af[3]) : "r"(addr));
}

// ================== merged weight packing ==================
__global__ void pack_all(const float* __restrict__ wihf, const float* __restrict__ wihb,
                         uint4* __restrict__ owih,
                         const float* __restrict__ whf, const float* __restrict__ whb,
                         uint4* __restrict__ owhh,
                         const float* __restrict__ wtf, const float* __restrict__ wtb,
                         uint4* __restrict__ owtag)
{
    int blk = blockIdx.x;
    int tid = threadIdx.x;
    if (blk < 208) {
        int i = blk * 256 + tid;
        if (i >= 2 * 13 * 64 * 32) return;
        const int per = 13 * 64 * 32;
        int dir = i / per, rem = i % per;
        int kt = rem >> 11, ng = (rem >> 5) & 63, lane = rem & 31;
        const float* w = dir ? wihb : wihf;
        int n = ng * 8 + (lane >> 2);
        int k = kt * 16 + (lane & 3);
        uint4 v;
        v.x = (k      < WD_) ? __float_as_uint(w[n * WD_ + k])      : 0u;
        v.y = (k + 4  < WD_) ? __float_as_uint(w[n * WD_ + k + 4])  : 0u;
        v.z = (k + 8  < WD_) ? __float_as_uint(w[n * WD_ + k + 8])  : 0u;
        v.w = (k + 12 < WD_) ? __float_as_uint(w[n * WD_ + k + 12]) : 0u;
        owih[i] = v;
    } else {
        int src = (blk < 336) ? 0 : 1;
        int i = (blk - (src ? 336 : 208)) * 256 + tid;
        int lane = i & 31, ng = (i >> 5) & 63, kt = (i >> 11) & 7, dir = i >> 14;
        const float* w = src ? (dir ? wtb : wtf) : (dir ? whb : whf);
        int n = ng * 8 + (lane >> 2);
        int k = kt * 16 + (lane & 3);
        uint4 v;
        v.x = __float_as_uint(w[n * 128 + k]);
        v.y = __float_as_uint(w[n * 128 + k + 4]);
        v.z = __float_as_uint(w[n * 128 + k + 8]);
        v.w = __float_as_uint(w[n * 128 + k + 12]);
        (src ? owtag : owhh)[i] = v;
    }
}

// ================== FUSED sentence BiLSTM ==================
#define SD_STR 212
#define SH_STR 132
#define OFF_SD0   0
#define OFF_SD1   6784
#define OFF_H0    13568
#define OFF_H1    17792
#define OFF_BIAS  22016
#define FUSED_SMEM ((22016 + 512) * 4)
#define SD_BUFB   27136
#define SH_BUFB   16896

__global__ __launch_bounds__(512, 1)
void lstm_sent_fused(const float* __restrict__ doc,
                     const uint4* __restrict__ wih, const uint4* __restrict__ whh,
                     const float* __restrict__ biasf, const float* __restrict__ biasb,
                     float* __restrict__ sentpres)
{
    extern __shared__ __align__(16) float smf[];
    float* sbias = smf + OFF_BIAS;

    int dir = blockIdx.y;
    int r0 = blockIdx.x << 5;
    const float* bias = dir ? biasb : biasf;

    int tid = threadIdx.x, lane = tid & 31, w = tid >> 5;
    int gid = lane >> 2, qk = (lane & 3) << 1;

    const uint4* wp_ih = wih + dir * 13 * 64 * 32 + w * 32 + lane;
    const uint4* wp_hh = whh + dir * 8 * 64 * 32 + w * 32 + lane;

    unsigned smbase = (unsigned)__cvta_generic_to_shared(smf);
    int tile = lane >> 3, rin = lane & 7;
    int r_off = ((tile & 1) << 3) + rin;
    int c_off = (tile >> 1) << 2;
    unsigned sd_addr[2], sh_addr[2];
#pragma unroll
    for (int mt = 0; mt < 2; mt++) {
        sd_addr[mt] = smbase + ((unsigned)(OFF_SD0 + (mt * 16 + r_off) * SD_STR + c_off) << 2);
        sh_addr[mt] = smbase + ((unsigned)(OFF_H0 + (mt * 16 + r_off) * SH_STR + c_off) << 2);
    }

    float c_reg[8], hs_reg[8];
#pragma unroll
    for (int i = 0; i < 8; i++) { c_reg[i] = 0.f; hs_reg[i] = 0.f; }
    for (int i = tid; i < 2 * 32 * SH_STR; i += 512) smf[OFF_H0 + i] = 0.f;
    if (tid < 512) sbias[tid] = bias[tid];

    {
        int t0 = dir ? (T_ - 1) : 0;
        for (int idx = tid; idx < 32 * 52; idx += 512) {
            int rr = idx / 52, c4 = idx - rr * 52;
            int k = c4 << 2;
            float4 v = (k < WD_)
                ? *(const float4*)(doc + ((size_t)(r0 + rr) * T_ + t0) * WD_ + k)
                : make_float4(0.f, 0.f, 0.f, 0.f);
            *(float4*)&smf[OFF_SD0 + rr * SD_STR + k] = v;
        }
    }
    __syncthreads();

    for (int s = 0; s < T_; s++) {
        int p = s & 1;
        unsigned po = p ? SD_BUFB : 0u;
        unsigned ph = p ? SH_BUFB : 0u;

        float acc[2][4][4];
#pragma unroll
        for (int mt = 0; mt < 2; mt++)
#pragma unroll
            for (int g = 0; g < 4; g++) {
                int col = (g << 7) + (w << 3) + qk;
                float b0 = sbias[col], b1 = sbias[col + 1];
                acc[mt][g][0] = b0; acc[mt][g][1] = b1;
                acc[mt][g][2] = b0; acc[mt][g][3] = b1;
            }

        uint4 wv0[4], wv1[4], wv2[4];

#define LOADW(dst, ktv) do { \
            int _kt = (ktv); \
            if (_kt < 21) { \
                const uint4* _p = (_kt < 13) ? (wp_ih + _kt * 2048) \
                                             : (wp_hh + (_kt - 13) * 2048); \
                dst[0] = _p[0];    dst[1] = _p[512]; \
                dst[2] = _p[1024]; dst[3] = _p[1536]; \
            } \
        } while (0)

#define COMPUTE(ktv, wv) do { \
            int _kt = (ktv); \
            _Pragma("unroll") \
            for (int mt = 0; mt < 2; mt++) { \
                unsigned _a0 = (_kt < 13) ? (sd_addr[mt] + po + ((unsigned)_kt << 6)) \
                                          : (sh_addr[mt] + ph + ((unsigned)(_kt - 13) << 6)); \
                unsigned _af0[4], _af1[4]; \
                ldsm_x4_a(_af0, _a0); \
                ldsm_x4_a(_af1, _a0 + 32); \
                _Pragma("unroll") \
                for (int g = 0; g < 4; g++) { \
                    unsigned _b0[2] = { wv[g].x, wv[g].y }; \
                    unsigned _b1[2] = { wv[g].z, wv[g].w }; \
                    MMA_TF32(acc[mt][g], _af0, _b0); \
                    MMA_TF32(acc[mt][g], _af1, _b1); \
                } \
            } \
        } while (0)

        LOADW(wv0, 0);
        LOADW(wv1, 1);
#pragma unroll 1
        for (int k3 = 0; k3 < 21; k3 += 3) {
            LOADW(wv2, k3 + 2);
            COMPUTE(k3, wv0);
            LOADW(wv0, k3 + 3);
            COMPUTE(k3 + 1, wv1);
            LOADW(wv1, k3 + 4);
            COMPUTE(k3 + 2, wv2);
        }
#undef LOADW
#undef COMPUTE

        if (s + 1 < T_) {
            int tn = dir ? (T_ - 2 - s) : (s + 1);
            float* sdn = smf + (p ? OFF_SD0 : OFF_SD1);
            for (int idx = tid; idx < 32 * 52; idx += 512) {
                int rr = idx / 52, c4 = idx - rr * 52;
                int k = c4 << 2;
                float4 v = (k < WD_)
                    ? *(const float4*)(doc + ((size_t)(r0 + rr) * T_ + tn) * WD_ + k)
                    : make_float4(0.f, 0.f, 0.f, 0.f);
                *(float4*)&sdn[rr * SD_STR + k] = v;
            }
        }

        float* hw = smf + (p ? OFF_H0 : OFF_H1);
#pragma unroll
        for (int mt = 0; mt < 2; mt++)
#pragma unroll
            for (int e = 0; e < 4; e++) {
                int row = mt * 16 + gid + ((e >> 1) << 3);
                int col = (w << 3) + qk + (e & 1);
                int ix = mt * 4 + e;
                float iv = acc[mt][0][e];
                float fv = acc[mt][1][e];
                float gv = acc[mt][2][e];
                float ov = acc[mt][3][e];
                float cv = sigf(fv) * c_reg[ix] + sigf(iv) * tanh_ap(gv);
                c_reg[ix] = cv;
                float h = sigf(ov) * tanh_ap(cv);
                hs_reg[ix] += h;
                hw[row * SH_STR + col] = h;
            }
        __syncthreads();
    }

#pragma unroll
    for (int mt = 0; mt < 2; mt++)
#pragma unroll
        for (int e = 0; e < 4; e++) {
            int row = mt * 16 + gid + ((e >> 1) << 3);
            int col = (w << 3) + qk + (e & 1);
            sentpres[(size_t)(r0 + row) * 256 + dir * 128 + col] =
                tanhf(hs_reg[mt * 4 + e] * (1.0f / T_));
        }
}

// ================== device GEMM body, K=256, 512 threads ==================
__device__ void gemm256_body(const float* __restrict__ A, const float* __restrict__ W,
                             const float* __restrict__ bias, float* __restrict__ Cc,
                             int amode, int relu, int bx, int by, int Gcols, float* smf)
{
    float* sA = smf;
    float* sB = smf + 2560;
    float* sC = smf;

    int tid = threadIdx.x;
    int lane = tid & 31, wid = tid >> 5;
    int wm = wid & 3, wn = (wid >> 2) & 1;
    int mb = by << 7, nb = bx << 7;
    int lrow = tid >> 2, lq = tid & 3;
    int r = lane >> 2, tc = lane & 3, c2 = tc << 1;

    int am = mb + lrow;
    long arow = amode ? ((long)(((am & 31) << 6) + (am >> 5)) << 8) : ((long)am << 8);
    const float* ap = A + arow + lq * 4;
    const float* bp = W + ((size_t)(nb + lrow) << 8) + lq * 4;

    float acc[2][8][4];
#pragma unroll
    for (int mi = 0; mi < 2; mi++)
#pragma unroll
        for (int ni = 0; ni < 8; ni++)
#pragma unroll
            for (int e = 0; e < 4; e++) acc[mi][ni][e] = 0.f;

#pragma unroll 1
    for (int kb = 0; kb < 256; kb += 16) {
        float4 va = *(const float4*)(ap + kb);
        float4 vb = *(const float4*)(bp + kb);
        __syncthreads();
        *(float4*)&sA[lrow * 20 + lq * 4] = va;
        *(float4*)&sB[lrow * 20 + lq * 4] = vb;
        __syncthreads();

        if (wid < 8) {
            unsigned af[2][2][4];
#pragma unroll
            for (int mi = 0; mi < 2; mi++) {
                int rb = (wm * 32 + mi * 16 + r) * 20;
#pragma unroll
                for (int kh = 0; kh < 2; kh++) {
                    af[mi][kh][0] = __float_as_uint(sA[rb + kh * 8 + tc]);
                    af[mi][kh][1] = __float_as_uint(sA[rb + 160 + kh * 8 + tc]);
                    af[mi][kh][2] = __float_as_uint(sA[rb + kh * 8 + tc + 4]);
                    af[mi][kh][3] = __float_as_uint(sA[rb + 160 + kh * 8 + tc + 4]);
                }
            }
#pragma unroll
            for (int ni = 0; ni < 8; ni++) {
                int nrb = (wn * 64 + ni * 8 + r) * 20;
#pragma unroll
                for (int kh = 0; kh < 2; kh++) {
                    unsigned bf[2];
                    bf[0] = __float_as_uint(sB[nrb + kh * 8 + tc]);
                    bf[1] = __float_as_uint(sB[nrb + kh * 8 + tc + 4]);
#pragma unroll
                    for (int mi = 0; mi < 2; mi++)
                        MMA_TF32(acc[mi][ni], af[mi][kh], bf);
                }
            }
        }
    }
    for (int wmc = 0; wmc < 4; wmc++) {
        __syncthreads();
        if (wid < 8 && wm == wmc) {
#pragma unroll
            for (int mi = 0; mi < 2; mi++)
#pragma unroll
                for (int ni = 0; ni < 8; ni++) {
                    int lr2 = mi * 16 + r;
                    int col = wn * 64 + ni * 8 + c2;
                    float b0 = bias[nb + col], b1 = bias[nb + col + 1];
                    float v0 = acc[mi][ni][0] + b0, v1 = acc[mi][ni][1] + b1;
                    float v2 = acc[mi][ni][2] + b0, v3 = acc[mi][ni][3] + b1;
                    if (relu) {
                        v0 = fmaxf(v0, 0.f); v1 = fmaxf(v1, 0.f);
                        v2 = fmaxf(v2, 0.f); v3 = fmaxf(v3, 0.f);
                    }
                    *(float2*)&sC[lr2 * 128 + col] = make_float2(v0, v1);
                    *(float2*)&sC[(lr2 + 8) * 128 + col] = make_float2(v2, v3);
                }
        }
        __syncthreads();
#pragma unroll
        for (int l = 0; l < 2; l++) {
            int idx = tid + l * 512;
            int row = idx >> 5, c4 = idx & 31;
            *(float4*)&Cc[(size_t)(mb + wmc * 32 + row) * Gcols + nb + c4 * 4] =
                ((float4*)sC)[idx];
        }
    }
}

// ================== tag recurrence half: 16 batch rows ==================
__device__ void tag_role_half(const float* __restrict__ Gt, const uint4* __restrict__ whhtag,
                              float* __restrict__ tag_out, int dir, int half, float* smt)
{
    float* h0 = smt;
    const uint4* wp0 = whhtag + dir * 8 * 64 * 32;
    const float* G0 = Gt + (size_t)dir * 2048 * 512;
    int rbase = half << 4;

    int tid = threadIdx.x, lane = tid & 31, w = tid >> 5;
    int gid = lane >> 2, qk = (lane & 3) << 1;

    float c_reg[4];
#pragma unroll
    for (int i = 0; i < 4; i++) c_reg[i] = 0.f;
    for (int i = tid; i < 2 * 16 * SH_STR; i += 512) h0[i] = 0.f;

    unsigned smbase = (unsigned)__cvta_generic_to_shared(h0);
    int tile = lane >> 3, rin = lane & 7;
    int r_off = ((tile & 1) << 3) + rin;
    int c_off = (tile >> 1) << 2;
    unsigned h_addr = smbase + ((unsigned)(r_off * SH_STR + c_off) << 2);
    const unsigned HBUF = 16 * SH_STR * 4;
    __syncthreads();

#define LOADG(dst, nn) do { \
        const float* _gr = G0 + (size_t)((nn) * 32 + rbase + gid) * 512; \
        _Pragma("unroll") \
        for (int g = 0; g < 4; g++) { \
            int _col = (g << 7) + (w << 3) + qk; \
            dst[g][0] = *(const float2*)(_gr + _col); \
            dst[g][1] = *(const float2*)(_gr + 8 * 512 + _col); \
        } \
    } while (0)

    float2 gc[4][2], gn[4][2];
    LOADG(gc, dir ? 63 : 0);

    for (int s = 0; s < 64; s++) {
        int n = dir ? (63 - s) : s;
        int p = s & 1;
        unsigned ph = p ? HBUF : 0u;

        float acc[4][4];
#pragma unroll
        for (int g = 0; g < 4; g++) {
            acc[g][0] = gc[g][0].x; acc[g][1] = gc[g][0].y;
            acc[g][2] = gc[g][1].x; acc[g][3] = gc[g][1].y;
        }

        if (s + 1 < 64) {
            int nn = dir ? (62 - s) : (s + 1);
            LOADG(gn, nn);
        }

        uint4 wv0[4], wv1[4];
        {
            const uint4* pptr = wp0 + w * 32 + lane;
#pragma unroll
            for (int g = 0; g < 4; g++) wv0[g] = pptr[(g << 4) * 32];
        }
#pragma unroll 1
        for (int kt = 0; kt < 8; kt += 2) {
            {
                const uint4* pptr = wp0 + ((kt + 1) * 64 + w) * 32 + lane;
#pragma unroll
                for (int g = 0; g < 4; g++) wv1[g] = pptr[(g << 4) * 32];
            }
            {
                unsigned af0[4], af1[4];
                unsigned a0 = h_addr + ph + ((unsigned)kt << 6);
                ldsm_x4_a(af0, a0);
                ldsm_x4_a(af1, a0 + 32);
#pragma unroll
                for (int g = 0; g < 4; g++) {
                    unsigned b0[2] = { wv0[g].x, wv0[g].y };
                    unsigned b1[2] = { wv0[g].z, wv0[g].w };
                    MMA_TF32(acc[g], af0, b0);
                    MMA_TF32(acc[g], af1, b1);
                }
            }
            if (kt + 2 < 8) {
                const uint4* pptr = wp0 + ((kt + 2) * 64 + w) * 32 + lane;
#pragma unroll
                for (int g = 0; g < 4; g++) wv0[g] = pptr[(g << 4) * 32];
            }
            {
                unsigned af0[4], af1[4];
                unsigned a0 = h_addr + ph + ((unsigned)(kt + 1) << 6);
                ldsm_x4_a(af0, a0);
                ldsm_x4_a(af1, a0 + 32);
#pragma unroll
                for (int g = 0; g < 4; g++) {
                    unsigned b0[2] = { wv1[g].x, wv1[g].y };
                    unsigned b1[2] = { wv1[g].z, wv1[g].w };
                    MMA_TF32(acc[g], af0, b0);
                    MMA_TF32(acc[g], af1, b1);
                }
            }
        }

        float* hw = h0 + (p ? 0 : 16 * SH_STR);
#pragma unroll
        for (int e = 0; e < 4; e++) {
            int lrow = gid + ((e >> 1) << 3);
            int col = (w << 3) + qk + (e & 1);
            float iv = acc[0][e];
            float fv = acc[1][e];
            float gv = acc[2][e];
            float ov = acc[3][e];
            float cv = sigf(fv) * c_reg[e] + sigf(iv) * tanh_ap(gv);
            c_reg[e] = cv;
            float h = sigf(ov) * tanh_ap(cv);
            hw[lrow * SH_STR + col] = h;
            tag_out[(size_t)((rbase + lrow) * 64 + n) * 256 + dir * 128 + col] = tanhf(h);
        }
        __syncthreads();

#pragma unroll
        for (int g = 0; g < 4; g++) { gc[g][0] = gn[g][0]; gc[g][1] = gn[g][1]; }
    }
#undef LOADG
}

// ================== SPP body: 512 threads, 8 bn per block ==================
__device__ void spp_body(const float* __restrict__ q, const float* __restrict__ k,
                         float* __restrict__ out, int bn_base, float* sm)
{
    float* shq = sm;
    float* att = sm + 2048;
    float* e8  = sm + 2560;
    int tid = threadIdx.x;
    int g = tid >> 6, t = tid & 63;
    int bn = bn_base + g;
    int b = bn >> 6;
    for (int l = t; l < 256; l += 64) shq[g * 256 + l] = q[(size_t)bn * 256 + l];
    __syncthreads();
    const float* kr = k + (size_t)(b * 64 + t) * 256;
    float s = 0.f;
    for (int l = 0; l < 256; l += 4) {
        float4 qa = *(float4*)&shq[g * 256 + l];
        float4 ka = *(const float4*)&kr[l];
        s += qa.x * ka.x + qa.y * ka.y + qa.z * ka.z + qa.w * ka.w;
    }
    att[g * 64 + t] = s * 0.0625f;
    __syncthreads();
    if (t < 8) {
        float m = att[g * 64 + t * 8];
#pragma unroll
        for (int l = 1; l < 8; l++) m = fmaxf(m, att[g * 64 + t * 8 + l]);
        e8[g * 8 + t] = m;
    }
    __syncthreads();
    if (t == 0) {
        float q4[4];
#pragma unroll
        for (int l = 0; l < 4; l++) q4[l] = fmaxf(e8[g * 8 + 2 * l], e8[g * 8 + 2 * l + 1]);
        float h2a = fmaxf(q4[0], q4[1]);
        float h2b = fmaxf(q4[2], q4[3]);
        float* o = out + bn * 15;
        o[0] = fmaxf(h2a, h2b);
        o[1] = h2a; o[2] = h2b;
        o[3] = q4[0]; o[4] = q4[1]; o[5] = q4[2]; o[6] = q4[3];
#pragma unroll
        for (int l = 0; l < 8; l++) o[7 + l] = e8[g * 8 + l];
    }
}

// ================== GCN body: 512 threads ==================
#define XS 257
#define GCN_SMEM ((64 * XS + 64 * 64 + 64) * 4)
__device__ void gcn_body(const float* __restrict__ x, float* __restrict__ agg, int b, float* gs)
{
    float* shx = gs;
    float* shc = gs + 64 * XS;
    float* shn = shc + 4096;
    int tid = threadIdx.x;
    for (int l = tid; l < 16384; l += 512) {
        int i = l >> 8, d = l & 255;
        shx[i * XS + d] = x[(size_t)b * 16384 + l];
    }
    __syncthreads();
    if (tid < 64) {
        float s = 0.f;
        for (int l = 0; l < 256; l++) { float v = shx[tid * XS + l]; s += v * v; }
        shn[tid] = sqrtf(s) + 1e-8f;
    }
    __syncthreads();
    for (int p = tid; p < 4096; p += 512) {
        int i = p >> 6, j = p & 63;
        float s = 0.f;
        for (int l = 0; l < 256; l++) s += shx[i * XS + l] * shx[j * XS + l];
        shc[p] = s / (shn[i] * shn[j]);
    }
    __syncthreads();
    for (int p = tid; p < 16384; p += 512) {
        int i = p >> 8, d = p & 255;
        float s = 2.0f * shx[i * XS + d];
        for (int j = 0; j < 64; j++) s += shc[i * 64 + j] * shx[j * XS + d];
        agg[(size_t)b * 16384 + p] = s * (1.0f / 66.0f);
    }
}

// ================== FAT LAUNCHES ==================
#define PROJ_SMEM (5120 * 4)
__global__ __launch_bounds__(512, 1)
void proj4_kernel(const float* __restrict__ sentpres,
                  const float* __restrict__ twf, const float* __restrict__ tbf,
                  const float* __restrict__ twb, const float* __restrict__ tbb,
                  float* __restrict__ gtag,
                  const float* __restrict__ Wq, const float* __restrict__ bq, float* __restrict__ qout,
                  const float* __restrict__ Wk, const float* __restrict__ bk, float* __restrict__ kout)
{
    extern __shared__ __align__(16) float smc[];
    int blk = blockIdx.x;
    if (blk < 64) {
        gemm256_body(sentpres, twf, tbf, gtag, 1, 0, blk & 3, blk >> 2, 512, smc);
    } else if (blk < 128) {
        int id = blk - 64;
        gemm256_body(sentpres, twb, tbb, gtag + BN_ * G4_, 1, 0, id & 3, id >> 2, 512, smc);
    } else if (blk < 160) {
        int id = blk - 128;
        gemm256_body(sentpres, Wq, bq, qout, 0, 0, id & 1, id >> 1, 256, smc);
    } else {
        int id = blk - 160;
        gemm256_body(sentpres, Wk, bk, kout, 0, 0, id & 1, id >> 1, 256, smc);
    }
}

#define COMB_SMEM (2 * 16 * SH_STR * 4)
__global__ __launch_bounds__(512, 1)
void tag_spp_combined(const float* __restrict__ Gt, const uint4* __restrict__ whhtag,
                      float* __restrict__ tag_out,
                      const float* __restrict__ qb, const float* __restrict__ kb,
                      float* __restrict__ sFt)
{
    extern __shared__ __align__(16) float smc[];
    int blk = blockIdx.x;
    if (blk < 4) tag_role_half(Gt, whhtag, tag_out, blk >> 1, blk & 1, smc);
    else         spp_body(qb, kb, sFt, (blk - 4) * 8, smc);
}

__global__ __launch_bounds__(512, 1)
void fat3_kernel(const float* __restrict__ tago, float* __restrict__ agg,
                 const float* __restrict__ Wq, const float* __restrict__ bq, float* __restrict__ qout,
                 const float* __restrict__ Wk, const float* __restrict__ bk, float* __restrict__ kout)
{
    extern __shared__ __align__(16) float smc[];
    int blk = blockIdx.x;
    if (blk < 32) {
        gcn_body(tago, agg, blk, smc);
    } else if (blk < 64) {
        int id = blk - 32;
        gemm256_body(tago, Wq, bq, qout, 0, 0, id & 1, id >> 1, 256, smc);
    } else {
        int id = blk - 64;
        gemm256_body(tago, Wk, bk, kout, 0, 0, id & 1, id >> 1, 256, smc);
    }
}

__global__ __launch_bounds__(512, 1)
void fat4_kernel(const float* __restrict__ agg,
                 const float* __restrict__ sW, const float* __restrict__ sb, float* __restrict__ gcn_out,
                 const float* __restrict__ qb, const float* __restrict__ kb, float* __restrict__ rFt)
{
    extern __shared__ __align__(16) float smc[];
    int blk = blockIdx.x;
    if (blk < 32) {
        gemm256_body(agg, sW, sb, gcn_out, 0, 1, blk & 1, blk >> 1, 256, smc);
    } else {
        spp_body(qb, kb, rFt, (blk - 32) * 8, smc);
    }
}

// ================== classifier + log_softmax ==================
__global__ void cls_kernel(const float* __restrict__ tago, const float* __restrict__ sFt,
                           const float* __restrict__ rFt, const float* __restrict__ W,
                           const float* __restrict__ bias, float* __restrict__ out)
{
    int bn = blockIdx.x;
    int tid = threadIdx.x;
    int c = tid >> 5, lane = tid & 31;
    __shared__ float sh[8];
    const float* w = W + c * 286;
    const float* t = tago + (size_t)bn * 256;
    float s = 0.f;
    for (int l = lane; l < 256; l += 32) s += t[l] * w[l];
    if (lane < 15) {
        s += sFt[bn * 15 + lane] * w[256 + lane];
        s += rFt[bn * 15 + lane] * w[271 + lane];
    }
#pragma unroll
    for (int off = 16; off > 0; off >>= 1)
        s += __shfl_down_sync(0xFFFFFFFF, s, off);
    if (lane == 0) sh[c] = s + bias[c];
    __syncthreads();
    if (tid < 8) {
        float m = sh[0];
#pragma unroll
        for (int l = 1; l < 8; l++) m = fmaxf(m, sh[l]);
        float se = 0.f;
#pragma unroll
        for (int l = 0; l < 8; l++) se += expf(sh[l] - m);
        out[bn * 8 + tid] = sh[tid] - m - logf(se);
    }
}

// ================== launch ==================
extern "C" void kernel_launch(void* const* d_in, const int* in_sizes, int n_in,
                              void* d_out, int out_size)
{
    const float* documents = (const float*)d_in[0];
    const float* sw_ih_f = (const float*)d_in[1];
    const float* sw_hh_f = (const float*)d_in[2];
    const float* sb_f    = (const float*)d_in[3];
    const float* sw_ih_b = (const float*)d_in[4];
    const float* sw_hh_b = (const float*)d_in[5];
    const float* sb_b    = (const float*)d_in[6];
    const float* sf_Wq = (const float*)d_in[7];
    const float* sf_bq = (const float*)d_in[8];
    const float* sf_Wk = (const float*)d_in[9];
    const float* sf_bk = (const float*)d_in[10];
    const float* rf_Wq = (const float*)d_in[11];
    const float* rf_bq = (const float*)d_in[12];
    const float* rf_Wk = (const float*)d_in[13];
    const float* rf_bk = (const float*)d_in[14];
    const float* tw_ih_f = (const float*)d_in[15];
    const float* tw_hh_f = (const float*)d_in[16];
    const float* tb_f    = (const float*)d_in[17];
    const float* tw_ih_b = (const float*)d_in[18];
    const float* tw_hh_b = (const float*)d_in[19];
    const float* tb_b    = (const float*)d_in[20];
    const float* sage_W = (const float*)d_in[21];
    const float* sage_b = (const float*)d_in[22];
    const float* cls_W  = (const float*)d_in[23];
    const float* cls_b  = (const float*)d_in[24];

    float* out = (float*)d_out;
    float* result_out = out;
    float* gcn_out = out + B_ * N_ * C_;

    float *sentpres, *qb, *kb, *q2, *k2, *sFt, *rFt, *gtag, *tago, *agg;
    uint4 *wihp, *whhp, *whhtagp;
    cudaGetSymbolAddress((void**)&wihp, wih_pk_buf);
    cudaGetSymbolAddress((void**)&whhp, whh_pk_buf);
    cudaGetSymbolAddress((void**)&whhtagp, whh_tag_pk_buf);
    cudaGetSymbolAddress((void**)&sentpres, sentpres_buf);
    cudaGetSymbolAddress((void**)&qb, q_buf);
    cudaGetSymbolAddress((void**)&kb, k_buf);
    cudaGetSymbolAddress((void**)&q2, q2_buf);
    cudaGetSymbolAddress((void**)&k2, k2_buf);
    cudaGetSymbolAddress((void**)&sFt, sentFt_buf);
    cudaGetSymbolAddress((void**)&rFt, roleFt_buf);
    cudaGetSymbolAddress((void**)&gtag, g_tag_buf);
    cudaGetSymbolAddress((void**)&tago, tag_out_buf);
    cudaGetSymbolAddress((void**)&agg, agg_buf);

    cudaFuncSetAttribute(lstm_sent_fused, cudaFuncAttributeMaxDynamicSharedMemorySize, FUSED_SMEM);
    cudaFuncSetAttribute(proj4_kernel, cudaFuncAttributeMaxDynamicSharedMemorySize, PROJ_SMEM);
    cudaFuncSetAttribute(tag_spp_combined, cudaFuncAttributeMaxDynamicSharedMemorySize, COMB_SMEM);
    cudaFuncSetAttribute(fat3_kernel, cudaFuncAttributeMaxDynamicSharedMemorySize, GCN_SMEM);
    cudaFuncSetAttribute(fat4_kernel, cudaFuncAttributeMaxDynamicSharedMemorySize, PROJ_SMEM);

    pack_all<<<464, 256>>>(sw_ih_f, sw_ih_b, wihp, sw_hh_f, sw_hh_b, whhp,
                           tw_hh_f, tw_hh_b, whhtagp);

    lstm_sent_fused<<<dim3(64, 2), 512, FUSED_SMEM>>>(documents, wihp, whhp, sb_f, sb_b, sentpres);

    proj4_kernel<<<192, 512, PROJ_SMEM>>>(sentpres, tw_ih_f, tb_f, tw_ih_b, tb_b, gtag,
                                          sf_Wq, sf_bq, qb, sf_Wk, sf_bk, kb);

    tag_spp_combined<<<260, 512, COMB_SMEM>>>(gtag, whhtagp, tago, qb, kb, sFt);

    fat3_kernel<<<96, 512, GCN_SMEM>>>(tago, agg, rf_Wq, rf_bq, q2, rf_Wk, rf_bk, k2);

    fat4_kernel<<<288, 512, PROJ_SMEM>>>(agg, sage_W, sage_b, gcn_out, q2, k2, rFt);

    cls_kernel<<<2048, 256>>>(tago, sFt, rFt, cls_W, cls_b, result_out);

    (void)in_sizes; (void)n_in; (void)out_size;
}